// round 13
// baseline (speedup 1.0000x reference)
#include <cuda_runtime.h>
#include <cuda_bf16.h>
#include <math.h>

#define B_    4096
#define REPR_ 39200
#define FEAT_ 256
#define HID_  1024
#define NE_   32
#define TOPK_ 4
#define SDIM_ 24
#define ADIM_ 7
#define MHID_ 256
#define KSPL_ 35
#define KCH_  1120          // REPR_/KSPL_
#define NROWS_ (B_*TOPK_)
#define ROWW  40            // smem row width (32 k + 8 pad), 80B stride
#define WDSZ  262144        // 1024*256 dense weight slice

typedef __nv_bfloat16 bh;

// trunk dynamic smem: two buffers of {A0,A1,B0,B1}
#define TA1O  (128*ROWW)           // 5120
#define TB0O  (2*128*ROWW)         // 10240
#define TB1O  (TB0O + 256*ROWW)    // 20480
#define TBUF  (TB1O + 256*ROWW)    // 30720 elems = 61440 B
#define SMEM_TRUNK (2*TBUF*2)      // 122880 B

// ------------------------------------------------------------------
// Device scratch
// ------------------------------------------------------------------
__device__ float g_hid[(size_t)B_*HID_];
__device__ float g_s[(size_t)B_*FEAT_];
__device__ float g_part[(size_t)KSPL_*B_*FEAT_];
__device__ float g_h[(size_t)B_*FEAT_];
__device__ float g_h2[(size_t)B_*FEAT_];
__device__ float g_x[(size_t)B_*HID_];
__device__ float g_gh[(size_t)B_*FEAT_];
__device__ float g_logits[(size_t)B_*NE_];
__device__ float g_imp[NE_];
__device__ int   g_ecount[NE_];
__device__ int   g_off[NE_];
__device__ int   g_elist[NE_*B_];
__device__ int   g_tok_e[B_*TOPK_];
__device__ int   g_tok_pos[B_*TOPK_];
__device__ float g_tok_w[B_*TOPK_];
__device__ float g_H1[(size_t)NROWS_*MHID_];
__device__ float g_Y[(size_t)NROWS_*HID_];
__device__ float g_xmoe[(size_t)B_*HID_];
// 2-plane bf16 splits, TRANSPOSED to [n][k] layout
__device__ bh g_wt0[(size_t)REPR_*FEAT_];
__device__ bh g_wt1[(size_t)REPR_*FEAT_];
__device__ bh g_wd0[5*(size_t)WDSZ];   // se2|fu1|fu2|p1|g1, [n][k]
__device__ bh g_wd1[5*(size_t)WDSZ];
__device__ bh g_e1t0[(size_t)NE_*HID_*MHID_];   // [e][n=256][k=1024]
__device__ bh g_e1t1[(size_t)NE_*HID_*MHID_];
__device__ bh g_e2t0[(size_t)NE_*MHID_*HID_];   // [e][n=1024][k=256]
__device__ bh g_e2t1[(size_t)NE_*MHID_*HID_];

// ------------------------------------------------------------------
__global__ void zero_kernel() {
    int t = threadIdx.x;
    if (t < NE_) { g_ecount[t] = 0; g_imp[t] = 0.f; }
}

// ------------------------------------------------------------------
// transpose + 2-plane split: src [z][K][N] fp32 -> d0/d1 [z][N][K] bf16
// ------------------------------------------------------------------
__global__ __launch_bounds__(256) void tconv(
    const float* __restrict__ src, bh* __restrict__ d0, bh* __restrict__ d1,
    int K, int N)
{
    const int z = blockIdx.z;
    const float* s = src + (size_t)z * K * N;
    bh* p0 = d0 + (size_t)z * K * N;
    bh* p1 = d1 + (size_t)z * K * N;
    __shared__ float t[32][33];
    const int k0 = blockIdx.x * 32, n0 = blockIdx.y * 32;
#pragma unroll
    for (int i = 0; i < 4; i++) {
        int ky = threadIdx.y + 8 * i;
        t[ky][threadIdx.x] = s[(size_t)(k0 + ky) * N + n0 + threadIdx.x];
    }
    __syncthreads();
#pragma unroll
    for (int i = 0; i < 4; i++) {
        int ny = threadIdx.y + 8 * i;
        float x = t[threadIdx.x][ny];
        bh b0 = __float2bfloat16(x);
        size_t o = (size_t)(n0 + ny) * K + k0 + threadIdx.x;
        p0[o] = b0;
        p1[o] = __float2bfloat16(x - __bfloat162float(b0));
    }
}

// ------------------------------------------------------------------
// MMA + LDSM + cp.async helpers
// ------------------------------------------------------------------
__device__ __forceinline__ void mma_bf16(float c[4], const unsigned a[4], const unsigned b[2]) {
    asm volatile(
        "mma.sync.aligned.m16n8k16.row.col.f32.bf16.bf16.f32 "
        "{%0,%1,%2,%3},{%4,%5,%6,%7},{%8,%9},{%0,%1,%2,%3};\n"
        : "+f"(c[0]), "+f"(c[1]), "+f"(c[2]), "+f"(c[3])
        : "r"(a[0]), "r"(a[1]), "r"(a[2]), "r"(a[3]), "r"(b[0]), "r"(b[1]));
}

__device__ __forceinline__ void ldsm4(unsigned r[4], const bh* p) {
    unsigned addr = (unsigned)__cvta_generic_to_shared(p);
    asm volatile("ldmatrix.sync.aligned.m8n8.x4.shared.b16 {%0,%1,%2,%3}, [%4];"
                 : "=r"(r[0]), "=r"(r[1]), "=r"(r[2]), "=r"(r[3]) : "r"(addr));
}

__device__ __forceinline__ void cpa16(bh* dst, const bh* src) {
    unsigned d = (unsigned)__cvta_generic_to_shared(dst);
    asm volatile("cp.async.cg.shared.global [%0], [%1], 16;\n" :: "r"(d), "l"(src));
}

__device__ __forceinline__ unsigned pk(bh a, bh b) {
    __nv_bfloat162 t(a, b);
    return *(unsigned*)&t;
}

// convert 8 fp32 -> two 16B plane stores
__device__ __forceinline__ void split8_store(
    const float x[8], bh* a0p, bh* a1p)
{
    unsigned u0[4], u1[4];
#pragma unroll
    for (int j = 0; j < 4; j++) {
        bh h0a = __float2bfloat16(x[2*j]);
        bh h0b = __float2bfloat16(x[2*j+1]);
        bh h1a = __float2bfloat16(x[2*j]   - __bfloat162float(h0a));
        bh h1b = __float2bfloat16(x[2*j+1] - __bfloat162float(h0b));
        u0[j] = pk(h0a, h0b);
        u1[j] = pk(h1a, h1b);
    }
    *(uint4*)a0p = make_uint4(u0[0], u0[1], u0[2], u0[3]);
    *(uint4*)a1p = make_uint4(u1[0], u1[1], u1[2], u1[3]);
}

// 32-k MMA block with B-fragment prefetch (p+1 loaded during p's MMAs).
// MMA order identical to prior rounds -> bit-identical accumulation.
template<int MT, int NP>
__device__ __forceinline__ void mma_iterG(
    const bh (*A0)[ROWW], const bh (*A1)[ROWW],
    const bh (*B0)[ROWW], const bh (*B1)[ROWW],
    int wr, int wc, int lane, float c[MT][2*NP][4])
{
    const int frow = lane & 15;
    const int fcol = (lane >> 4) << 3;
#pragma unroll
    for (int kh = 0; kh < 2; kh++) {
        const int kc = kh * 16 + fcol;
        unsigned a0f[MT][4], a1f[MT][4];
#pragma unroll
        for (int mt = 0; mt < MT; mt++) {
            ldsm4(a0f[mt], &A0[wr * (MT * 16) + mt * 16 + frow][kc]);
            ldsm4(a1f[mt], &A1[wr * (MT * 16) + mt * 16 + frow][kc]);
        }
        unsigned q0[2][4], q1[2][4];
        ldsm4(q0[0], &B0[wc * (NP * 16) + frow][kc]);
        ldsm4(q1[0], &B1[wc * (NP * 16) + frow][kc]);
#pragma unroll
        for (int p = 0; p < NP; p++) {
            const int cur = p & 1;
            if (p + 1 < NP) {
                ldsm4(q0[cur ^ 1], &B0[wc * (NP * 16) + (p + 1) * 16 + frow][kc]);
                ldsm4(q1[cur ^ 1], &B1[wc * (NP * 16) + (p + 1) * 16 + frow][kc]);
            }
            unsigned be0[2] = {q0[cur][0], q0[cur][2]}, bo0[2] = {q0[cur][1], q0[cur][3]};
            unsigned be1[2] = {q1[cur][0], q1[cur][2]}, bo1[2] = {q1[cur][1], q1[cur][3]};
#pragma unroll
            for (int mt = 0; mt < MT; mt++) {
                mma_bf16(c[mt][2*p],   a0f[mt], be0);
                mma_bf16(c[mt][2*p],   a0f[mt], be1);
                mma_bf16(c[mt][2*p],   a1f[mt], be0);
                mma_bf16(c[mt][2*p+1], a0f[mt], bo0);
                mma_bf16(c[mt][2*p+1], a0f[mt], bo1);
                mma_bf16(c[mt][2*p+1], a1f[mt], bo0);
            }
        }
    }
}

// ------------------------------------------------------------------
// Trunk GEMM: M128 x N256 (R10 shape), cp.async double-buffered B,
// double-buffered A, 1 barrier/iter, split-K=35
// ------------------------------------------------------------------
__global__ __launch_bounds__(256) void trunk_mma(
    const float* __restrict__ obs, float* __restrict__ part)
{
    extern __shared__ __align__(16) bh dyn[];
    const int s = blockIdx.x;
    const int m0 = blockIdx.y * 128;
    const int kbase = s * KCH_;
    const int tid = threadIdx.x;
    const int wid = tid >> 5, lane = tid & 31;
    const int wr = wid >> 2, wc = wid & 3;
    const int g = lane >> 2, tg = lane & 3;
    const int ar = tid >> 1;            // A row 0..127
    const int ak = (tid & 1) * 16;      // A k-offset 0/16
    float c[4][8][4] = {};

    const float* abase = &obs[(size_t)(m0 + ar) * REPR_ + kbase + ak];
    const bh* w0row = &g_wt0[(size_t)tid * REPR_ + kbase];
    const bh* w1row = &g_wt1[(size_t)tid * REPR_ + kbase];

    float xv[16];

#define T_LOADA(IT) do { \
        const float* ap = abase + (IT) * 32; \
        float4 f1 = *(const float4*)ap; \
        float4 f2 = *(const float4*)(ap + 4); \
        float4 f3 = *(const float4*)(ap + 8); \
        float4 f4 = *(const float4*)(ap + 12); \
        xv[0]=f1.x; xv[1]=f1.y; xv[2]=f1.z; xv[3]=f1.w; \
        xv[4]=f2.x; xv[5]=f2.y; xv[6]=f2.z; xv[7]=f2.w; \
        xv[8]=f3.x; xv[9]=f3.y; xv[10]=f3.z; xv[11]=f3.w; \
        xv[12]=f4.x; xv[13]=f4.y; xv[14]=f4.z; xv[15]=f4.w; \
    } while (0)

#define T_STOREA(BUFI) do { \
        bh* base = dyn + (BUFI) * TBUF; \
        split8_store(xv,     base + ar * ROWW + ak,        base + TA1O + ar * ROWW + ak); \
        split8_store(xv + 8, base + ar * ROWW + ak + 8,    base + TA1O + ar * ROWW + ak + 8); \
    } while (0)

#define T_CPB(IT, BUFI) do { \
        bh* b0 = dyn + (BUFI) * TBUF + TB0O + tid * ROWW; \
        bh* b1 = dyn + (BUFI) * TBUF + TB1O + tid * ROWW; \
        const bh* s0 = w0row + (IT) * 32; \
        const bh* s1 = w1row + (IT) * 32; \
        cpa16(b0,      s0);      cpa16(b0 + 8,  s0 + 8); \
        cpa16(b0 + 16, s0 + 16); cpa16(b0 + 24, s0 + 24); \
        cpa16(b1,      s1);      cpa16(b1 + 8,  s1 + 8); \
        cpa16(b1 + 16, s1 + 16); cpa16(b1 + 24, s1 + 24); \
        asm volatile("cp.async.commit_group;\n"); \
    } while (0)

    const int n = KCH_ / 32;
    // prologue
    T_LOADA(0);
    T_CPB(0, 0);
    T_STOREA(0);
    T_LOADA(1);
    asm volatile("cp.async.wait_group 0;\n");
    __syncthreads();

    for (int it = 0; it < n; ++it) {
        const int cur = it & 1;
        if (it + 1 < n) {
            T_STOREA(cur ^ 1);          // write A into the idle buffer
            T_CPB(it + 1, cur ^ 1);     // async B into the idle buffer
            if (it + 2 < n) T_LOADA(it + 2);
        }
        bh* base = dyn + cur * TBUF;
        mma_iterG<4, 4>((bh(*)[ROWW])base, (bh(*)[ROWW])(base + TA1O),
                        (bh(*)[ROWW])(base + TB0O), (bh(*)[ROWW])(base + TB1O),
                        wr, wc, lane, c);
        if (it + 1 < n) asm volatile("cp.async.wait_group 0;\n");
        __syncthreads();
    }
#undef T_LOADA
#undef T_STOREA
#undef T_CPB
#pragma unroll
    for (int mt = 0; mt < 4; mt++)
#pragma unroll
        for (int nt = 0; nt < 8; nt++) {
            int r = m0 + wr * 64 + mt * 16 + g;
            int cc = wc * 64 + nt * 8 + 2 * tg;
            float* p = &part[((size_t)s * B_ + r) * FEAT_ + cc];
            p[0] = c[mt][nt][0];
            p[1] = c[mt][nt][1];
            float* q = p + 8 * FEAT_;
            q[0] = c[mt][nt][2];
            q[1] = c[mt][nt][3];
        }
}

// ------------------------------------------------------------------
// Dense MMA GEMM (M64 x N256, R10 structure + fragment prefetch)
// ------------------------------------------------------------------
__global__ __launch_bounds__(256) void mma_dense(
    const float* __restrict__ A,
    const bh* __restrict__ W0, const bh* __restrict__ W1,
    const float* __restrict__ bias, float* __restrict__ C,
    int N, int K, int relu_flag)
{
    const int col0 = blockIdx.x * 256;
    const int m0 = blockIdx.y * 64;
    __shared__ __align__(16) bh A0[64][ROWW], A1[64][ROWW];
    __shared__ __align__(16) bh B0[256][ROWW], B1[256][ROWW];
    const int tid = threadIdx.x;
    const int wid = tid >> 5, lane = tid & 31;
    const int wr = wid >> 2, wc = wid & 3;
    const int g = lane >> 2, tg = lane & 3;
    const int ar = tid >> 2;
    const int ak = (tid & 3) * 8;
    float c[2][8][4] = {};

    const float* abase = &A[(size_t)(m0 + ar) * K + ak];
    const uint4* wb0 = (const uint4*)&W0[(size_t)(col0 + tid) * K];
    const uint4* wb1 = (const uint4*)&W1[(size_t)(col0 + tid) * K];

    float xv[8];
    uint4 pb0[4], pb1[4];
    {
        float4 f1 = *(const float4*)abase;
        float4 f2 = *(const float4*)(abase + 4);
        xv[0]=f1.x; xv[1]=f1.y; xv[2]=f1.z; xv[3]=f1.w;
        xv[4]=f2.x; xv[5]=f2.y; xv[6]=f2.z; xv[7]=f2.w;
#pragma unroll
        for (int j = 0; j < 4; j++) { pb0[j] = wb0[j]; pb1[j] = wb1[j]; }
    }

    const int iters = K / 32;
    for (int it = 0; it < iters; ++it) {
        split8_store(xv, &A0[ar][ak], &A1[ar][ak]);
        {
            uint4* d0 = (uint4*)&B0[tid][0];
            uint4* d1 = (uint4*)&B1[tid][0];
#pragma unroll
            for (int j = 0; j < 4; j++) { d0[j] = pb0[j]; d1[j] = pb1[j]; }
        }
        __syncthreads();
        if (it + 1 < iters) {
            const float* ap = abase + (it + 1) * 32;
            float4 f1 = *(const float4*)ap;
            float4 f2 = *(const float4*)(ap + 4);
            xv[0]=f1.x; xv[1]=f1.y; xv[2]=f1.z; xv[3]=f1.w;
            xv[4]=f2.x; xv[5]=f2.y; xv[6]=f2.z; xv[7]=f2.w;
            const uint4* s0 = wb0 + (it + 1) * 4;
            const uint4* s1 = wb1 + (it + 1) * 4;
#pragma unroll
            for (int j = 0; j < 4; j++) { pb0[j] = s0[j]; pb1[j] = s1[j]; }
        }
        mma_iterG<2, 4>(A0, A1, B0, B1, wr, wc, lane, c);
        __syncthreads();
    }
#pragma unroll
    for (int mt = 0; mt < 2; mt++)
#pragma unroll
        for (int nt = 0; nt < 8; nt++) {
            int r = m0 + wr * 32 + mt * 16 + g;
            int cc = col0 + wc * 64 + nt * 8 + 2 * tg;
            float v0 = c[mt][nt][0] + bias[cc];
            float v1 = c[mt][nt][1] + bias[cc + 1];
            float v2 = c[mt][nt][2] + bias[cc];
            float v3 = c[mt][nt][3] + bias[cc + 1];
            if (relu_flag) {
                v0 = fmaxf(v0, 0.f); v1 = fmaxf(v1, 0.f);
                v2 = fmaxf(v2, 0.f); v3 = fmaxf(v3, 0.f);
            }
            C[(size_t)r * N + cc] = v0;
            C[(size_t)r * N + cc + 1] = v1;
            C[(size_t)(r + 8) * N + cc] = v2;
            C[(size_t)(r + 8) * N + cc + 1] = v3;
        }
}

// ------------------------------------------------------------------
// Expert GEMM 1: H1 = relu(gather(x) @ e1[e] + b)  K=1024, N=256
// ------------------------------------------------------------------
__global__ __launch_bounds__(256) void mma_eg1(const float* __restrict__ e1b)
{
    const int e = blockIdx.z;
    const int ce = g_ecount[e];
    const int m0 = blockIdx.y * 64;
    if (m0 >= ce) return;
    const int off = g_off[e];
    const bh* W0 = g_e1t0 + (size_t)e * HID_ * MHID_;
    const bh* W1 = g_e1t1 + (size_t)e * HID_ * MHID_;
    const float* bias = e1b + (size_t)e * MHID_;

    __shared__ __align__(16) bh A0[64][ROWW], A1[64][ROWW];
    __shared__ __align__(16) bh B0[256][ROWW], B1[256][ROWW];
    const int tid = threadIdx.x;
    const int wid = tid >> 5, lane = tid & 31;
    const int wr = wid >> 2, wc = wid & 3;
    const int g = lane >> 2, tg = lane & 3;
    const int ar = tid >> 2;
    const int ak = (tid & 3) * 8;
    const int gr0 = m0 + ar;
    const int tok = (gr0 < ce) ? g_elist[e * B_ + gr0] : -1;
    const float* abase = (tok >= 0) ? &g_x[(size_t)tok * HID_ + ak] : nullptr;
    const uint4* wb0 = (const uint4*)&W0[(size_t)tid * HID_];
    const uint4* wb1 = (const uint4*)&W1[(size_t)tid * HID_];
    float c[2][8][4] = {};

    float xv[8] = {0.f,0.f,0.f,0.f,0.f,0.f,0.f,0.f};
    uint4 pb0[4], pb1[4];
    {
        if (abase) {
            float4 f1 = *(const float4*)abase;
            float4 f2 = *(const float4*)(abase + 4);
            xv[0]=f1.x; xv[1]=f1.y; xv[2]=f1.z; xv[3]=f1.w;
            xv[4]=f2.x; xv[5]=f2.y; xv[6]=f2.z; xv[7]=f2.w;
        }
#pragma unroll
        for (int j = 0; j < 4; j++) { pb0[j] = wb0[j]; pb1[j] = wb1[j]; }
    }

    for (int it = 0; it < HID_ / 32; ++it) {
        split8_store(xv, &A0[ar][ak], &A1[ar][ak]);
        {
            uint4* d0 = (uint4*)&B0[tid][0];
            uint4* d1 = (uint4*)&B1[tid][0];
#pragma unroll
            for (int j = 0; j < 4; j++) { d0[j] = pb0[j]; d1[j] = pb1[j]; }
        }
        __syncthreads();
        if (it + 1 < HID_ / 32) {
            if (abase) {
                const float* ap = abase + (it + 1) * 32;
                float4 f1 = *(const float4*)ap;
                float4 f2 = *(const float4*)(ap + 4);
                xv[0]=f1.x; xv[1]=f1.y; xv[2]=f1.z; xv[3]=f1.w;
                xv[4]=f2.x; xv[5]=f2.y; xv[6]=f2.z; xv[7]=f2.w;
            }
            const uint4* s0 = wb0 + (it + 1) * 4;
            const uint4* s1 = wb1 + (it + 1) * 4;
#pragma unroll
            for (int j = 0; j < 4; j++) { pb0[j] = s0[j]; pb1[j] = s1[j]; }
        }
        mma_iterG<2, 4>(A0, A1, B0, B1, wr, wc, lane, c);
        __syncthreads();
    }
#pragma unroll
    for (int mt = 0; mt < 2; mt++)
#pragma unroll
        for (int nt = 0; nt < 8; nt++) {
            int gr = m0 + wr * 32 + mt * 16 + g;
            int cc = wc * 64 + nt * 8 + 2 * tg;
            if (gr < ce) {
                g_H1[(size_t)(off + gr) * MHID_ + cc]     = fmaxf(c[mt][nt][0] + bias[cc], 0.f);
                g_H1[(size_t)(off + gr) * MHID_ + cc + 1] = fmaxf(c[mt][nt][1] + bias[cc + 1], 0.f);
            }
            if (gr + 8 < ce) {
                g_H1[(size_t)(off + gr + 8) * MHID_ + cc]     = fmaxf(c[mt][nt][2] + bias[cc], 0.f);
                g_H1[(size_t)(off + gr + 8) * MHID_ + cc + 1] = fmaxf(c[mt][nt][3] + bias[cc + 1], 0.f);
            }
        }
}

// ------------------------------------------------------------------
// Expert GEMM 2: Y = H1 @ e2[e] + b   K=256, N=1024
// ------------------------------------------------------------------
__global__ __launch_bounds__(256) void mma_eg2(const float* __restrict__ e2b)
{
    const int e = blockIdx.z;
    const int ce = g_ecount[e];
    const int m0 = blockIdx.y * 64;
    if (m0 >= ce) return;
    const int off = g_off[e];
    const int col0 = blockIdx.x * 256;
    const bh* W0 = g_e2t0 + (size_t)e * MHID_ * HID_;
    const bh* W1 = g_e2t1 + (size_t)e * MHID_ * HID_;
    const float* bias = e2b + (size_t)e * HID_;

    __shared__ __align__(16) bh A0[64][ROWW], A1[64][ROWW];
    __shared__ __align__(16) bh B0[256][ROWW], B1[256][ROWW];
    const int tid = threadIdx.x;
    const int wid = tid >> 5, lane = tid & 31;
    const int wr = wid >> 2, wc = wid & 3;
    const int g = lane >> 2, tg = lane & 3;
    const int ar = tid >> 2;
    const int ak = (tid & 3) * 8;
    const int gr0 = m0 + ar;
    const float* abase = (gr0 < ce) ? &g_H1[(size_t)(off + gr0) * MHID_ + ak] : nullptr;
    const uint4* wb0 = (const uint4*)&W0[(size_t)(col0 + tid) * MHID_];
    const uint4* wb1 = (const uint4*)&W1[(size_t)(col0 + tid) * MHID_];
    float c[2][8][4] = {};

    float xv[8] = {0.f,0.f,0.f,0.f,0.f,0.f,0.f,0.f};
    uint4 pb0[4], pb1[4];
    {
        if (abase) {
            float4 f1 = *(const float4*)abase;
            float4 f2 = *(const float4*)(abase + 4);
            xv[0]=f1.x; xv[1]=f1.y; xv[2]=f1.z; xv[3]=f1.w;
            xv[4]=f2.x; xv[5]=f2.y; xv[6]=f2.z; xv[7]=f2.w;
        }
#pragma unroll
        for (int j = 0; j < 4; j++) { pb0[j] = wb0[j]; pb1[j] = wb1[j]; }
    }

    for (int it = 0; it < MHID_ / 32; ++it) {
        split8_store(xv, &A0[ar][ak], &A1[ar][ak]);
        {
            uint4* d0 = (uint4*)&B0[tid][0];
            uint4* d1 = (uint4*)&B1[tid][0];
#pragma unroll
            for (int j = 0; j < 4; j++) { d0[j] = pb0[j]; d1[j] = pb1[j]; }
        }
        __syncthreads();
        if (it + 1 < MHID_ / 32) {
            if (abase) {
                const float* ap = abase + (it + 1) * 32;
                float4 f1 = *(const float4*)ap;
                float4 f2 = *(const float4*)(ap + 4);
                xv[0]=f1.x; xv[1]=f1.y; xv[2]=f1.z; xv[3]=f1.w;
                xv[4]=f2.x; xv[5]=f2.y; xv[6]=f2.z; xv[7]=f2.w;
            }
            const uint4* s0 = wb0 + (it + 1) * 4;
            const uint4* s1 = wb1 + (it + 1) * 4;
#pragma unroll
            for (int j = 0; j < 4; j++) { pb0[j] = s0[j]; pb1[j] = s1[j]; }
        }
        mma_iterG<2, 4>(A0, A1, B0, B1, wr, wc, lane, c);
        __syncthreads();
    }
#pragma unroll
    for (int mt = 0; mt < 2; mt++)
#pragma unroll
        for (int nt = 0; nt < 8; nt++) {
            int gr = m0 + wr * 32 + mt * 16 + g;
            int cc = col0 + wc * 64 + nt * 8 + 2 * tg;
            if (gr < ce) {
                g_Y[(size_t)(off + gr) * HID_ + cc]     = c[mt][nt][0] + bias[cc];
                g_Y[(size_t)(off + gr) * HID_ + cc + 1] = c[mt][nt][1] + bias[cc + 1];
            }
            if (gr + 8 < ce) {
                g_Y[(size_t)(off + gr + 8) * HID_ + cc]     = c[mt][nt][2] + bias[cc];
                g_Y[(size_t)(off + gr + 8) * HID_ + cc + 1] = c[mt][nt][3] + bias[cc + 1];
            }
        }
}

// ------------------------------------------------------------------
// Generic fp32 GEMM (se1 K=24, g2 N=32 only)
// ------------------------------------------------------------------
__global__ __launch_bounds__(256) void gemm64(
    const float* __restrict__ A, const float* __restrict__ W,
    const float* __restrict__ bias, float* __restrict__ C,
    int M, int N, int K, int relu_flag)
{
    __shared__ float As[16][68];
    __shared__ float Bs[16][68];
    const int tid = threadIdx.x;
    const int tx = tid & 15, ty = tid >> 4;
    const int row0 = blockIdx.y * 64, col0 = blockIdx.x * 64;
    float acc[4][4] = {};
    for (int k0 = 0; k0 < K; k0 += 16) {
#pragma unroll
        for (int i = 0; i < 4; i++) {
            int id = tid + 256 * i;
            int m = id >> 4, kk = id & 15;
            float v = 0.f;
            int gr = row0 + m, gk = k0 + kk;
            if (gr < M && gk < K) v = A[(size_t)gr * K + gk];
            As[kk][m] = v;
        }
#pragma unroll
        for (int i = 0; i < 4; i++) {
            int id = tid + 256 * i;
            int kk = id >> 6, n = id & 63;
            float v = 0.f;
            int gc = col0 + n, gk = k0 + kk;
            if (gk < K && gc < N) v = W[(size_t)gk * N + gc];
            Bs[kk][n] = v;
        }
        __syncthreads();
        float at[4][4] = {};
#pragma unroll
        for (int kk = 0; kk < 16; kk++) {
            float4 a4 = *(const float4*)&As[kk][ty * 4];
            float4 b4 = *(const float4*)&Bs[kk][tx * 4];
            float av[4] = {a4.x, a4.y, a4.z, a4.w};
            float bv[4] = {b4.x, b4.y, b4.z, b4.w};
#pragma unroll
            for (int i = 0; i < 4; i++)
#pragma unroll
                for (int j = 0; j < 4; j++) at[i][j] += av[i] * bv[j];
        }
#pragma unroll
        for (int i = 0; i < 4; i++)
#pragma unroll
            for (int j = 0; j < 4; j++) acc[i][j] += at[i][j];
        __syncthreads();
    }
#pragma unroll
    for (int i = 0; i < 4; i++) {
        int r = row0 + ty * 4 + i;
        if (r < M) {
#pragma unroll
            for (int j = 0; j < 4; j++) {
                int c = col0 + tx * 4 + j;
                if (c < N) {
                    float v = acc[i][j] + bias[c];
                    if (relu_flag) v = fmaxf(v, 0.f);
                    C[(size_t)r * N + c] = v;
                }
            }
        }
    }
}

// ------------------------------------------------------------------
// reduce partials (double) + bias + LayerNorm + tanh + add state enc
// ------------------------------------------------------------------
__global__ __launch_bounds__(256) void ln_fuse(
    const float* __restrict__ tb, const float* __restrict__ lng,
    const float* __restrict__ lnb)
{
    const int b = blockIdx.x, f = threadIdx.x;
    double vd = (double)tb[f];
#pragma unroll
    for (int s = 0; s < KSPL_; s++)
        vd += (double)g_part[((size_t)s * B_ + b) * FEAT_ + f];
    float v = (float)vd;

    __shared__ float sred[2][8];
    const int wid = f >> 5, lane = f & 31;
    float s1 = v, s2 = v * v;
#pragma unroll
    for (int o = 16; o; o >>= 1) {
        s1 += __shfl_xor_sync(0xffffffffu, s1, o);
        s2 += __shfl_xor_sync(0xffffffffu, s2, o);
    }
    if (lane == 0) { sred[0][wid] = s1; sred[1][wid] = s2; }
    __syncthreads();
    float t1 = 0.f, t2 = 0.f;
#pragma unroll
    for (int i = 0; i < 8; i++) { t1 += sred[0][i]; t2 += sred[1][i]; }
    float mu = t1 * (1.f / FEAT_);
    float var = t2 * (1.f / FEAT_) - mu * mu;
    float y = (v - mu) * rsqrtf(var + 1e-5f) * lng[f] + lnb[f];
    g_h[(size_t)b * FEAT_ + f] = tanhf(y) + g_s[(size_t)b * FEAT_ + f];
}

// ------------------------------------------------------------------
// top-k + softmax weights + importance
// ------------------------------------------------------------------
__global__ __launch_bounds__(256) void topk_kernel()
{
    const int wid = threadIdx.x >> 5, lane = threadIdx.x & 31;
    const int b = blockIdx.x * 8 + wid;
    __shared__ float simp[NE_];
    if (threadIdx.x < NE_) simp[threadIdx.x] = 0.f;
    __syncthreads();

    float v = g_logits[(size_t)b * NE_ + lane];

    float m = v;
#pragma unroll
    for (int o = 16; o; o >>= 1) m = fmaxf(m, __shfl_xor_sync(0xffffffffu, m, o));
    float p = expf(v - m);
    float ps = p;
#pragma unroll
    for (int o = 16; o; o >>= 1) ps += __shfl_xor_sync(0xffffffffu, ps, o);
    atomicAdd(&simp[lane], p / ps);

    const float NEG_INF = __int_as_float(0xff800000);
    float vv = v;
    float tv0 = 0.f, tv1 = 0.f, tv2 = 0.f, tv3 = 0.f;
    int ti0 = 0, ti1 = 0, ti2 = 0, ti3 = 0;
#pragma unroll
    for (int k = 0; k < 4; k++) {
        float mv = vv; int mi = lane;
#pragma unroll
        for (int o = 16; o; o >>= 1) {
            float ov = __shfl_xor_sync(0xffffffffu, mv, o);
            int   oi = __shfl_xor_sync(0xffffffffu, mi, o);
            if (ov > mv || (ov == mv && oi < mi)) { mv = ov; mi = oi; }
        }
        if (k == 0) { tv0 = mv; ti0 = mi; }
        else if (k == 1) { tv1 = mv; ti1 = mi; }
        else if (k == 2) { tv2 = mv; ti2 = mi; }
        else { tv3 = mv; ti3 = mi; }
        if (lane == mi) vv = NEG_INF;
    }
    float e0 = 1.f;
    float e1 = expf(tv1 - tv0);
    float e2 = expf(tv2 - tv0);
    float e3 = expf(tv3 - tv0);
    float sw = e0 + e1 + e2 + e3;

    if (lane < 4) {
        int   mye = (lane == 0) ? ti0 : (lane == 1) ? ti1 : (lane == 2) ? ti2 : ti3;
        float myw = ((lane == 0) ? e0 : (lane == 1) ? e1 : (lane == 2) ? e2 : e3) / sw;
        int pos = atomicAdd(&g_ecount[mye], 1);
        g_elist[mye * B_ + pos] = b;
        g_tok_e[b * TOPK_ + lane] = mye;
        g_tok_pos[b * TOPK_ + lane] = pos;
        g_tok_w[b * TOPK_ + lane] = myw;
    }
    __syncthreads();
    if (threadIdx.x < NE_) atomicAdd(&g_imp[threadIdx.x], simp[threadIdx.x]);
}

// ------------------------------------------------------------------
__global__ void scan_aux(float* aux_out)
{
    if (threadIdx.x == 0) {
        int off = 0;
        float aux = 0.f;
        for (int e = 0; e < NE_; e++) {
            g_off[e] = off;
            off += g_ecount[e];
            aux += (g_imp[e] / (float)B_) * ((float)g_ecount[e] / (float)B_);
        }
        if (aux_out) *aux_out = (float)NE_ * aux;
    }
}

// ------------------------------------------------------------------
__global__ __launch_bounds__(256) void combine_kernel()
{
    const int b = blockIdx.x;
    int   go[TOPK_];
    float w[TOPK_];
#pragma unroll
    for (int k = 0; k < TOPK_; k++) {
        int e = g_tok_e[b * TOPK_ + k];
        go[k] = g_off[e] + g_tok_pos[b * TOPK_ + k];
        w[k] = g_tok_w[b * TOPK_ + k];
    }
    for (int n = threadIdx.x; n < HID_; n += 256) {
        float acc = 0.f;
#pragma unroll
        for (int k = 0; k < TOPK_; k++)
            acc += w[k] * g_Y[(size_t)go[k] * HID_ + n];
        g_xmoe[(size_t)b * HID_ + n] = fmaxf(acc, 0.f);
    }
}

// ------------------------------------------------------------------
__global__ __launch_bounds__(256) void p2_kernel(
    const float* __restrict__ w, const float* __restrict__ bias,
    float* __restrict__ out)
{
    const int b = blockIdx.x;
    __shared__ float xs[HID_];
    for (int i = threadIdx.x; i < HID_; i += 256)
        xs[i] = g_xmoe[(size_t)b * HID_ + i];
    __syncthreads();
    const int wid = threadIdx.x >> 5, lane = threadIdx.x & 31;
    if (wid < ADIM_) {
        float acc = 0.f;
        for (int k = lane; k < HID_; k += 32)
            acc += xs[k] * w[(size_t)k * ADIM_ + wid];
#pragma unroll
        for (int o = 16; o; o >>= 1) acc += __shfl_xor_sync(0xffffffffu, acc, o);
        if (lane == 0) out[(size_t)b * ADIM_ + wid] = tanhf(acc + bias[wid]);
    }
}

// ------------------------------------------------------------------
// launcher
// ------------------------------------------------------------------
extern "C" void kernel_launch(void* const* d_in, const int* in_sizes, int n_in,
                              void* d_out, int out_size)
{
    const float* obs        = (const float*)d_in[0];
    const float* obs_sensor = (const float*)d_in[2];
    const float* trunk_w    = (const float*)d_in[3];
    const float* trunk_b    = (const float*)d_in[4];
    const float* ln_g       = (const float*)d_in[5];
    const float* ln_b       = (const float*)d_in[6];
    const float* se1_w      = (const float*)d_in[7];
    const float* se1_b      = (const float*)d_in[8];
    const float* se2_w      = (const float*)d_in[9];
    const float* se2_b      = (const float*)d_in[10];
    const float* fu1_w      = (const float*)d_in[11];
    const float* fu1_b      = (const float*)d_in[12];
    const float* fu2_w      = (const float*)d_in[13];
    const float* fu2_b      = (const float*)d_in[14];
    const float* p1_w       = (const float*)d_in[15];
    const float* p1_b       = (const float*)d_in[16];
    const float* g1_w       = (const float*)d_in[17];
    const float* g1_b       = (const float*)d_in[18];
    const float* g2_w       = (const float*)d_in[19];
    const float* g2_b       = (const float*)d_in[20];
    const float* e1_w       = (const float*)d_in[21];
    const float* e1_b       = (const float*)d_in[22];
    const float* e2_w       = (const float*)d_in[23];
    const float* e2_b       = (const float*)d_in[24];
    const float* p2_w       = (const float*)d_in[25];
    const float* p2_b       = (const float*)d_in[26];

    float* out = (float*)d_out;
    float* aux_out = (out_size > B_ * ADIM_) ? (out + (size_t)B_ * ADIM_) : nullptr;

    float* hid;    cudaGetSymbolAddress((void**)&hid,    g_hid);
    float* sbuf;   cudaGetSymbolAddress((void**)&sbuf,   g_s);
    float* part;   cudaGetSymbolAddress((void**)&part,   g_part);
    float* hbuf;   cudaGetSymbolAddress((void**)&hbuf,   g_h);
    float* h2buf;  cudaGetSymbolAddress((void**)&h2buf,  g_h2);
    float* xbuf;   cudaGetSymbolAddress((void**)&xbuf,   g_x);
    float* ghbuf;  cudaGetSymbolAddress((void**)&ghbuf,  g_gh);
    float* lgbuf;  cudaGetSymbolAddress((void**)&lgbuf,  g_logits);
    bh *wt0, *wt1, *wd0, *wd1, *e1t0, *e1t1, *e2t0, *e2t1;
    cudaGetSymbolAddress((void**)&wt0, g_wt0);
    cudaGetSymbolAddress((void**)&wt1, g_wt1);
    cudaGetSymbolAddress((void**)&wd0, g_wd0);
    cudaGetSymbolAddress((void**)&wd1, g_wd1);
    cudaGetSymbolAddress((void**)&e1t0, g_e1t0);
    cudaGetSymbolAddress((void**)&e1t1, g_e1t1);
    cudaGetSymbolAddress((void**)&e2t0, g_e2t0);
    cudaGetSymbolAddress((void**)&e2t1, g_e2t1);

    cudaFuncSetAttribute(trunk_mma, cudaFuncAttributeMaxDynamicSharedMemorySize, SMEM_TRUNK);

    zero_kernel<<<1, 32>>>();
    tconv<<<dim3(REPR_/32, FEAT_/32, 1), dim3(32, 8)>>>(trunk_w, wt0, wt1, REPR_, FEAT_);
    tconv<<<dim3(1024/32, 256/32, 1), dim3(32, 8)>>>(se2_w, wd0 + 0*(size_t)WDSZ, wd1 + 0*(size_t)WDSZ, 1024, 256);
    trunk_mma<<<dim3(KSPL_, B_ / 128), 256, SMEM_TRUNK>>>(obs, part);
    tconv<<<dim3(256/32, 1024/32, 1), dim3(32, 8)>>>(fu1_w, wd0 + 1*(size_t)WDSZ, wd1 + 1*(size_t)WDSZ, 256, 1024);
    tconv<<<dim3(1024/32, 256/32, 1), dim3(32, 8)>>>(fu2_w, wd0 + 2*(size_t)WDSZ, wd1 + 2*(size_t)WDSZ, 1024, 256);
    tconv<<<dim3(256/32, 1024/32, 1), dim3(32, 8)>>>(p1_w,  wd0 + 3*(size_t)WDSZ, wd1 + 3*(size_t)WDSZ, 256, 1024);
    tconv<<<dim3(1024/32, 256/32, 1), dim3(32, 8)>>>(g1_w,  wd0 + 4*(size_t)WDSZ, wd1 + 4*(size_t)WDSZ, 1024, 256);
    tconv<<<dim3(HID_/32, MHID_/32, NE_), dim3(32, 8)>>>(e1_w, e1t0, e1t1, HID_, MHID_);
    tconv<<<dim3(MHID_/32, HID_/32, NE_), dim3(32, 8)>>>(e2_w, e2t0, e2t1, MHID_, HID_);

    // state encoder: se1 (K=24, SIMT) -> se2 (MMA)
    gemm64<<<dim3(HID_ / 64, B_ / 64), 256>>>(obs_sensor, se1_w, se1_b, hid,
                                              B_, HID_, SDIM_, 1);
    mma_dense<<<dim3(1, B_ / 64), 256>>>(hid, wd0 + 0*(size_t)WDSZ, wd1 + 0*(size_t)WDSZ,
                                         se2_b, sbuf, FEAT_, HID_, 0);

    // reduce + LN + tanh + add s
    ln_fuse<<<B_, 256>>>(trunk_b, ln_g, ln_b);

    // fusion MLP + policy1 + gate hidden (MMA)
    mma_dense<<<dim3(4, B_ / 64), 256>>>(hbuf, wd0 + 1*(size_t)WDSZ, wd1 + 1*(size_t)WDSZ,
                                         fu1_b, hid, HID_, FEAT_, 1);
    mma_dense<<<dim3(1, B_ / 64), 256>>>(hid, wd0 + 2*(size_t)WDSZ, wd1 + 2*(size_t)WDSZ,
                                         fu2_b, h2buf, FEAT_, HID_, 0);
    mma_dense<<<dim3(4, B_ / 64), 256>>>(h2buf, wd0 + 3*(size_t)WDSZ, wd1 + 3*(size_t)WDSZ,
                                         p1_b, xbuf, HID_, FEAT_, 1);
    mma_dense<<<dim3(1, B_ / 64), 256>>>(xbuf, wd0 + 4*(size_t)WDSZ, wd1 + 4*(size_t)WDSZ,
                                         g1_b, ghbuf, FEAT_, HID_, 1);
    // g2 (N=32, SIMT)
    gemm64<<<dim3(1, B_ / 64), 256>>>(ghbuf, g2_w, g2_b, lgbuf,
                                      B_, NE_, FEAT_, 0);

    // routing
    topk_kernel<<<B_ / 8, 256>>>();
    scan_aux<<<1, 32>>>(aux_out);

    // experts (3-pass MMA, pipelined)
    mma_eg1<<<dim3(1, B_ / 64, NE_), 256>>>(e1_b);
    mma_eg2<<<dim3(4, B_ / 64, NE_), 256>>>(e2_b);

    // combine + policy2
    combine_kernel<<<B_, 256>>>();
    p2_kernel<<<B_, 256>>>(p2_w, p2_b, out);
}

// round 14
// speedup vs baseline: 1.0846x; 1.0846x over previous
#include <cuda_runtime.h>
#include <cuda_bf16.h>
#include <math.h>

#define B_    4096
#define REPR_ 39200
#define FEAT_ 256
#define HID_  1024
#define NE_   32
#define TOPK_ 4
#define SDIM_ 24
#define ADIM_ 7
#define MHID_ 256
#define KSPL_ 35
#define KCH_  1120          // REPR_/KSPL_
#define NROWS_ (B_*TOPK_)
#define ROWW  40            // smem row width (32 k + 8 pad), 80B stride
#define WDSZ  262144        // 1024*256 dense weight slice

typedef __nv_bfloat16 bh;

// ------------------------------------------------------------------
// Device scratch
// ------------------------------------------------------------------
__device__ float g_hid[(size_t)B_*HID_];
__device__ float g_s[(size_t)B_*FEAT_];
__device__ float g_part[(size_t)KSPL_*B_*FEAT_];
__device__ float g_h[(size_t)B_*FEAT_];
__device__ float g_h2[(size_t)B_*FEAT_];
__device__ float g_x[(size_t)B_*HID_];
__device__ float g_gh[(size_t)B_*FEAT_];
__device__ float g_logits[(size_t)B_*NE_];
__device__ float g_imp[NE_];
__device__ int   g_ecount[NE_];
__device__ int   g_off[NE_];
__device__ int   g_elist[NE_*B_];
__device__ int   g_tok_e[B_*TOPK_];
__device__ int   g_tok_pos[B_*TOPK_];
__device__ float g_tok_w[B_*TOPK_];
__device__ float g_H1[(size_t)NROWS_*MHID_];
__device__ float g_Y[(size_t)NROWS_*HID_];
__device__ float g_xmoe[(size_t)B_*HID_];
// 2-plane bf16 splits, TRANSPOSED to [n][k] layout
__device__ bh g_wt0[(size_t)REPR_*FEAT_];
__device__ bh g_wt1[(size_t)REPR_*FEAT_];
__device__ bh g_wd0[5*(size_t)WDSZ];   // se2|fu1|fu2|p1|g1, [n][k]
__device__ bh g_wd1[5*(size_t)WDSZ];
__device__ bh g_e1t0[(size_t)NE_*HID_*MHID_];   // [e][n=256][k=1024]
__device__ bh g_e1t1[(size_t)NE_*HID_*MHID_];
__device__ bh g_e2t0[(size_t)NE_*MHID_*HID_];   // [e][n=1024][k=256]
__device__ bh g_e2t1[(size_t)NE_*MHID_*HID_];

// ------------------------------------------------------------------
__global__ void zero_kernel() {
    int t = threadIdx.x;
    if (t < NE_) { g_ecount[t] = 0; g_imp[t] = 0.f; }
}

// ------------------------------------------------------------------
// transpose + 2-plane split: src [z][K][N] fp32 -> d0/d1 [z][N][K] bf16
// ------------------------------------------------------------------
__global__ __launch_bounds__(256) void tconv(
    const float* __restrict__ src, bh* __restrict__ d0, bh* __restrict__ d1,
    int K, int N)
{
    const int z = blockIdx.z;
    const float* s = src + (size_t)z * K * N;
    bh* p0 = d0 + (size_t)z * K * N;
    bh* p1 = d1 + (size_t)z * K * N;
    __shared__ float t[32][33];
    const int k0 = blockIdx.x * 32, n0 = blockIdx.y * 32;
#pragma unroll
    for (int i = 0; i < 4; i++) {
        int ky = threadIdx.y + 8 * i;
        t[ky][threadIdx.x] = s[(size_t)(k0 + ky) * N + n0 + threadIdx.x];
    }
    __syncthreads();
#pragma unroll
    for (int i = 0; i < 4; i++) {
        int ny = threadIdx.y + 8 * i;
        float x = t[threadIdx.x][ny];
        bh b0 = __float2bfloat16(x);
        size_t o = (size_t)(n0 + ny) * K + k0 + threadIdx.x;
        p0[o] = b0;
        p1[o] = __float2bfloat16(x - __bfloat162float(b0));
    }
}

// ------------------------------------------------------------------
// MMA + LDSM helpers
// ------------------------------------------------------------------
__device__ __forceinline__ void mma_bf16(float c[4], const unsigned a[4], const unsigned b[2]) {
    asm volatile(
        "mma.sync.aligned.m16n8k16.row.col.f32.bf16.bf16.f32 "
        "{%0,%1,%2,%3},{%4,%5,%6,%7},{%8,%9},{%0,%1,%2,%3};\n"
        : "+f"(c[0]), "+f"(c[1]), "+f"(c[2]), "+f"(c[3])
        : "r"(a[0]), "r"(a[1]), "r"(a[2]), "r"(a[3]), "r"(b[0]), "r"(b[1]));
}

__device__ __forceinline__ void ldsm4(unsigned r[4], const bh* p) {
    unsigned addr = (unsigned)__cvta_generic_to_shared(p);
    asm volatile("ldmatrix.sync.aligned.m8n8.x4.shared.b16 {%0,%1,%2,%3}, [%4];"
                 : "=r"(r[0]), "=r"(r[1]), "=r"(r[2]), "=r"(r[3]) : "r"(addr));
}

__device__ __forceinline__ unsigned pk(bh a, bh b) {
    __nv_bfloat162 t(a, b);
    return *(unsigned*)&t;
}

// convert 8 fp32 -> two 16B plane stores at A0/A1[row][kcol]
__device__ __forceinline__ void split8_store(
    const float x[8], bh* a0p, bh* a1p)
{
    unsigned u0[4], u1[4];
#pragma unroll
    for (int j = 0; j < 4; j++) {
        bh h0a = __float2bfloat16(x[2*j]);
        bh h0b = __float2bfloat16(x[2*j+1]);
        bh h1a = __float2bfloat16(x[2*j]   - __bfloat162float(h0a));
        bh h1b = __float2bfloat16(x[2*j+1] - __bfloat162float(h0b));
        u0[j] = pk(h0a, h0b);
        u1[j] = pk(h1a, h1b);
    }
    *(uint4*)a0p = make_uint4(u0[0], u0[1], u0[2], u0[3]);
    *(uint4*)a1p = make_uint4(u1[0], u1[1], u1[2], u1[3]);
}

// 32-k MMA block, MT m-tiles per warp-row, 3-pass split planes, LDSM
template<int MT>
__device__ __forceinline__ void mma_iter32(
    const bh (*A0)[ROWW], const bh (*A1)[ROWW],
    const bh (*B0)[ROWW], const bh (*B1)[ROWW],
    int wr, int wc, int lane, float c[MT][8][4])
{
    const int frow = lane & 15;
    const int fcol = (lane >> 4) << 3;
#pragma unroll
    for (int kh = 0; kh < 2; kh++) {
        const int kc = kh * 16 + fcol;
        unsigned a0f[MT][4], a1f[MT][4];
#pragma unroll
        for (int mt = 0; mt < MT; mt++) {
            ldsm4(a0f[mt], &A0[wr * (MT * 16) + mt * 16 + frow][kc]);
            ldsm4(a1f[mt], &A1[wr * (MT * 16) + mt * 16 + frow][kc]);
        }
#pragma unroll
        for (int p = 0; p < 4; p++) {
            unsigned q0[4], q1[4];
            ldsm4(q0, &B0[wc * 64 + p * 16 + frow][kc]);
            ldsm4(q1, &B1[wc * 64 + p * 16 + frow][kc]);
            unsigned be0[2] = {q0[0], q0[2]}, bo0[2] = {q0[1], q0[3]};
            unsigned be1[2] = {q1[0], q1[2]}, bo1[2] = {q1[1], q1[3]};
#pragma unroll
            for (int mt = 0; mt < MT; mt++) {
                mma_bf16(c[mt][2*p],   a0f[mt], be0);
                mma_bf16(c[mt][2*p],   a0f[mt], be1);
                mma_bf16(c[mt][2*p],   a1f[mt], be0);
                mma_bf16(c[mt][2*p+1], a0f[mt], bo0);
                mma_bf16(c[mt][2*p+1], a0f[mt], bo1);
                mma_bf16(c[mt][2*p+1], a1f[mt], bo0);
            }
        }
    }
}

// ------------------------------------------------------------------
// Trunk GEMM: M-tile 128, N 256, split-K=35, pipelined, LDSM
// ------------------------------------------------------------------
__global__ __launch_bounds__(256) void trunk_mma(
    const float* __restrict__ obs, float* __restrict__ part)
{
    const int s = blockIdx.x;
    const int m0 = blockIdx.y * 128;
    const int kbase = s * KCH_;
    __shared__ __align__(16) bh A0[128][ROWW], A1[128][ROWW];
    __shared__ __align__(16) bh B0[256][ROWW], B1[256][ROWW];
    const int tid = threadIdx.x;
    const int wid = tid >> 5, lane = tid & 31;
    const int wr = wid >> 2, wc = wid & 3;
    const int g = lane >> 2, tg = lane & 3;
    const int ar = tid >> 1;            // A row 0..127
    const int ak = (tid & 1) * 16;      // A k-offset 0/16
    float c[4][8][4] = {};

    const float* abase = &obs[(size_t)(m0 + ar) * REPR_ + kbase + ak];
    const uint4* wb0 = (const uint4*)&g_wt0[(size_t)tid * REPR_ + kbase];
    const uint4* wb1 = (const uint4*)&g_wt1[(size_t)tid * REPR_ + kbase];

    float xv[16];
    uint4 pb0[4], pb1[4];
    {
        float4 f1 = *(const float4*)abase;
        float4 f2 = *(const float4*)(abase + 4);
        float4 f3 = *(const float4*)(abase + 8);
        float4 f4 = *(const float4*)(abase + 12);
        xv[0]=f1.x; xv[1]=f1.y; xv[2]=f1.z; xv[3]=f1.w;
        xv[4]=f2.x; xv[5]=f2.y; xv[6]=f2.z; xv[7]=f2.w;
        xv[8]=f3.x; xv[9]=f3.y; xv[10]=f3.z; xv[11]=f3.w;
        xv[12]=f4.x; xv[13]=f4.y; xv[14]=f4.z; xv[15]=f4.w;
#pragma unroll
        for (int j = 0; j < 4; j++) { pb0[j] = wb0[j]; pb1[j] = wb1[j]; }
    }

    for (int it = 0; it < KCH_ / 32; ++it) {
        split8_store(xv,     &A0[ar][ak],     &A1[ar][ak]);
        split8_store(xv + 8, &A0[ar][ak + 8], &A1[ar][ak + 8]);
        {
            uint4* d0 = (uint4*)&B0[tid][0];
            uint4* d1 = (uint4*)&B1[tid][0];
#pragma unroll
            for (int j = 0; j < 4; j++) { d0[j] = pb0[j]; d1[j] = pb1[j]; }
        }
        __syncthreads();
        if (it + 1 < KCH_ / 32) {
            const float* ap = abase + (it + 1) * 32;
            float4 f1 = *(const float4*)ap;
            float4 f2 = *(const float4*)(ap + 4);
            float4 f3 = *(const float4*)(ap + 8);
            float4 f4 = *(const float4*)(ap + 12);
            xv[0]=f1.x; xv[1]=f1.y; xv[2]=f1.z; xv[3]=f1.w;
            xv[4]=f2.x; xv[5]=f2.y; xv[6]=f2.z; xv[7]=f2.w;
            xv[8]=f3.x; xv[9]=f3.y; xv[10]=f3.z; xv[11]=f3.w;
            xv[12]=f4.x; xv[13]=f4.y; xv[14]=f4.z; xv[15]=f4.w;
            const uint4* s0 = wb0 + (it + 1) * 4;
            const uint4* s1 = wb1 + (it + 1) * 4;
#pragma unroll
            for (int j = 0; j < 4; j++) { pb0[j] = s0[j]; pb1[j] = s1[j]; }
        }
        mma_iter32<4>(A0, A1, B0, B1, wr, wc, lane, c);
        __syncthreads();
    }
#pragma unroll
    for (int mt = 0; mt < 4; mt++)
#pragma unroll
        for (int nt = 0; nt < 8; nt++) {
            int r = m0 + wr * 64 + mt * 16 + g;
            int cc = wc * 64 + nt * 8 + 2 * tg;
            float* p = &part[((size_t)s * B_ + r) * FEAT_ + cc];
            p[0] = c[mt][nt][0];
            p[1] = c[mt][nt][1];
            float* q = p + 8 * FEAT_;
            q[0] = c[mt][nt][2];
            q[1] = c[mt][nt][3];
        }
}

// ------------------------------------------------------------------
// Dense MMA GEMM (M-tile 64): C[4096,N] = act(A @ Wplanes + bias)
// grid (N/256, 64); pipelined, 3-pass
// ------------------------------------------------------------------
__global__ __launch_bounds__(256) void mma_dense(
    const float* __restrict__ A,
    const bh* __restrict__ W0, const bh* __restrict__ W1,
    const float* __restrict__ bias, float* __restrict__ C,
    int N, int K, int relu_flag)
{
    const int col0 = blockIdx.x * 256;
    const int m0 = blockIdx.y * 64;
    __shared__ __align__(16) bh A0[64][ROWW], A1[64][ROWW];
    __shared__ __align__(16) bh B0[256][ROWW], B1[256][ROWW];
    const int tid = threadIdx.x;
    const int wid = tid >> 5, lane = tid & 31;
    const int wr = wid >> 2, wc = wid & 3;
    const int g = lane >> 2, tg = lane & 3;
    const int ar = tid >> 2;
    const int ak = (tid & 3) * 8;
    float c[2][8][4] = {};

    const float* abase = &A[(size_t)(m0 + ar) * K + ak];
    const uint4* wb0 = (const uint4*)&W0[(size_t)(col0 + tid) * K];
    const uint4* wb1 = (const uint4*)&W1[(size_t)(col0 + tid) * K];

    float xv[8];
    uint4 pb0[4], pb1[4];
    {
        float4 f1 = *(const float4*)abase;
        float4 f2 = *(const float4*)(abase + 4);
        xv[0]=f1.x; xv[1]=f1.y; xv[2]=f1.z; xv[3]=f1.w;
        xv[4]=f2.x; xv[5]=f2.y; xv[6]=f2.z; xv[7]=f2.w;
#pragma unroll
        for (int j = 0; j < 4; j++) { pb0[j] = wb0[j]; pb1[j] = wb1[j]; }
    }

    const int iters = K / 32;
    for (int it = 0; it < iters; ++it) {
        split8_store(xv, &A0[ar][ak], &A1[ar][ak]);
        {
            uint4* d0 = (uint4*)&B0[tid][0];
            uint4* d1 = (uint4*)&B1[tid][0];
#pragma unroll
            for (int j = 0; j < 4; j++) { d0[j] = pb0[j]; d1[j] = pb1[j]; }
        }
        __syncthreads();
        if (it + 1 < iters) {
            const float* ap = abase + (it + 1) * 32;
            float4 f1 = *(const float4*)ap;
            float4 f2 = *(const float4*)(ap + 4);
            xv[0]=f1.x; xv[1]=f1.y; xv[2]=f1.z; xv[3]=f1.w;
            xv[4]=f2.x; xv[5]=f2.y; xv[6]=f2.z; xv[7]=f2.w;
            const uint4* s0 = wb0 + (it + 1) * 4;
            const uint4* s1 = wb1 + (it + 1) * 4;
#pragma unroll
            for (int j = 0; j < 4; j++) { pb0[j] = s0[j]; pb1[j] = s1[j]; }
        }
        mma_iter32<2>(A0, A1, B0, B1, wr, wc, lane, c);
        __syncthreads();
    }
#pragma unroll
    for (int mt = 0; mt < 2; mt++)
#pragma unroll
        for (int nt = 0; nt < 8; nt++) {
            int r = m0 + wr * 32 + mt * 16 + g;
            int cc = col0 + wc * 64 + nt * 8 + 2 * tg;
            float v0 = c[mt][nt][0] + bias[cc];
            float v1 = c[mt][nt][1] + bias[cc + 1];
            float v2 = c[mt][nt][2] + bias[cc];
            float v3 = c[mt][nt][3] + bias[cc + 1];
            if (relu_flag) {
                v0 = fmaxf(v0, 0.f); v1 = fmaxf(v1, 0.f);
                v2 = fmaxf(v2, 0.f); v3 = fmaxf(v3, 0.f);
            }
            C[(size_t)r * N + cc] = v0;
            C[(size_t)r * N + cc + 1] = v1;
            C[(size_t)(r + 8) * N + cc] = v2;
            C[(size_t)(r + 8) * N + cc + 1] = v3;
        }
}

// ------------------------------------------------------------------
// Expert GEMM 1: H1 = relu(gather(x) @ e1[e] + b)  K=1024, N=256
// ------------------------------------------------------------------
__global__ __launch_bounds__(256) void mma_eg1(const float* __restrict__ e1b)
{
    const int e = blockIdx.z;
    const int ce = g_ecount[e];
    const int m0 = blockIdx.y * 64;
    if (m0 >= ce) return;
    const int off = g_off[e];
    const bh* W0 = g_e1t0 + (size_t)e * HID_ * MHID_;
    const bh* W1 = g_e1t1 + (size_t)e * HID_ * MHID_;
    const float* bias = e1b + (size_t)e * MHID_;

    __shared__ __align__(16) bh A0[64][ROWW], A1[64][ROWW];
    __shared__ __align__(16) bh B0[256][ROWW], B1[256][ROWW];
    const int tid = threadIdx.x;
    const int wid = tid >> 5, lane = tid & 31;
    const int wr = wid >> 2, wc = wid & 3;
    const int g = lane >> 2, tg = lane & 3;
    const int ar = tid >> 2;
    const int ak = (tid & 3) * 8;
    const int gr0 = m0 + ar;
    const int tok = (gr0 < ce) ? g_elist[e * B_ + gr0] : -1;
    const float* abase = (tok >= 0) ? &g_x[(size_t)tok * HID_ + ak] : nullptr;
    const uint4* wb0 = (const uint4*)&W0[(size_t)tid * HID_];
    const uint4* wb1 = (const uint4*)&W1[(size_t)tid * HID_];
    float c[2][8][4] = {};

    float xv[8] = {0.f,0.f,0.f,0.f,0.f,0.f,0.f,0.f};
    uint4 pb0[4], pb1[4];
    {
        if (abase) {
            float4 f1 = *(const float4*)abase;
            float4 f2 = *(const float4*)(abase + 4);
            xv[0]=f1.x; xv[1]=f1.y; xv[2]=f1.z; xv[3]=f1.w;
            xv[4]=f2.x; xv[5]=f2.y; xv[6]=f2.z; xv[7]=f2.w;
        }
#pragma unroll
        for (int j = 0; j < 4; j++) { pb0[j] = wb0[j]; pb1[j] = wb1[j]; }
    }

    for (int it = 0; it < HID_ / 32; ++it) {
        split8_store(xv, &A0[ar][ak], &A1[ar][ak]);
        {
            uint4* d0 = (uint4*)&B0[tid][0];
            uint4* d1 = (uint4*)&B1[tid][0];
#pragma unroll
            for (int j = 0; j < 4; j++) { d0[j] = pb0[j]; d1[j] = pb1[j]; }
        }
        __syncthreads();
        if (it + 1 < HID_ / 32) {
            if (abase) {
                const float* ap = abase + (it + 1) * 32;
                float4 f1 = *(const float4*)ap;
                float4 f2 = *(const float4*)(ap + 4);
                xv[0]=f1.x; xv[1]=f1.y; xv[2]=f1.z; xv[3]=f1.w;
                xv[4]=f2.x; xv[5]=f2.y; xv[6]=f2.z; xv[7]=f2.w;
            }
            const uint4* s0 = wb0 + (it + 1) * 4;
            const uint4* s1 = wb1 + (it + 1) * 4;
#pragma unroll
            for (int j = 0; j < 4; j++) { pb0[j] = s0[j]; pb1[j] = s1[j]; }
        }
        mma_iter32<2>(A0, A1, B0, B1, wr, wc, lane, c);
        __syncthreads();
    }
#pragma unroll
    for (int mt = 0; mt < 2; mt++)
#pragma unroll
        for (int nt = 0; nt < 8; nt++) {
            int gr = m0 + wr * 32 + mt * 16 + g;
            int cc = wc * 64 + nt * 8 + 2 * tg;
            if (gr < ce) {
                g_H1[(size_t)(off + gr) * MHID_ + cc]     = fmaxf(c[mt][nt][0] + bias[cc], 0.f);
                g_H1[(size_t)(off + gr) * MHID_ + cc + 1] = fmaxf(c[mt][nt][1] + bias[cc + 1], 0.f);
            }
            if (gr + 8 < ce) {
                g_H1[(size_t)(off + gr + 8) * MHID_ + cc]     = fmaxf(c[mt][nt][2] + bias[cc], 0.f);
                g_H1[(size_t)(off + gr + 8) * MHID_ + cc + 1] = fmaxf(c[mt][nt][3] + bias[cc + 1], 0.f);
            }
        }
}

// ------------------------------------------------------------------
// Expert GEMM 2: Y = H1 @ e2[e] + b   K=256, N=1024; pipelined
// ------------------------------------------------------------------
__global__ __launch_bounds__(256) void mma_eg2(const float* __restrict__ e2b)
{
    const int e = blockIdx.z;
    const int ce = g_ecount[e];
    const int m0 = blockIdx.y * 64;
    if (m0 >= ce) return;
    const int off = g_off[e];
    const int col0 = blockIdx.x * 256;
    const bh* W0 = g_e2t0 + (size_t)e * MHID_ * HID_;
    const bh* W1 = g_e2t1 + (size_t)e * MHID_ * HID_;
    const float* bias = e2b + (size_t)e * HID_;

    __shared__ __align__(16) bh A0[64][ROWW], A1[64][ROWW];
    __shared__ __align__(16) bh B0[256][ROWW], B1[256][ROWW];
    const int tid = threadIdx.x;
    const int wid = tid >> 5, lane = tid & 31;
    const int wr = wid >> 2, wc = wid & 3;
    const int g = lane >> 2, tg = lane & 3;
    const int ar = tid >> 2;
    const int ak = (tid & 3) * 8;
    const int gr0 = m0 + ar;
    const float* abase = (gr0 < ce) ? &g_H1[(size_t)(off + gr0) * MHID_ + ak] : nullptr;
    const uint4* wb0 = (const uint4*)&W0[(size_t)(col0 + tid) * MHID_];
    const uint4* wb1 = (const uint4*)&W1[(size_t)(col0 + tid) * MHID_];
    float c[2][8][4] = {};

    float xv[8] = {0.f,0.f,0.f,0.f,0.f,0.f,0.f,0.f};
    uint4 pb0[4], pb1[4];
    {
        if (abase) {
            float4 f1 = *(const float4*)abase;
            float4 f2 = *(const float4*)(abase + 4);
            xv[0]=f1.x; xv[1]=f1.y; xv[2]=f1.z; xv[3]=f1.w;
            xv[4]=f2.x; xv[5]=f2.y; xv[6]=f2.z; xv[7]=f2.w;
        }
#pragma unroll
        for (int j = 0; j < 4; j++) { pb0[j] = wb0[j]; pb1[j] = wb1[j]; }
    }

    for (int it = 0; it < MHID_ / 32; ++it) {
        split8_store(xv, &A0[ar][ak], &A1[ar][ak]);
        {
            uint4* d0 = (uint4*)&B0[tid][0];
            uint4* d1 = (uint4*)&B1[tid][0];
#pragma unroll
            for (int j = 0; j < 4; j++) { d0[j] = pb0[j]; d1[j] = pb1[j]; }
        }
        __syncthreads();
        if (it + 1 < MHID_ / 32) {
            if (abase) {
                const float* ap = abase + (it + 1) * 32;
                float4 f1 = *(const float4*)ap;
                float4 f2 = *(const float4*)(ap + 4);
                xv[0]=f1.x; xv[1]=f1.y; xv[2]=f1.z; xv[3]=f1.w;
                xv[4]=f2.x; xv[5]=f2.y; xv[6]=f2.z; xv[7]=f2.w;
            }
            const uint4* s0 = wb0 + (it + 1) * 4;
            const uint4* s1 = wb1 + (it + 1) * 4;
#pragma unroll
            for (int j = 0; j < 4; j++) { pb0[j] = s0[j]; pb1[j] = s1[j]; }
        }
        mma_iter32<2>(A0, A1, B0, B1, wr, wc, lane, c);
        __syncthreads();
    }
#pragma unroll
    for (int mt = 0; mt < 2; mt++)
#pragma unroll
        for (int nt = 0; nt < 8; nt++) {
            int gr = m0 + wr * 32 + mt * 16 + g;
            int cc = col0 + wc * 64 + nt * 8 + 2 * tg;
            if (gr < ce) {
                g_Y[(size_t)(off + gr) * HID_ + cc]     = c[mt][nt][0] + bias[cc];
                g_Y[(size_t)(off + gr) * HID_ + cc + 1] = c[mt][nt][1] + bias[cc + 1];
            }
            if (gr + 8 < ce) {
                g_Y[(size_t)(off + gr + 8) * HID_ + cc]     = c[mt][nt][2] + bias[cc];
                g_Y[(size_t)(off + gr + 8) * HID_ + cc + 1] = c[mt][nt][3] + bias[cc + 1];
            }
        }
}

// ------------------------------------------------------------------
// Generic fp32 GEMM (se1 K=24, g2 N=32 only)
// ------------------------------------------------------------------
__global__ __launch_bounds__(256) void gemm64(
    const float* __restrict__ A, const float* __restrict__ W,
    const float* __restrict__ bias, float* __restrict__ C,
    int M, int N, int K, int relu_flag)
{
    __shared__ float As[16][68];
    __shared__ float Bs[16][68];
    const int tid = threadIdx.x;
    const int tx = tid & 15, ty = tid >> 4;
    const int row0 = blockIdx.y * 64, col0 = blockIdx.x * 64;
    float acc[4][4] = {};
    for (int k0 = 0; k0 < K; k0 += 16) {
#pragma unroll
        for (int i = 0; i < 4; i++) {
            int id = tid + 256 * i;
            int m = id >> 4, kk = id & 15;
            float v = 0.f;
            int gr = row0 + m, gk = k0 + kk;
            if (gr < M && gk < K) v = A[(size_t)gr * K + gk];
            As[kk][m] = v;
        }
#pragma unroll
        for (int i = 0; i < 4; i++) {
            int id = tid + 256 * i;
            int kk = id >> 6, n = id & 63;
            float v = 0.f;
            int gc = col0 + n, gk = k0 + kk;
            if (gk < K && gc < N) v = W[(size_t)gk * N + gc];
            Bs[kk][n] = v;
        }
        __syncthreads();
        float at[4][4] = {};
#pragma unroll
        for (int kk = 0; kk < 16; kk++) {
            float4 a4 = *(const float4*)&As[kk][ty * 4];
            float4 b4 = *(const float4*)&Bs[kk][tx * 4];
            float av[4] = {a4.x, a4.y, a4.z, a4.w};
            float bv[4] = {b4.x, b4.y, b4.z, b4.w};
#pragma unroll
            for (int i = 0; i < 4; i++)
#pragma unroll
                for (int j = 0; j < 4; j++) at[i][j] += av[i] * bv[j];
        }
#pragma unroll
        for (int i = 0; i < 4; i++)
#pragma unroll
            for (int j = 0; j < 4; j++) acc[i][j] += at[i][j];
        __syncthreads();
    }
#pragma unroll
    for (int i = 0; i < 4; i++) {
        int r = row0 + ty * 4 + i;
        if (r < M) {
#pragma unroll
            for (int j = 0; j < 4; j++) {
                int c = col0 + tx * 4 + j;
                if (c < N) {
                    float v = acc[i][j] + bias[c];
                    if (relu_flag) v = fmaxf(v, 0.f);
                    C[(size_t)r * N + c] = v;
                }
            }
        }
    }
}

// ------------------------------------------------------------------
// reduce partials (double) + bias + LayerNorm + tanh + add state enc
// ------------------------------------------------------------------
__global__ __launch_bounds__(256) void ln_fuse(
    const float* __restrict__ tb, const float* __restrict__ lng,
    const float* __restrict__ lnb)
{
    const int b = blockIdx.x, f = threadIdx.x;
    double vd = (double)tb[f];
#pragma unroll
    for (int s = 0; s < KSPL_; s++)
        vd += (double)g_part[((size_t)s * B_ + b) * FEAT_ + f];
    float v = (float)vd;

    __shared__ float sred[2][8];
    const int wid = f >> 5, lane = f & 31;
    float s1 = v, s2 = v * v;
#pragma unroll
    for (int o = 16; o; o >>= 1) {
        s1 += __shfl_xor_sync(0xffffffffu, s1, o);
        s2 += __shfl_xor_sync(0xffffffffu, s2, o);
    }
    if (lane == 0) { sred[0][wid] = s1; sred[1][wid] = s2; }
    __syncthreads();
    float t1 = 0.f, t2 = 0.f;
#pragma unroll
    for (int i = 0; i < 8; i++) { t1 += sred[0][i]; t2 += sred[1][i]; }
    float mu = t1 * (1.f / FEAT_);
    float var = t2 * (1.f / FEAT_) - mu * mu;
    float y = (v - mu) * rsqrtf(var + 1e-5f) * lng[f] + lnb[f];
    g_h[(size_t)b * FEAT_ + f] = tanhf(y) + g_s[(size_t)b * FEAT_ + f];
}

// ------------------------------------------------------------------
// top-k + softmax weights + importance
// ------------------------------------------------------------------
__global__ __launch_bounds__(256) void topk_kernel()
{
    const int wid = threadIdx.x >> 5, lane = threadIdx.x & 31;
    const int b = blockIdx.x * 8 + wid;
    __shared__ float simp[NE_];
    if (threadIdx.x < NE_) simp[threadIdx.x] = 0.f;
    __syncthreads();

    float v = g_logits[(size_t)b * NE_ + lane];

    float m = v;
#pragma unroll
    for (int o = 16; o; o >>= 1) m = fmaxf(m, __shfl_xor_sync(0xffffffffu, m, o));
    float p = expf(v - m);
    float ps = p;
#pragma unroll
    for (int o = 16; o; o >>= 1) ps += __shfl_xor_sync(0xffffffffu, ps, o);
    atomicAdd(&simp[lane], p / ps);

    const float NEG_INF = __int_as_float(0xff800000);
    float vv = v;
    float tv0 = 0.f, tv1 = 0.f, tv2 = 0.f, tv3 = 0.f;
    int ti0 = 0, ti1 = 0, ti2 = 0, ti3 = 0;
#pragma unroll
    for (int k = 0; k < 4; k++) {
        float mv = vv; int mi = lane;
#pragma unroll
        for (int o = 16; o; o >>= 1) {
            float ov = __shfl_xor_sync(0xffffffffu, mv, o);
            int   oi = __shfl_xor_sync(0xffffffffu, mi, o);
            if (ov > mv || (ov == mv && oi < mi)) { mv = ov; mi = oi; }
        }
        if (k == 0) { tv0 = mv; ti0 = mi; }
        else if (k == 1) { tv1 = mv; ti1 = mi; }
        else if (k == 2) { tv2 = mv; ti2 = mi; }
        else { tv3 = mv; ti3 = mi; }
        if (lane == mi) vv = NEG_INF;
    }
    float e0 = 1.f;
    float e1 = expf(tv1 - tv0);
    float e2 = expf(tv2 - tv0);
    float e3 = expf(tv3 - tv0);
    float sw = e0 + e1 + e2 + e3;

    if (lane < 4) {
        int   mye = (lane == 0) ? ti0 : (lane == 1) ? ti1 : (lane == 2) ? ti2 : ti3;
        float myw = ((lane == 0) ? e0 : (lane == 1) ? e1 : (lane == 2) ? e2 : e3) / sw;
        int pos = atomicAdd(&g_ecount[mye], 1);
        g_elist[mye * B_ + pos] = b;
        g_tok_e[b * TOPK_ + lane] = mye;
        g_tok_pos[b * TOPK_ + lane] = pos;
        g_tok_w[b * TOPK_ + lane] = myw;
    }
    __syncthreads();
    if (threadIdx.x < NE_) atomicAdd(&g_imp[threadIdx.x], simp[threadIdx.x]);
}

// ------------------------------------------------------------------
__global__ void scan_aux(float* aux_out)
{
    if (threadIdx.x == 0) {
        int off = 0;
        float aux = 0.f;
        for (int e = 0; e < NE_; e++) {
            g_off[e] = off;
            off += g_ecount[e];
            aux += (g_imp[e] / (float)B_) * ((float)g_ecount[e] / (float)B_);
        }
        if (aux_out) *aux_out = (float)NE_ * aux;
    }
}

// ------------------------------------------------------------------
__global__ __launch_bounds__(256) void combine_kernel()
{
    const int b = blockIdx.x;
    int   go[TOPK_];
    float w[TOPK_];
#pragma unroll
    for (int k = 0; k < TOPK_; k++) {
        int e = g_tok_e[b * TOPK_ + k];
        go[k] = g_off[e] + g_tok_pos[b * TOPK_ + k];
        w[k] = g_tok_w[b * TOPK_ + k];
    }
    for (int n = threadIdx.x; n < HID_; n += 256) {
        float acc = 0.f;
#pragma unroll
        for (int k = 0; k < TOPK_; k++)
            acc += w[k] * g_Y[(size_t)go[k] * HID_ + n];
        g_xmoe[(size_t)b * HID_ + n] = fmaxf(acc, 0.f);
    }
}

// ------------------------------------------------------------------
__global__ __launch_bounds__(256) void p2_kernel(
    const float* __restrict__ w, const float* __restrict__ bias,
    float* __restrict__ out)
{
    const int b = blockIdx.x;
    __shared__ float xs[HID_];
    for (int i = threadIdx.x; i < HID_; i += 256)
        xs[i] = g_xmoe[(size_t)b * HID_ + i];
    __syncthreads();
    const int wid = threadIdx.x >> 5, lane = threadIdx.x & 31;
    if (wid < ADIM_) {
        float acc = 0.f;
        for (int k = lane; k < HID_; k += 32)
            acc += xs[k] * w[(size_t)k * ADIM_ + wid];
#pragma unroll
        for (int o = 16; o; o >>= 1) acc += __shfl_xor_sync(0xffffffffu, acc, o);
        if (lane == 0) out[(size_t)b * ADIM_ + wid] = tanhf(acc + bias[wid]);
    }
}

// ------------------------------------------------------------------
// launcher
// ------------------------------------------------------------------
extern "C" void kernel_launch(void* const* d_in, const int* in_sizes, int n_in,
                              void* d_out, int out_size)
{
    const float* obs        = (const float*)d_in[0];
    const float* obs_sensor = (const float*)d_in[2];
    const float* trunk_w    = (const float*)d_in[3];
    const float* trunk_b    = (const float*)d_in[4];
    const float* ln_g       = (const float*)d_in[5];
    const float* ln_b       = (const float*)d_in[6];
    const float* se1_w      = (const float*)d_in[7];
    const float* se1_b      = (const float*)d_in[8];
    const float* se2_w      = (const float*)d_in[9];
    const float* se2_b      = (const float*)d_in[10];
    const float* fu1_w      = (const float*)d_in[11];
    const float* fu1_b      = (const float*)d_in[12];
    const float* fu2_w      = (const float*)d_in[13];
    const float* fu2_b      = (const float*)d_in[14];
    const float* p1_w       = (const float*)d_in[15];
    const float* p1_b       = (const float*)d_in[16];
    const float* g1_w       = (const float*)d_in[17];
    const float* g1_b       = (const float*)d_in[18];
    const float* g2_w       = (const float*)d_in[19];
    const float* g2_b       = (const float*)d_in[20];
    const float* e1_w       = (const float*)d_in[21];
    const float* e1_b       = (const float*)d_in[22];
    const float* e2_w       = (const float*)d_in[23];
    const float* e2_b       = (const float*)d_in[24];
    const float* p2_w       = (const float*)d_in[25];
    const float* p2_b       = (const float*)d_in[26];

    float* out = (float*)d_out;
    float* aux_out = (out_size > B_ * ADIM_) ? (out + (size_t)B_ * ADIM_) : nullptr;

    float* hid;    cudaGetSymbolAddress((void**)&hid,    g_hid);
    float* sbuf;   cudaGetSymbolAddress((void**)&sbuf,   g_s);
    float* part;   cudaGetSymbolAddress((void**)&part,   g_part);
    float* hbuf;   cudaGetSymbolAddress((void**)&hbuf,   g_h);
    float* h2buf;  cudaGetSymbolAddress((void**)&h2buf,  g_h2);
    float* xbuf;   cudaGetSymbolAddress((void**)&xbuf,   g_x);
    float* ghbuf;  cudaGetSymbolAddress((void**)&ghbuf,  g_gh);
    float* lgbuf;  cudaGetSymbolAddress((void**)&lgbuf,  g_logits);
    bh *wt0, *wt1, *wd0, *wd1, *e1t0, *e1t1, *e2t0, *e2t1;
    cudaGetSymbolAddress((void**)&wt0, g_wt0);
    cudaGetSymbolAddress((void**)&wt1, g_wt1);
    cudaGetSymbolAddress((void**)&wd0, g_wd0);
    cudaGetSymbolAddress((void**)&wd1, g_wd1);
    cudaGetSymbolAddress((void**)&e1t0, g_e1t0);
    cudaGetSymbolAddress((void**)&e1t1, g_e1t1);
    cudaGetSymbolAddress((void**)&e2t0, g_e2t0);
    cudaGetSymbolAddress((void**)&e2t1, g_e2t1);

    zero_kernel<<<1, 32>>>();
    tconv<<<dim3(REPR_/32, FEAT_/32, 1), dim3(32, 8)>>>(trunk_w, wt0, wt1, REPR_, FEAT_);
    tconv<<<dim3(1024/32, 256/32, 1), dim3(32, 8)>>>(se2_w, wd0 + 0*(size_t)WDSZ, wd1 + 0*(size_t)WDSZ, 1024, 256);
    trunk_mma<<<dim3(KSPL_, B_ / 128), 256>>>(obs, part);
    tconv<<<dim3(256/32, 1024/32, 1), dim3(32, 8)>>>(fu1_w, wd0 + 1*(size_t)WDSZ, wd1 + 1*(size_t)WDSZ, 256, 1024);
    tconv<<<dim3(1024/32, 256/32, 1), dim3(32, 8)>>>(fu2_w, wd0 + 2*(size_t)WDSZ, wd1 + 2*(size_t)WDSZ, 1024, 256);
    tconv<<<dim3(256/32, 1024/32, 1), dim3(32, 8)>>>(p1_w,  wd0 + 3*(size_t)WDSZ, wd1 + 3*(size_t)WDSZ, 256, 1024);
    tconv<<<dim3(1024/32, 256/32, 1), dim3(32, 8)>>>(g1_w,  wd0 + 4*(size_t)WDSZ, wd1 + 4*(size_t)WDSZ, 1024, 256);
    tconv<<<dim3(HID_/32, MHID_/32, NE_), dim3(32, 8)>>>(e1_w, e1t0, e1t1, HID_, MHID_);
    tconv<<<dim3(MHID_/32, HID_/32, NE_), dim3(32, 8)>>>(e2_w, e2t0, e2t1, MHID_, HID_);

    // state encoder: se1 (K=24, SIMT) -> se2 (MMA)
    gemm64<<<dim3(HID_ / 64, B_ / 64), 256>>>(obs_sensor, se1_w, se1_b, hid,
                                              B_, HID_, SDIM_, 1);
    mma_dense<<<dim3(1, B_ / 64), 256>>>(hid, wd0 + 0*(size_t)WDSZ, wd1 + 0*(size_t)WDSZ,
                                         se2_b, sbuf, FEAT_, HID_, 0);

    // reduce + LN + tanh + add s
    ln_fuse<<<B_, 256>>>(trunk_b, ln_g, ln_b);

    // fusion MLP + policy1 + gate hidden (MMA)
    mma_dense<<<dim3(4, B_ / 64), 256>>>(hbuf, wd0 + 1*(size_t)WDSZ, wd1 + 1*(size_t)WDSZ,
                                         fu1_b, hid, HID_, FEAT_, 1);
    mma_dense<<<dim3(1, B_ / 64), 256>>>(hid, wd0 + 2*(size_t)WDSZ, wd1 + 2*(size_t)WDSZ,
                                         fu2_b, h2buf, FEAT_, HID_, 0);
    mma_dense<<<dim3(4, B_ / 64), 256>>>(h2buf, wd0 + 3*(size_t)WDSZ, wd1 + 3*(size_t)WDSZ,
                                         p1_b, xbuf, HID_, FEAT_, 1);
    mma_dense<<<dim3(1, B_ / 64), 256>>>(xbuf, wd0 + 4*(size_t)WDSZ, wd1 + 4*(size_t)WDSZ,
                                         g1_b, ghbuf, FEAT_, HID_, 1);
    // g2 (N=32, SIMT)
    gemm64<<<dim3(1, B_ / 64), 256>>>(ghbuf, g2_w, g2_b, lgbuf,
                                      B_, NE_, FEAT_, 0);

    // routing
    topk_kernel<<<B_ / 8, 256>>>();
    scan_aux<<<1, 32>>>(aux_out);

    // experts (3-pass MMA, pipelined)
    mma_eg1<<<dim3(1, B_ / 64, NE_), 256>>>(e1_b);
    mma_eg2<<<dim3(4, B_ / 64, NE_), 256>>>(e2_b);

    // combine + policy2
    combine_kernel<<<B_, 256>>>();
    p2_kernel<<<B_, 256>>>(p2_w, p2_b, out);
}

// round 15
// speedup vs baseline: 1.1606x; 1.0701x over previous
#include <cuda_runtime.h>
#include <cuda_bf16.h>
#include <math.h>

#define B_    4096
#define REPR_ 39200
#define FEAT_ 256
#define HID_  1024
#define NE_   32
#define TOPK_ 4
#define SDIM_ 24
#define ADIM_ 7
#define MHID_ 256
#define KSPL_ 35
#define KCH_  1120          // REPR_/KSPL_
#define NROWS_ (B_*TOPK_)
#define ROWW  40            // smem row width (32 k + 8 pad), 80B stride
#define WDSZ  262144        // 1024*256 dense weight slice

typedef __nv_bfloat16 bh;

// ------------------------------------------------------------------
// Device scratch
// ------------------------------------------------------------------
__device__ float g_hid[(size_t)B_*HID_];
__device__ float g_s[(size_t)B_*FEAT_];
__device__ float g_part[(size_t)KSPL_*B_*FEAT_];
__device__ float g_h[(size_t)B_*FEAT_];
__device__ float g_h2[(size_t)B_*FEAT_];
__device__ float g_x[(size_t)B_*HID_];
__device__ float g_gh[(size_t)B_*FEAT_];
__device__ float g_logits[(size_t)B_*NE_];
__device__ float g_imp[NE_];
__device__ int   g_ecount[NE_];
__device__ int   g_off[NE_];
__device__ int   g_elist[NE_*B_];
__device__ int   g_tok_e[B_*TOPK_];
__device__ int   g_tok_pos[B_*TOPK_];
__device__ float g_tok_w[B_*TOPK_];
__device__ float g_H1[(size_t)NROWS_*MHID_];
__device__ float g_Y[(size_t)NROWS_*HID_];
__device__ float g_xmoe[(size_t)B_*HID_];
// 2-plane bf16 splits, TRANSPOSED to [n][k] layout
__device__ bh g_wt0[(size_t)REPR_*FEAT_];
__device__ bh g_wt1[(size_t)REPR_*FEAT_];
__device__ bh g_wd0[5*(size_t)WDSZ];   // se2|fu1|fu2|p1|g1, [n][k]
__device__ bh g_wd1[5*(size_t)WDSZ];
__device__ bh g_e1t0[(size_t)NE_*HID_*MHID_];   // [e][n=256][k=1024]
__device__ bh g_e1t1[(size_t)NE_*HID_*MHID_];
__device__ bh g_e2t0[(size_t)NE_*MHID_*HID_];   // [e][n=1024][k=256]
__device__ bh g_e2t1[(size_t)NE_*MHID_*HID_];

// ------------------------------------------------------------------
__global__ void zero_kernel() {
    int t = threadIdx.x;
    if (t < NE_) { g_ecount[t] = 0; g_imp[t] = 0.f; }
}

// ------------------------------------------------------------------
// transpose + 2-plane split: src [z][K][N] fp32 -> d0/d1 [z][N][K] bf16
// ------------------------------------------------------------------
__global__ __launch_bounds__(256) void tconv(
    const float* __restrict__ src, bh* __restrict__ d0, bh* __restrict__ d1,
    int K, int N)
{
    const int z = blockIdx.z;
    const float* s = src + (size_t)z * K * N;
    bh* p0 = d0 + (size_t)z * K * N;
    bh* p1 = d1 + (size_t)z * K * N;
    __shared__ float t[32][33];
    const int k0 = blockIdx.x * 32, n0 = blockIdx.y * 32;
#pragma unroll
    for (int i = 0; i < 4; i++) {
        int ky = threadIdx.y + 8 * i;
        t[ky][threadIdx.x] = s[(size_t)(k0 + ky) * N + n0 + threadIdx.x];
    }
    __syncthreads();
#pragma unroll
    for (int i = 0; i < 4; i++) {
        int ny = threadIdx.y + 8 * i;
        float x = t[threadIdx.x][ny];
        bh b0 = __float2bfloat16(x);
        size_t o = (size_t)(n0 + ny) * K + k0 + threadIdx.x;
        p0[o] = b0;
        p1[o] = __float2bfloat16(x - __bfloat162float(b0));
    }
}

// ------------------------------------------------------------------
// MMA + LDSM helpers
// ------------------------------------------------------------------
__device__ __forceinline__ void mma_bf16(float c[4], const unsigned a[4], const unsigned b[2]) {
    asm volatile(
        "mma.sync.aligned.m16n8k16.row.col.f32.bf16.bf16.f32 "
        "{%0,%1,%2,%3},{%4,%5,%6,%7},{%8,%9},{%0,%1,%2,%3};\n"
        : "+f"(c[0]), "+f"(c[1]), "+f"(c[2]), "+f"(c[3])
        : "r"(a[0]), "r"(a[1]), "r"(a[2]), "r"(a[3]), "r"(b[0]), "r"(b[1]));
}

__device__ __forceinline__ void ldsm4(unsigned r[4], const bh* p) {
    unsigned addr = (unsigned)__cvta_generic_to_shared(p);
    asm volatile("ldmatrix.sync.aligned.m8n8.x4.shared.b16 {%0,%1,%2,%3}, [%4];"
                 : "=r"(r[0]), "=r"(r[1]), "=r"(r[2]), "=r"(r[3]) : "r"(addr));
}

__device__ __forceinline__ unsigned pk(bh a, bh b) {
    __nv_bfloat162 t(a, b);
    return *(unsigned*)&t;
}

// convert 8 fp32 -> two 16B plane stores at A0/A1[row][kcol]
__device__ __forceinline__ void split8_store(
    const float x[8], bh* a0p, bh* a1p)
{
    unsigned u0[4], u1[4];
#pragma unroll
    for (int j = 0; j < 4; j++) {
        bh h0a = __float2bfloat16(x[2*j]);
        bh h0b = __float2bfloat16(x[2*j+1]);
        bh h1a = __float2bfloat16(x[2*j]   - __bfloat162float(h0a));
        bh h1b = __float2bfloat16(x[2*j+1] - __bfloat162float(h0b));
        u0[j] = pk(h0a, h0b);
        u1[j] = pk(h1a, h1b);
    }
    *(uint4*)a0p = make_uint4(u0[0], u0[1], u0[2], u0[3]);
    *(uint4*)a1p = make_uint4(u1[0], u1[1], u1[2], u1[3]);
}

// 32-k MMA block: MT m-tiles per warp-row, NP n-16-pairs per warp-col
// (per-element accumulation order identical across NP choices)
template<int MT, int NP>
__device__ __forceinline__ void mma_iterT(
    const bh (*A0)[ROWW], const bh (*A1)[ROWW],
    const bh (*B0)[ROWW], const bh (*B1)[ROWW],
    int wr, int wc, int lane, float c[MT][2*NP][4])
{
    const int frow = lane & 15;
    const int fcol = (lane >> 4) << 3;
#pragma unroll
    for (int kh = 0; kh < 2; kh++) {
        const int kc = kh * 16 + fcol;
        unsigned a0f[MT][4], a1f[MT][4];
#pragma unroll
        for (int mt = 0; mt < MT; mt++) {
            ldsm4(a0f[mt], &A0[wr * (MT * 16) + mt * 16 + frow][kc]);
            ldsm4(a1f[mt], &A1[wr * (MT * 16) + mt * 16 + frow][kc]);
        }
#pragma unroll
        for (int p = 0; p < NP; p++) {
            unsigned q0[4], q1[4];
            ldsm4(q0, &B0[wc * (NP * 16) + p * 16 + frow][kc]);
            ldsm4(q1, &B1[wc * (NP * 16) + p * 16 + frow][kc]);
            unsigned be0[2] = {q0[0], q0[2]}, bo0[2] = {q0[1], q0[3]};
            unsigned be1[2] = {q1[0], q1[2]}, bo1[2] = {q1[1], q1[3]};
#pragma unroll
            for (int mt = 0; mt < MT; mt++) {
                mma_bf16(c[mt][2*p],   a0f[mt], be0);
                mma_bf16(c[mt][2*p],   a0f[mt], be1);
                mma_bf16(c[mt][2*p],   a1f[mt], be0);
                mma_bf16(c[mt][2*p+1], a0f[mt], bo0);
                mma_bf16(c[mt][2*p+1], a0f[mt], bo1);
                mma_bf16(c[mt][2*p+1], a1f[mt], bo0);
            }
        }
    }
}

// ------------------------------------------------------------------
// Trunk GEMM: M-tile 128, N 256, split-K=35, pipelined, LDSM (R10 shape)
// ------------------------------------------------------------------
__global__ __launch_bounds__(256) void trunk_mma(
    const float* __restrict__ obs, float* __restrict__ part)
{
    const int s = blockIdx.x;
    const int m0 = blockIdx.y * 128;
    const int kbase = s * KCH_;
    __shared__ __align__(16) bh A0[128][ROWW], A1[128][ROWW];
    __shared__ __align__(16) bh B0[256][ROWW], B1[256][ROWW];
    const int tid = threadIdx.x;
    const int wid = tid >> 5, lane = tid & 31;
    const int wr = wid >> 2, wc = wid & 3;
    const int g = lane >> 2, tg = lane & 3;
    const int ar = tid >> 1;            // A row 0..127
    const int ak = (tid & 1) * 16;      // A k-offset 0/16
    float c[4][8][4] = {};

    const float* abase = &obs[(size_t)(m0 + ar) * REPR_ + kbase + ak];
    const uint4* wb0 = (const uint4*)&g_wt0[(size_t)tid * REPR_ + kbase];
    const uint4* wb1 = (const uint4*)&g_wt1[(size_t)tid * REPR_ + kbase];

    float xv[16];
    uint4 pb0[4], pb1[4];
    {
        float4 f1 = *(const float4*)abase;
        float4 f2 = *(const float4*)(abase + 4);
        float4 f3 = *(const float4*)(abase + 8);
        float4 f4 = *(const float4*)(abase + 12);
        xv[0]=f1.x; xv[1]=f1.y; xv[2]=f1.z; xv[3]=f1.w;
        xv[4]=f2.x; xv[5]=f2.y; xv[6]=f2.z; xv[7]=f2.w;
        xv[8]=f3.x; xv[9]=f3.y; xv[10]=f3.z; xv[11]=f3.w;
        xv[12]=f4.x; xv[13]=f4.y; xv[14]=f4.z; xv[15]=f4.w;
#pragma unroll
        for (int j = 0; j < 4; j++) { pb0[j] = wb0[j]; pb1[j] = wb1[j]; }
    }

    for (int it = 0; it < KCH_ / 32; ++it) {
        split8_store(xv,     &A0[ar][ak],     &A1[ar][ak]);
        split8_store(xv + 8, &A0[ar][ak + 8], &A1[ar][ak + 8]);
        {
            uint4* d0 = (uint4*)&B0[tid][0];
            uint4* d1 = (uint4*)&B1[tid][0];
#pragma unroll
            for (int j = 0; j < 4; j++) { d0[j] = pb0[j]; d1[j] = pb1[j]; }
        }
        __syncthreads();
        if (it + 1 < KCH_ / 32) {
            const float* ap = abase + (it + 1) * 32;
            float4 f1 = *(const float4*)ap;
            float4 f2 = *(const float4*)(ap + 4);
            float4 f3 = *(const float4*)(ap + 8);
            float4 f4 = *(const float4*)(ap + 12);
            xv[0]=f1.x; xv[1]=f1.y; xv[2]=f1.z; xv[3]=f1.w;
            xv[4]=f2.x; xv[5]=f2.y; xv[6]=f2.z; xv[7]=f2.w;
            xv[8]=f3.x; xv[9]=f3.y; xv[10]=f3.z; xv[11]=f3.w;
            xv[12]=f4.x; xv[13]=f4.y; xv[14]=f4.z; xv[15]=f4.w;
            const uint4* s0 = wb0 + (it + 1) * 4;
            const uint4* s1 = wb1 + (it + 1) * 4;
#pragma unroll
            for (int j = 0; j < 4; j++) { pb0[j] = s0[j]; pb1[j] = s1[j]; }
        }
        mma_iterT<4, 4>(A0, A1, B0, B1, wr, wc, lane, c);
        __syncthreads();
    }
#pragma unroll
    for (int mt = 0; mt < 4; mt++)
#pragma unroll
        for (int nt = 0; nt < 8; nt++) {
            int r = m0 + wr * 64 + mt * 16 + g;
            int cc = wc * 64 + nt * 8 + 2 * tg;
            float* p = &part[((size_t)s * B_ + r) * FEAT_ + cc];
            p[0] = c[mt][nt][0];
            p[1] = c[mt][nt][1];
            float* q = p + 8 * FEAT_;
            q[0] = c[mt][nt][2];
            q[1] = c[mt][nt][3];
        }
}

// ------------------------------------------------------------------
// Dense MMA GEMM, N-tile 128 (better SM coverage for the serial chain):
// grid (N/128, 64); M-tile 64; pipelined, 3-pass
// ------------------------------------------------------------------
__global__ __launch_bounds__(256) void mma_dense128(
    const float* __restrict__ A,
    const bh* __restrict__ W0, const bh* __restrict__ W1,
    const float* __restrict__ bias, float* __restrict__ C,
    int N, int K, int relu_flag)
{
    const int col0 = blockIdx.x * 128;
    const int m0 = blockIdx.y * 64;
    __shared__ __align__(16) bh A0[64][ROWW], A1[64][ROWW];
    __shared__ __align__(16) bh B0[128][ROWW], B1[128][ROWW];
    const int tid = threadIdx.x;
    const int wid = tid >> 5, lane = tid & 31;
    const int wr = wid >> 2, wc = wid & 3;
    const int g = lane >> 2, tg = lane & 3;
    const int ar = tid >> 2;
    const int ak = (tid & 3) * 8;
    const int brow = tid >> 1;          // B row 0..127
    const int bk = (tid & 1) * 16;      // B k-offset 0/16
    float c[2][4][4] = {};

    const float* abase = &A[(size_t)(m0 + ar) * K + ak];
    const bh* w0p = &W0[(size_t)(col0 + brow) * K + bk];
    const bh* w1p = &W1[(size_t)(col0 + brow) * K + bk];

    float xv[8];
    uint4 pb0[2], pb1[2];
    {
        float4 f1 = *(const float4*)abase;
        float4 f2 = *(const float4*)(abase + 4);
        xv[0]=f1.x; xv[1]=f1.y; xv[2]=f1.z; xv[3]=f1.w;
        xv[4]=f2.x; xv[5]=f2.y; xv[6]=f2.z; xv[7]=f2.w;
        const uint4* s0 = (const uint4*)w0p;
        const uint4* s1 = (const uint4*)w1p;
        pb0[0] = s0[0]; pb0[1] = s0[1];
        pb1[0] = s1[0]; pb1[1] = s1[1];
    }

    const int iters = K / 32;
    for (int it = 0; it < iters; ++it) {
        split8_store(xv, &A0[ar][ak], &A1[ar][ak]);
        {
            uint4* d0 = (uint4*)&B0[brow][bk];
            uint4* d1 = (uint4*)&B1[brow][bk];
            d0[0] = pb0[0]; d0[1] = pb0[1];
            d1[0] = pb1[0]; d1[1] = pb1[1];
        }
        __syncthreads();
        if (it + 1 < iters) {
            const float* ap = abase + (it + 1) * 32;
            float4 f1 = *(const float4*)ap;
            float4 f2 = *(const float4*)(ap + 4);
            xv[0]=f1.x; xv[1]=f1.y; xv[2]=f1.z; xv[3]=f1.w;
            xv[4]=f2.x; xv[5]=f2.y; xv[6]=f2.z; xv[7]=f2.w;
            const uint4* s0 = (const uint4*)(w0p + (it + 1) * 32);
            const uint4* s1 = (const uint4*)(w1p + (it + 1) * 32);
            pb0[0] = s0[0]; pb0[1] = s0[1];
            pb1[0] = s1[0]; pb1[1] = s1[1];
        }
        mma_iterT<2, 2>(A0, A1, B0, B1, wr, wc, lane, c);
        __syncthreads();
    }
#pragma unroll
    for (int mt = 0; mt < 2; mt++)
#pragma unroll
        for (int nt = 0; nt < 4; nt++) {
            int r = m0 + wr * 32 + mt * 16 + g;
            int cc = col0 + wc * 32 + nt * 8 + 2 * tg;
            float v0 = c[mt][nt][0] + bias[cc];
            float v1 = c[mt][nt][1] + bias[cc + 1];
            float v2 = c[mt][nt][2] + bias[cc];
            float v3 = c[mt][nt][3] + bias[cc + 1];
            if (relu_flag) {
                v0 = fmaxf(v0, 0.f); v1 = fmaxf(v1, 0.f);
                v2 = fmaxf(v2, 0.f); v3 = fmaxf(v3, 0.f);
            }
            C[(size_t)r * N + cc] = v0;
            C[(size_t)r * N + cc + 1] = v1;
            C[(size_t)(r + 8) * N + cc] = v2;
            C[(size_t)(r + 8) * N + cc + 1] = v3;
        }
}

// ------------------------------------------------------------------
// Expert GEMM 1: H1 = relu(gather(x) @ e1[e] + b)  K=1024, N=256
// ------------------------------------------------------------------
__global__ __launch_bounds__(256) void mma_eg1(const float* __restrict__ e1b)
{
    const int e = blockIdx.z;
    const int ce = g_ecount[e];
    const int m0 = blockIdx.y * 64;
    if (m0 >= ce) return;
    const int off = g_off[e];
    const bh* W0 = g_e1t0 + (size_t)e * HID_ * MHID_;
    const bh* W1 = g_e1t1 + (size_t)e * HID_ * MHID_;
    const float* bias = e1b + (size_t)e * MHID_;

    __shared__ __align__(16) bh A0[64][ROWW], A1[64][ROWW];
    __shared__ __align__(16) bh B0[256][ROWW], B1[256][ROWW];
    const int tid = threadIdx.x;
    const int wid = tid >> 5, lane = tid & 31;
    const int wr = wid >> 2, wc = wid & 3;
    const int g = lane >> 2, tg = lane & 3;
    const int ar = tid >> 2;
    const int ak = (tid & 3) * 8;
    const int gr0 = m0 + ar;
    const int tok = (gr0 < ce) ? g_elist[e * B_ + gr0] : -1;
    const float* abase = (tok >= 0) ? &g_x[(size_t)tok * HID_ + ak] : nullptr;
    const uint4* wb0 = (const uint4*)&W0[(size_t)tid * HID_];
    const uint4* wb1 = (const uint4*)&W1[(size_t)tid * HID_];
    float c[2][8][4] = {};

    float xv[8] = {0.f,0.f,0.f,0.f,0.f,0.f,0.f,0.f};
    uint4 pb0[4], pb1[4];
    {
        if (abase) {
            float4 f1 = *(const float4*)abase;
            float4 f2 = *(const float4*)(abase + 4);
            xv[0]=f1.x; xv[1]=f1.y; xv[2]=f1.z; xv[3]=f1.w;
            xv[4]=f2.x; xv[5]=f2.y; xv[6]=f2.z; xv[7]=f2.w;
        }
#pragma unroll
        for (int j = 0; j < 4; j++) { pb0[j] = wb0[j]; pb1[j] = wb1[j]; }
    }

    for (int it = 0; it < HID_ / 32; ++it) {
        split8_store(xv, &A0[ar][ak], &A1[ar][ak]);
        {
            uint4* d0 = (uint4*)&B0[tid][0];
            uint4* d1 = (uint4*)&B1[tid][0];
#pragma unroll
            for (int j = 0; j < 4; j++) { d0[j] = pb0[j]; d1[j] = pb1[j]; }
        }
        __syncthreads();
        if (it + 1 < HID_ / 32) {
            if (abase) {
                const float* ap = abase + (it + 1) * 32;
                float4 f1 = *(const float4*)ap;
                float4 f2 = *(const float4*)(ap + 4);
                xv[0]=f1.x; xv[1]=f1.y; xv[2]=f1.z; xv[3]=f1.w;
                xv[4]=f2.x; xv[5]=f2.y; xv[6]=f2.z; xv[7]=f2.w;
            }
            const uint4* s0 = wb0 + (it + 1) * 4;
            const uint4* s1 = wb1 + (it + 1) * 4;
#pragma unroll
            for (int j = 0; j < 4; j++) { pb0[j] = s0[j]; pb1[j] = s1[j]; }
        }
        mma_iterT<2, 4>(A0, A1, B0, B1, wr, wc, lane, c);
        __syncthreads();
    }
#pragma unroll
    for (int mt = 0; mt < 2; mt++)
#pragma unroll
        for (int nt = 0; nt < 8; nt++) {
            int gr = m0 + wr * 32 + mt * 16 + g;
            int cc = wc * 64 + nt * 8 + 2 * tg;
            if (gr < ce) {
                g_H1[(size_t)(off + gr) * MHID_ + cc]     = fmaxf(c[mt][nt][0] + bias[cc], 0.f);
                g_H1[(size_t)(off + gr) * MHID_ + cc + 1] = fmaxf(c[mt][nt][1] + bias[cc + 1], 0.f);
            }
            if (gr + 8 < ce) {
                g_H1[(size_t)(off + gr + 8) * MHID_ + cc]     = fmaxf(c[mt][nt][2] + bias[cc], 0.f);
                g_H1[(size_t)(off + gr + 8) * MHID_ + cc + 1] = fmaxf(c[mt][nt][3] + bias[cc + 1], 0.f);
            }
        }
}

// ------------------------------------------------------------------
// Expert GEMM 2: Y = H1 @ e2[e] + b   K=256, N=1024; pipelined
// ------------------------------------------------------------------
__global__ __launch_bounds__(256) void mma_eg2(const float* __restrict__ e2b)
{
    const int e = blockIdx.z;
    const int ce = g_ecount[e];
    const int m0 = blockIdx.y * 64;
    if (m0 >= ce) return;
    const int off = g_off[e];
    const int col0 = blockIdx.x * 256;
    const bh* W0 = g_e2t0 + (size_t)e * MHID_ * HID_;
    const bh* W1 = g_e2t1 + (size_t)e * MHID_ * HID_;
    const float* bias = e2b + (size_t)e * HID_;

    __shared__ __align__(16) bh A0[64][ROWW], A1[64][ROWW];
    __shared__ __align__(16) bh B0[256][ROWW], B1[256][ROWW];
    const int tid = threadIdx.x;
    const int wid = tid >> 5, lane = tid & 31;
    const int wr = wid >> 2, wc = wid & 3;
    const int g = lane >> 2, tg = lane & 3;
    const int ar = tid >> 2;
    const int ak = (tid & 3) * 8;
    const int gr0 = m0 + ar;
    const float* abase = (gr0 < ce) ? &g_H1[(size_t)(off + gr0) * MHID_ + ak] : nullptr;
    const uint4* wb0 = (const uint4*)&W0[(size_t)(col0 + tid) * MHID_];
    const uint4* wb1 = (const uint4*)&W1[(size_t)(col0 + tid) * MHID_];
    float c[2][8][4] = {};

    float xv[8] = {0.f,0.f,0.f,0.f,0.f,0.f,0.f,0.f};
    uint4 pb0[4], pb1[4];
    {
        if (abase) {
            float4 f1 = *(const float4*)abase;
            float4 f2 = *(const float4*)(abase + 4);
            xv[0]=f1.x; xv[1]=f1.y; xv[2]=f1.z; xv[3]=f1.w;
            xv[4]=f2.x; xv[5]=f2.y; xv[6]=f2.z; xv[7]=f2.w;
        }
#pragma unroll
        for (int j = 0; j < 4; j++) { pb0[j] = wb0[j]; pb1[j] = wb1[j]; }
    }

    for (int it = 0; it < MHID_ / 32; ++it) {
        split8_store(xv, &A0[ar][ak], &A1[ar][ak]);
        {
            uint4* d0 = (uint4*)&B0[tid][0];
            uint4* d1 = (uint4*)&B1[tid][0];
#pragma unroll
            for (int j = 0; j < 4; j++) { d0[j] = pb0[j]; d1[j] = pb1[j]; }
        }
        __syncthreads();
        if (it + 1 < MHID_ / 32) {
            if (abase) {
                const float* ap = abase + (it + 1) * 32;
                float4 f1 = *(const float4*)ap;
                float4 f2 = *(const float4*)(ap + 4);
                xv[0]=f1.x; xv[1]=f1.y; xv[2]=f1.z; xv[3]=f1.w;
                xv[4]=f2.x; xv[5]=f2.y; xv[6]=f2.z; xv[7]=f2.w;
            }
            const uint4* s0 = wb0 + (it + 1) * 4;
            const uint4* s1 = wb1 + (it + 1) * 4;
#pragma unroll
            for (int j = 0; j < 4; j++) { pb0[j] = s0[j]; pb1[j] = s1[j]; }
        }
        mma_iterT<2, 4>(A0, A1, B0, B1, wr, wc, lane, c);
        __syncthreads();
    }
#pragma unroll
    for (int mt = 0; mt < 2; mt++)
#pragma unroll
        for (int nt = 0; nt < 8; nt++) {
            int gr = m0 + wr * 32 + mt * 16 + g;
            int cc = col0 + wc * 64 + nt * 8 + 2 * tg;
            if (gr < ce) {
                g_Y[(size_t)(off + gr) * HID_ + cc]     = c[mt][nt][0] + bias[cc];
                g_Y[(size_t)(off + gr) * HID_ + cc + 1] = c[mt][nt][1] + bias[cc + 1];
            }
            if (gr + 8 < ce) {
                g_Y[(size_t)(off + gr + 8) * HID_ + cc]     = c[mt][nt][2] + bias[cc];
                g_Y[(size_t)(off + gr + 8) * HID_ + cc + 1] = c[mt][nt][3] + bias[cc + 1];
            }
        }
}

// ------------------------------------------------------------------
// Generic fp32 GEMM (se1 K=24, g2 N=32 only)
// ------------------------------------------------------------------
__global__ __launch_bounds__(256) void gemm64(
    const float* __restrict__ A, const float* __restrict__ W,
    const float* __restrict__ bias, float* __restrict__ C,
    int M, int N, int K, int relu_flag)
{
    __shared__ float As[16][68];
    __shared__ float Bs[16][68];
    const int tid = threadIdx.x;
    const int tx = tid & 15, ty = tid >> 4;
    const int row0 = blockIdx.y * 64, col0 = blockIdx.x * 64;
    float acc[4][4] = {};
    for (int k0 = 0; k0 < K; k0 += 16) {
#pragma unroll
        for (int i = 0; i < 4; i++) {
            int id = tid + 256 * i;
            int m = id >> 4, kk = id & 15;
            float v = 0.f;
            int gr = row0 + m, gk = k0 + kk;
            if (gr < M && gk < K) v = A[(size_t)gr * K + gk];
            As[kk][m] = v;
        }
#pragma unroll
        for (int i = 0; i < 4; i++) {
            int id = tid + 256 * i;
            int kk = id >> 6, n = id & 63;
            float v = 0.f;
            int gc = col0 + n, gk = k0 + kk;
            if (gk < K && gc < N) v = W[(size_t)gk * N + gc];
            Bs[kk][n] = v;
        }
        __syncthreads();
        float at[4][4] = {};
#pragma unroll
        for (int kk = 0; kk < 16; kk++) {
            float4 a4 = *(const float4*)&As[kk][ty * 4];
            float4 b4 = *(const float4*)&Bs[kk][tx * 4];
            float av[4] = {a4.x, a4.y, a4.z, a4.w};
            float bv[4] = {b4.x, b4.y, b4.z, b4.w};
#pragma unroll
            for (int i = 0; i < 4; i++)
#pragma unroll
                for (int j = 0; j < 4; j++) at[i][j] += av[i] * bv[j];
        }
#pragma unroll
        for (int i = 0; i < 4; i++)
#pragma unroll
            for (int j = 0; j < 4; j++) acc[i][j] += at[i][j];
        __syncthreads();
    }
#pragma unroll
    for (int i = 0; i < 4; i++) {
        int r = row0 + ty * 4 + i;
        if (r < M) {
#pragma unroll
            for (int j = 0; j < 4; j++) {
                int c = col0 + tx * 4 + j;
                if (c < N) {
                    float v = acc[i][j] + bias[c];
                    if (relu_flag) v = fmaxf(v, 0.f);
                    C[(size_t)r * N + c] = v;
                }
            }
        }
    }
}

// ------------------------------------------------------------------
// reduce partials (double) + bias + LayerNorm + tanh + add state enc
// ------------------------------------------------------------------
__global__ __launch_bounds__(256) void ln_fuse(
    const float* __restrict__ tb, const float* __restrict__ lng,
    const float* __restrict__ lnb)
{
    const int b = blockIdx.x, f = threadIdx.x;
    double vd = (double)tb[f];
#pragma unroll
    for (int s = 0; s < KSPL_; s++)
        vd += (double)g_part[((size_t)s * B_ + b) * FEAT_ + f];
    float v = (float)vd;

    __shared__ float sred[2][8];
    const int wid = f >> 5, lane = f & 31;
    float s1 = v, s2 = v * v;
#pragma unroll
    for (int o = 16; o; o >>= 1) {
        s1 += __shfl_xor_sync(0xffffffffu, s1, o);
        s2 += __shfl_xor_sync(0xffffffffu, s2, o);
    }
    if (lane == 0) { sred[0][wid] = s1; sred[1][wid] = s2; }
    __syncthreads();
    float t1 = 0.f, t2 = 0.f;
#pragma unroll
    for (int i = 0; i < 8; i++) { t1 += sred[0][i]; t2 += sred[1][i]; }
    float mu = t1 * (1.f / FEAT_);
    float var = t2 * (1.f / FEAT_) - mu * mu;
    float y = (v - mu) * rsqrtf(var + 1e-5f) * lng[f] + lnb[f];
    g_h[(size_t)b * FEAT_ + f] = tanhf(y) + g_s[(size_t)b * FEAT_ + f];
}

// ------------------------------------------------------------------
// top-k + softmax weights + importance
// ------------------------------------------------------------------
__global__ __launch_bounds__(256) void topk_kernel()
{
    const int wid = threadIdx.x >> 5, lane = threadIdx.x & 31;
    const int b = blockIdx.x * 8 + wid;
    __shared__ float simp[NE_];
    if (threadIdx.x < NE_) simp[threadIdx.x] = 0.f;
    __syncthreads();

    float v = g_logits[(size_t)b * NE_ + lane];

    float m = v;
#pragma unroll
    for (int o = 16; o; o >>= 1) m = fmaxf(m, __shfl_xor_sync(0xffffffffu, m, o));
    float p = expf(v - m);
    float ps = p;
#pragma unroll
    for (int o = 16; o; o >>= 1) ps += __shfl_xor_sync(0xffffffffu, ps, o);
    atomicAdd(&simp[lane], p / ps);

    const float NEG_INF = __int_as_float(0xff800000);
    float vv = v;
    float tv0 = 0.f, tv1 = 0.f, tv2 = 0.f, tv3 = 0.f;
    int ti0 = 0, ti1 = 0, ti2 = 0, ti3 = 0;
#pragma unroll
    for (int k = 0; k < 4; k++) {
        float mv = vv; int mi = lane;
#pragma unroll
        for (int o = 16; o; o >>= 1) {
            float ov = __shfl_xor_sync(0xffffffffu, mv, o);
            int   oi = __shfl_xor_sync(0xffffffffu, mi, o);
            if (ov > mv || (ov == mv && oi < mi)) { mv = ov; mi = oi; }
        }
        if (k == 0) { tv0 = mv; ti0 = mi; }
        else if (k == 1) { tv1 = mv; ti1 = mi; }
        else if (k == 2) { tv2 = mv; ti2 = mi; }
        else { tv3 = mv; ti3 = mi; }
        if (lane == mi) vv = NEG_INF;
    }
    float e0 = 1.f;
    float e1 = expf(tv1 - tv0);
    float e2 = expf(tv2 - tv0);
    float e3 = expf(tv3 - tv0);
    float sw = e0 + e1 + e2 + e3;

    if (lane < 4) {
        int   mye = (lane == 0) ? ti0 : (lane == 1) ? ti1 : (lane == 2) ? ti2 : ti3;
        float myw = ((lane == 0) ? e0 : (lane == 1) ? e1 : (lane == 2) ? e2 : e3) / sw;
        int pos = atomicAdd(&g_ecount[mye], 1);
        g_elist[mye * B_ + pos] = b;
        g_tok_e[b * TOPK_ + lane] = mye;
        g_tok_pos[b * TOPK_ + lane] = pos;
        g_tok_w[b * TOPK_ + lane] = myw;
    }
    __syncthreads();
    if (threadIdx.x < NE_) atomicAdd(&g_imp[threadIdx.x], simp[threadIdx.x]);
}

// ------------------------------------------------------------------
__global__ void scan_aux(float* aux_out)
{
    if (threadIdx.x == 0) {
        int off = 0;
        float aux = 0.f;
        for (int e = 0; e < NE_; e++) {
            g_off[e] = off;
            off += g_ecount[e];
            aux += (g_imp[e] / (float)B_) * ((float)g_ecount[e] / (float)B_);
        }
        if (aux_out) *aux_out = (float)NE_ * aux;
    }
}

// ------------------------------------------------------------------
__global__ __launch_bounds__(256) void combine_kernel()
{
    const int b = blockIdx.x;
    int   go[TOPK_];
    float w[TOPK_];
#pragma unroll
    for (int k = 0; k < TOPK_; k++) {
        int e = g_tok_e[b * TOPK_ + k];
        go[k] = g_off[e] + g_tok_pos[b * TOPK_ + k];
        w[k] = g_tok_w[b * TOPK_ + k];
    }
    for (int n = threadIdx.x; n < HID_; n += 256) {
        float acc = 0.f;
#pragma unroll
        for (int k = 0; k < TOPK_; k++)
            acc += w[k] * g_Y[(size_t)go[k] * HID_ + n];
        g_xmoe[(size_t)b * HID_ + n] = fmaxf(acc, 0.f);
    }
}

// ------------------------------------------------------------------
__global__ __launch_bounds__(256) void p2_kernel(
    const float* __restrict__ w, const float* __restrict__ bias,
    float* __restrict__ out)
{
    const int b = blockIdx.x;
    __shared__ float xs[HID_];
    for (int i = threadIdx.x; i < HID_; i += 256)
        xs[i] = g_xmoe[(size_t)b * HID_ + i];
    __syncthreads();
    const int wid = threadIdx.x >> 5, lane = threadIdx.x & 31;
    if (wid < ADIM_) {
        float acc = 0.f;
        for (int k = lane; k < HID_; k += 32)
            acc += xs[k] * w[(size_t)k * ADIM_ + wid];
#pragma unroll
        for (int o = 16; o; o >>= 1) acc += __shfl_xor_sync(0xffffffffu, acc, o);
        if (lane == 0) out[(size_t)b * ADIM_ + wid] = tanhf(acc + bias[wid]);
    }
}

// ------------------------------------------------------------------
// launcher
// ------------------------------------------------------------------
extern "C" void kernel_launch(void* const* d_in, const int* in_sizes, int n_in,
                              void* d_out, int out_size)
{
    const float* obs        = (const float*)d_in[0];
    const float* obs_sensor = (const float*)d_in[2];
    const float* trunk_w    = (const float*)d_in[3];
    const float* trunk_b    = (const float*)d_in[4];
    const float* ln_g       = (const float*)d_in[5];
    const float* ln_b       = (const float*)d_in[6];
    const float* se1_w      = (const float*)d_in[7];
    const float* se1_b      = (const float*)d_in[8];
    const float* se2_w      = (const float*)d_in[9];
    const float* se2_b      = (const float*)d_in[10];
    const float* fu1_w      = (const float*)d_in[11];
    const float* fu1_b      = (const float*)d_in[12];
    const float* fu2_w      = (const float*)d_in[13];
    const float* fu2_b      = (const float*)d_in[14];
    const float* p1_w       = (const float*)d_in[15];
    const float* p1_b       = (const float*)d_in[16];
    const float* g1_w       = (const float*)d_in[17];
    const float* g1_b       = (const float*)d_in[18];
    const float* g2_w       = (const float*)d_in[19];
    const float* g2_b       = (const float*)d_in[20];
    const float* e1_w       = (const float*)d_in[21];
    const float* e1_b       = (const float*)d_in[22];
    const float* e2_w       = (const float*)d_in[23];
    const float* e2_b       = (const float*)d_in[24];
    const float* p2_w       = (const float*)d_in[25];
    const float* p2_b       = (const float*)d_in[26];

    float* out = (float*)d_out;
    float* aux_out = (out_size > B_ * ADIM_) ? (out + (size_t)B_ * ADIM_) : nullptr;

    float* hid;    cudaGetSymbolAddress((void**)&hid,    g_hid);
    float* sbuf;   cudaGetSymbolAddress((void**)&sbuf,   g_s);
    float* part;   cudaGetSymbolAddress((void**)&part,   g_part);
    float* hbuf;   cudaGetSymbolAddress((void**)&hbuf,   g_h);
    float* h2buf;  cudaGetSymbolAddress((void**)&h2buf,  g_h2);
    float* xbuf;   cudaGetSymbolAddress((void**)&xbuf,   g_x);
    float* ghbuf;  cudaGetSymbolAddress((void**)&ghbuf,  g_gh);
    float* lgbuf;  cudaGetSymbolAddress((void**)&lgbuf,  g_logits);
    bh *wt0, *wt1, *wd0, *wd1, *e1t0, *e1t1, *e2t0, *e2t1;
    cudaGetSymbolAddress((void**)&wt0, g_wt0);
    cudaGetSymbolAddress((void**)&wt1, g_wt1);
    cudaGetSymbolAddress((void**)&wd0, g_wd0);
    cudaGetSymbolAddress((void**)&wd1, g_wd1);
    cudaGetSymbolAddress((void**)&e1t0, g_e1t0);
    cudaGetSymbolAddress((void**)&e1t1, g_e1t1);
    cudaGetSymbolAddress((void**)&e2t0, g_e2t0);
    cudaGetSymbolAddress((void**)&e2t1, g_e2t1);

    zero_kernel<<<1, 32>>>();
    tconv<<<dim3(REPR_/32, FEAT_/32, 1), dim3(32, 8)>>>(trunk_w, wt0, wt1, REPR_, FEAT_);
    tconv<<<dim3(1024/32, 256/32, 1), dim3(32, 8)>>>(se2_w, wd0 + 0*(size_t)WDSZ, wd1 + 0*(size_t)WDSZ, 1024, 256);
    trunk_mma<<<dim3(KSPL_, B_ / 128), 256>>>(obs, part);
    tconv<<<dim3(256/32, 1024/32, 1), dim3(32, 8)>>>(fu1_w, wd0 + 1*(size_t)WDSZ, wd1 + 1*(size_t)WDSZ, 256, 1024);
    tconv<<<dim3(1024/32, 256/32, 1), dim3(32, 8)>>>(fu2_w, wd0 + 2*(size_t)WDSZ, wd1 + 2*(size_t)WDSZ, 1024, 256);
    tconv<<<dim3(256/32, 1024/32, 1), dim3(32, 8)>>>(p1_w,  wd0 + 3*(size_t)WDSZ, wd1 + 3*(size_t)WDSZ, 256, 1024);
    tconv<<<dim3(1024/32, 256/32, 1), dim3(32, 8)>>>(g1_w,  wd0 + 4*(size_t)WDSZ, wd1 + 4*(size_t)WDSZ, 1024, 256);
    tconv<<<dim3(HID_/32, MHID_/32, NE_), dim3(32, 8)>>>(e1_w, e1t0, e1t1, HID_, MHID_);
    tconv<<<dim3(MHID_/32, HID_/32, NE_), dim3(32, 8)>>>(e2_w, e2t0, e2t1, MHID_, HID_);

    // state encoder: se1 (K=24, SIMT) -> se2 (MMA, N-tile 128)
    gemm64<<<dim3(HID_ / 64, B_ / 64), 256>>>(obs_sensor, se1_w, se1_b, hid,
                                              B_, HID_, SDIM_, 1);
    mma_dense128<<<dim3(2, B_ / 64), 256>>>(hid, wd0 + 0*(size_t)WDSZ, wd1 + 0*(size_t)WDSZ,
                                            se2_b, sbuf, FEAT_, HID_, 0);

    // reduce + LN + tanh + add s
    ln_fuse<<<B_, 256>>>(trunk_b, ln_g, ln_b);

    // fusion MLP + policy1 + gate hidden (MMA, N-tile 128)
    mma_dense128<<<dim3(8, B_ / 64), 256>>>(hbuf, wd0 + 1*(size_t)WDSZ, wd1 + 1*(size_t)WDSZ,
                                            fu1_b, hid, HID_, FEAT_, 1);
    mma_dense128<<<dim3(2, B_ / 64), 256>>>(hid, wd0 + 2*(size_t)WDSZ, wd1 + 2*(size_t)WDSZ,
                                            fu2_b, h2buf, FEAT_, HID_, 0);
    mma_dense128<<<dim3(8, B_ / 64), 256>>>(h2buf, wd0 + 3*(size_t)WDSZ, wd1 + 3*(size_t)WDSZ,
                                            p1_b, xbuf, HID_, FEAT_, 1);
    mma_dense128<<<dim3(2, B_ / 64), 256>>>(xbuf, wd0 + 4*(size_t)WDSZ, wd1 + 4*(size_t)WDSZ,
                                            g1_b, ghbuf, FEAT_, HID_, 1);
    // g2 (N=32, SIMT)
    gemm64<<<dim3(1, B_ / 64), 256>>>(ghbuf, g2_w, g2_b, lgbuf,
                                      B_, NE_, FEAT_, 0);

    // routing
    topk_kernel<<<B_ / 8, 256>>>();
    scan_aux<<<1, 32>>>(aux_out);

    // experts (3-pass MMA, pipelined, N-tile 256)
    mma_eg1<<<dim3(1, B_ / 64, NE_), 256>>>(e1_b);
    mma_eg2<<<dim3(4, B_ / 64, NE_), 256>>>(e2_b);

    // combine + policy2
    combine_kernel<<<B_, 256>>>();
    p2_kernel<<<B_, 256>>>(p2_w, p2_b, out);
}

// round 16
// speedup vs baseline: 1.1933x; 1.0282x over previous
#include <cuda_runtime.h>
#include <cuda_bf16.h>
#include <math.h>

#define B_    4096
#define REPR_ 39200
#define FEAT_ 256
#define HID_  1024
#define NE_   32
#define TOPK_ 4
#define SDIM_ 24
#define ADIM_ 7
#define MHID_ 256
#define KSPL_ 35
#define KCH_  1120          // REPR_/KSPL_
#define NROWS_ (B_*TOPK_)
#define ROWW  40            // smem row width (32 k + 8 pad), 80B stride
#define WDSZ  262144        // 1024*256 dense weight slice

typedef __nv_bfloat16 bh;

// ------------------------------------------------------------------
// Device scratch
// ------------------------------------------------------------------
__device__ float g_hid[(size_t)B_*HID_];
__device__ float g_s[(size_t)B_*FEAT_];
__device__ float g_part[(size_t)KSPL_*B_*FEAT_];
__device__ float g_h[(size_t)B_*FEAT_];
__device__ float g_h2[(size_t)B_*FEAT_];
__device__ float g_x[(size_t)B_*HID_];
__device__ float g_gh[(size_t)B_*FEAT_];
__device__ float g_logits[(size_t)B_*NE_];
__device__ float g_imp[NE_];
__device__ int   g_ecount[NE_];
__device__ int   g_off[NE_];
__device__ int   g_elist[NE_*B_];
__device__ int   g_tok_e[B_*TOPK_];
__device__ int   g_tok_pos[B_*TOPK_];
__device__ float g_tok_w[B_*TOPK_];
__device__ float g_H1[(size_t)NROWS_*MHID_];
__device__ float g_Y[(size_t)NROWS_*HID_];
__device__ float g_xmoe[(size_t)B_*HID_];
// 2-plane bf16 splits, TRANSPOSED to [n][k] layout
__device__ bh g_wt0[(size_t)REPR_*FEAT_];
__device__ bh g_wt1[(size_t)REPR_*FEAT_];
__device__ bh g_wd0[5*(size_t)WDSZ];   // se2|fu1|fu2|p1|g1, [n][k]
__device__ bh g_wd1[5*(size_t)WDSZ];
__device__ bh g_e1t0[(size_t)NE_*HID_*MHID_];   // [e][n=256][k=1024]
__device__ bh g_e1t1[(size_t)NE_*HID_*MHID_];
__device__ bh g_e2t0[(size_t)NE_*MHID_*HID_];   // [e][n=1024][k=256]
__device__ bh g_e2t1[(size_t)NE_*MHID_*HID_];

// ------------------------------------------------------------------
__global__ void zero_kernel() {
    int t = threadIdx.x;
    if (t < NE_) { g_ecount[t] = 0; g_imp[t] = 0.f; }
}

// ------------------------------------------------------------------
// transpose + 2-plane split: src [z][K][N] fp32 -> d0/d1 [z][N][K] bf16
// ------------------------------------------------------------------
__global__ __launch_bounds__(256) void tconv(
    const float* __restrict__ src, bh* __restrict__ d0, bh* __restrict__ d1,
    int K, int N)
{
    const int z = blockIdx.z;
    const float* s = src + (size_t)z * K * N;
    bh* p0 = d0 + (size_t)z * K * N;
    bh* p1 = d1 + (size_t)z * K * N;
    __shared__ float t[32][33];
    const int k0 = blockIdx.x * 32, n0 = blockIdx.y * 32;
#pragma unroll
    for (int i = 0; i < 4; i++) {
        int ky = threadIdx.y + 8 * i;
        t[ky][threadIdx.x] = s[(size_t)(k0 + ky) * N + n0 + threadIdx.x];
    }
    __syncthreads();
#pragma unroll
    for (int i = 0; i < 4; i++) {
        int ny = threadIdx.y + 8 * i;
        float x = t[threadIdx.x][ny];
        bh b0 = __float2bfloat16(x);
        size_t o = (size_t)(n0 + ny) * K + k0 + threadIdx.x;
        p0[o] = b0;
        p1[o] = __float2bfloat16(x - __bfloat162float(b0));
    }
}

// ------------------------------------------------------------------
// MMA + LDSM helpers
// ------------------------------------------------------------------
__device__ __forceinline__ void mma_bf16(float c[4], const unsigned a[4], const unsigned b[2]) {
    asm volatile(
        "mma.sync.aligned.m16n8k16.row.col.f32.bf16.bf16.f32 "
        "{%0,%1,%2,%3},{%4,%5,%6,%7},{%8,%9},{%0,%1,%2,%3};\n"
        : "+f"(c[0]), "+f"(c[1]), "+f"(c[2]), "+f"(c[3])
        : "r"(a[0]), "r"(a[1]), "r"(a[2]), "r"(a[3]), "r"(b[0]), "r"(b[1]));
}

__device__ __forceinline__ void ldsm4(unsigned r[4], const bh* p) {
    unsigned addr = (unsigned)__cvta_generic_to_shared(p);
    asm volatile("ldmatrix.sync.aligned.m8n8.x4.shared.b16 {%0,%1,%2,%3}, [%4];"
                 : "=r"(r[0]), "=r"(r[1]), "=r"(r[2]), "=r"(r[3]) : "r"(addr));
}

__device__ __forceinline__ unsigned pk(bh a, bh b) {
    __nv_bfloat162 t(a, b);
    return *(unsigned*)&t;
}

// convert 8 fp32 -> two 16B plane stores at A0/A1[row][kcol]
__device__ __forceinline__ void split8_store(
    const float x[8], bh* a0p, bh* a1p)
{
    unsigned u0[4], u1[4];
#pragma unroll
    for (int j = 0; j < 4; j++) {
        bh h0a = __float2bfloat16(x[2*j]);
        bh h0b = __float2bfloat16(x[2*j+1]);
        bh h1a = __float2bfloat16(x[2*j]   - __bfloat162float(h0a));
        bh h1b = __float2bfloat16(x[2*j+1] - __bfloat162float(h0b));
        u0[j] = pk(h0a, h0b);
        u1[j] = pk(h1a, h1b);
    }
    *(uint4*)a0p = make_uint4(u0[0], u0[1], u0[2], u0[3]);
    *(uint4*)a1p = make_uint4(u1[0], u1[1], u1[2], u1[3]);
}

// 32-k MMA block: MT m-tiles per warp-row, NP n-16-pairs per warp-col
// (per-element accumulation order identical across NP choices)
template<int MT, int NP>
__device__ __forceinline__ void mma_iterT(
    const bh (*A0)[ROWW], const bh (*A1)[ROWW],
    const bh (*B0)[ROWW], const bh (*B1)[ROWW],
    int wr, int wc, int lane, float c[MT][2*NP][4])
{
    const int frow = lane & 15;
    const int fcol = (lane >> 4) << 3;
#pragma unroll
    for (int kh = 0; kh < 2; kh++) {
        const int kc = kh * 16 + fcol;
        unsigned a0f[MT][4], a1f[MT][4];
#pragma unroll
        for (int mt = 0; mt < MT; mt++) {
            ldsm4(a0f[mt], &A0[wr * (MT * 16) + mt * 16 + frow][kc]);
            ldsm4(a1f[mt], &A1[wr * (MT * 16) + mt * 16 + frow][kc]);
        }
#pragma unroll
        for (int p = 0; p < NP; p++) {
            unsigned q0[4], q1[4];
            ldsm4(q0, &B0[wc * (NP * 16) + p * 16 + frow][kc]);
            ldsm4(q1, &B1[wc * (NP * 16) + p * 16 + frow][kc]);
            unsigned be0[2] = {q0[0], q0[2]}, bo0[2] = {q0[1], q0[3]};
            unsigned be1[2] = {q1[0], q1[2]}, bo1[2] = {q1[1], q1[3]};
#pragma unroll
            for (int mt = 0; mt < MT; mt++) {
                mma_bf16(c[mt][2*p],   a0f[mt], be0);
                mma_bf16(c[mt][2*p],   a0f[mt], be1);
                mma_bf16(c[mt][2*p],   a1f[mt], be0);
                mma_bf16(c[mt][2*p+1], a0f[mt], bo0);
                mma_bf16(c[mt][2*p+1], a0f[mt], bo1);
                mma_bf16(c[mt][2*p+1], a1f[mt], bo0);
            }
        }
    }
}

// ------------------------------------------------------------------
// Trunk GEMM: M-tile 128, N 256, split-K=35, pipelined, LDSM (R10 shape)
// ------------------------------------------------------------------
__global__ __launch_bounds__(256) void trunk_mma(
    const float* __restrict__ obs, float* __restrict__ part)
{
    const int s = blockIdx.x;
    const int m0 = blockIdx.y * 128;
    const int kbase = s * KCH_;
    __shared__ __align__(16) bh A0[128][ROWW], A1[128][ROWW];
    __shared__ __align__(16) bh B0[256][ROWW], B1[256][ROWW];
    const int tid = threadIdx.x;
    const int wid = tid >> 5, lane = tid & 31;
    const int wr = wid >> 2, wc = wid & 3;
    const int g = lane >> 2, tg = lane & 3;
    const int ar = tid >> 1;            // A row 0..127
    const int ak = (tid & 1) * 16;      // A k-offset 0/16
    float c[4][8][4] = {};

    const float* abase = &obs[(size_t)(m0 + ar) * REPR_ + kbase + ak];
    const uint4* wb0 = (const uint4*)&g_wt0[(size_t)tid * REPR_ + kbase];
    const uint4* wb1 = (const uint4*)&g_wt1[(size_t)tid * REPR_ + kbase];

    float xv[16];
    uint4 pb0[4], pb1[4];
    {
        float4 f1 = *(const float4*)abase;
        float4 f2 = *(const float4*)(abase + 4);
        float4 f3 = *(const float4*)(abase + 8);
        float4 f4 = *(const float4*)(abase + 12);
        xv[0]=f1.x; xv[1]=f1.y; xv[2]=f1.z; xv[3]=f1.w;
        xv[4]=f2.x; xv[5]=f2.y; xv[6]=f2.z; xv[7]=f2.w;
        xv[8]=f3.x; xv[9]=f3.y; xv[10]=f3.z; xv[11]=f3.w;
        xv[12]=f4.x; xv[13]=f4.y; xv[14]=f4.z; xv[15]=f4.w;
#pragma unroll
        for (int j = 0; j < 4; j++) { pb0[j] = wb0[j]; pb1[j] = wb1[j]; }
    }

    for (int it = 0; it < KCH_ / 32; ++it) {
        split8_store(xv,     &A0[ar][ak],     &A1[ar][ak]);
        split8_store(xv + 8, &A0[ar][ak + 8], &A1[ar][ak + 8]);
        {
            uint4* d0 = (uint4*)&B0[tid][0];
            uint4* d1 = (uint4*)&B1[tid][0];
#pragma unroll
            for (int j = 0; j < 4; j++) { d0[j] = pb0[j]; d1[j] = pb1[j]; }
        }
        __syncthreads();
        if (it + 1 < KCH_ / 32) {
            const float* ap = abase + (it + 1) * 32;
            float4 f1 = *(const float4*)ap;
            float4 f2 = *(const float4*)(ap + 4);
            float4 f3 = *(const float4*)(ap + 8);
            float4 f4 = *(const float4*)(ap + 12);
            xv[0]=f1.x; xv[1]=f1.y; xv[2]=f1.z; xv[3]=f1.w;
            xv[4]=f2.x; xv[5]=f2.y; xv[6]=f2.z; xv[7]=f2.w;
            xv[8]=f3.x; xv[9]=f3.y; xv[10]=f3.z; xv[11]=f3.w;
            xv[12]=f4.x; xv[13]=f4.y; xv[14]=f4.z; xv[15]=f4.w;
            const uint4* s0 = wb0 + (it + 1) * 4;
            const uint4* s1 = wb1 + (it + 1) * 4;
#pragma unroll
            for (int j = 0; j < 4; j++) { pb0[j] = s0[j]; pb1[j] = s1[j]; }
        }
        mma_iterT<4, 4>(A0, A1, B0, B1, wr, wc, lane, c);
        __syncthreads();
    }
#pragma unroll
    for (int mt = 0; mt < 4; mt++)
#pragma unroll
        for (int nt = 0; nt < 8; nt++) {
            int r = m0 + wr * 64 + mt * 16 + g;
            int cc = wc * 64 + nt * 8 + 2 * tg;
            float* p = &part[((size_t)s * B_ + r) * FEAT_ + cc];
            p[0] = c[mt][nt][0];
            p[1] = c[mt][nt][1];
            float* q = p + 8 * FEAT_;
            q[0] = c[mt][nt][2];
            q[1] = c[mt][nt][3];
        }
}

// ------------------------------------------------------------------
// Dense MMA GEMM, N-tile 128: grid (N/128, 64); M-tile 64; pipelined
// ------------------------------------------------------------------
__global__ __launch_bounds__(256) void mma_dense128(
    const float* __restrict__ A,
    const bh* __restrict__ W0, const bh* __restrict__ W1,
    const float* __restrict__ bias, float* __restrict__ C,
    int N, int K, int relu_flag)
{
    const int col0 = blockIdx.x * 128;
    const int m0 = blockIdx.y * 64;
    __shared__ __align__(16) bh A0[64][ROWW], A1[64][ROWW];
    __shared__ __align__(16) bh B0[128][ROWW], B1[128][ROWW];
    const int tid = threadIdx.x;
    const int wid = tid >> 5, lane = tid & 31;
    const int wr = wid >> 2, wc = wid & 3;
    const int g = lane >> 2, tg = lane & 3;
    const int ar = tid >> 2;
    const int ak = (tid & 3) * 8;
    const int brow = tid >> 1;          // B row 0..127
    const int bk = (tid & 1) * 16;      // B k-offset 0/16
    float c[2][4][4] = {};

    const float* abase = &A[(size_t)(m0 + ar) * K + ak];
    const bh* w0p = &W0[(size_t)(col0 + brow) * K + bk];
    const bh* w1p = &W1[(size_t)(col0 + brow) * K + bk];

    float xv[8];
    uint4 pb0[2], pb1[2];
    {
        float4 f1 = *(const float4*)abase;
        float4 f2 = *(const float4*)(abase + 4);
        xv[0]=f1.x; xv[1]=f1.y; xv[2]=f1.z; xv[3]=f1.w;
        xv[4]=f2.x; xv[5]=f2.y; xv[6]=f2.z; xv[7]=f2.w;
        const uint4* s0 = (const uint4*)w0p;
        const uint4* s1 = (const uint4*)w1p;
        pb0[0] = s0[0]; pb0[1] = s0[1];
        pb1[0] = s1[0]; pb1[1] = s1[1];
    }

    const int iters = K / 32;
    for (int it = 0; it < iters; ++it) {
        split8_store(xv, &A0[ar][ak], &A1[ar][ak]);
        {
            uint4* d0 = (uint4*)&B0[brow][bk];
            uint4* d1 = (uint4*)&B1[brow][bk];
            d0[0] = pb0[0]; d0[1] = pb0[1];
            d1[0] = pb1[0]; d1[1] = pb1[1];
        }
        __syncthreads();
        if (it + 1 < iters) {
            const float* ap = abase + (it + 1) * 32;
            float4 f1 = *(const float4*)ap;
            float4 f2 = *(const float4*)(ap + 4);
            xv[0]=f1.x; xv[1]=f1.y; xv[2]=f1.z; xv[3]=f1.w;
            xv[4]=f2.x; xv[5]=f2.y; xv[6]=f2.z; xv[7]=f2.w;
            const uint4* s0 = (const uint4*)(w0p + (it + 1) * 32);
            const uint4* s1 = (const uint4*)(w1p + (it + 1) * 32);
            pb0[0] = s0[0]; pb0[1] = s0[1];
            pb1[0] = s1[0]; pb1[1] = s1[1];
        }
        mma_iterT<2, 2>(A0, A1, B0, B1, wr, wc, lane, c);
        __syncthreads();
    }
#pragma unroll
    for (int mt = 0; mt < 2; mt++)
#pragma unroll
        for (int nt = 0; nt < 4; nt++) {
            int r = m0 + wr * 32 + mt * 16 + g;
            int cc = col0 + wc * 32 + nt * 8 + 2 * tg;
            float v0 = c[mt][nt][0] + bias[cc];
            float v1 = c[mt][nt][1] + bias[cc + 1];
            float v2 = c[mt][nt][2] + bias[cc];
            float v3 = c[mt][nt][3] + bias[cc + 1];
            if (relu_flag) {
                v0 = fmaxf(v0, 0.f); v1 = fmaxf(v1, 0.f);
                v2 = fmaxf(v2, 0.f); v3 = fmaxf(v3, 0.f);
            }
            C[(size_t)r * N + cc] = v0;
            C[(size_t)r * N + cc + 1] = v1;
            C[(size_t)(r + 8) * N + cc] = v2;
            C[(size_t)(r + 8) * N + cc + 1] = v3;
        }
}

// ------------------------------------------------------------------
// Expert GEMM 1, N-tile 128: H1 = relu(gather(x) @ e1[e] + b)
// K=1024; grid (2, B/64, NE)
// ------------------------------------------------------------------
__global__ __launch_bounds__(256) void mma_eg1(const float* __restrict__ e1b)
{
    const int e = blockIdx.z;
    const int ce = g_ecount[e];
    const int m0 = blockIdx.y * 64;
    if (m0 >= ce) return;
    const int off = g_off[e];
    const int col0 = blockIdx.x * 128;
    const bh* W0 = g_e1t0 + (size_t)e * HID_ * MHID_;
    const bh* W1 = g_e1t1 + (size_t)e * HID_ * MHID_;
    const float* bias = e1b + (size_t)e * MHID_;

    __shared__ __align__(16) bh A0[64][ROWW], A1[64][ROWW];
    __shared__ __align__(16) bh B0[128][ROWW], B1[128][ROWW];
    const int tid = threadIdx.x;
    const int wid = tid >> 5, lane = tid & 31;
    const int wr = wid >> 2, wc = wid & 3;
    const int g = lane >> 2, tg = lane & 3;
    const int ar = tid >> 2;
    const int ak = (tid & 3) * 8;
    const int brow = tid >> 1;
    const int bk = (tid & 1) * 16;
    const int gr0 = m0 + ar;
    const int tok = (gr0 < ce) ? g_elist[e * B_ + gr0] : -1;
    const float* abase = (tok >= 0) ? &g_x[(size_t)tok * HID_ + ak] : nullptr;
    const bh* w0p = &W0[(size_t)(col0 + brow) * HID_ + bk];
    const bh* w1p = &W1[(size_t)(col0 + brow) * HID_ + bk];
    float c[2][4][4] = {};

    float xv[8] = {0.f,0.f,0.f,0.f,0.f,0.f,0.f,0.f};
    uint4 pb0[2], pb1[2];
    {
        if (abase) {
            float4 f1 = *(const float4*)abase;
            float4 f2 = *(const float4*)(abase + 4);
            xv[0]=f1.x; xv[1]=f1.y; xv[2]=f1.z; xv[3]=f1.w;
            xv[4]=f2.x; xv[5]=f2.y; xv[6]=f2.z; xv[7]=f2.w;
        }
        const uint4* s0 = (const uint4*)w0p;
        const uint4* s1 = (const uint4*)w1p;
        pb0[0] = s0[0]; pb0[1] = s0[1];
        pb1[0] = s1[0]; pb1[1] = s1[1];
    }

    for (int it = 0; it < HID_ / 32; ++it) {
        split8_store(xv, &A0[ar][ak], &A1[ar][ak]);
        {
            uint4* d0 = (uint4*)&B0[brow][bk];
            uint4* d1 = (uint4*)&B1[brow][bk];
            d0[0] = pb0[0]; d0[1] = pb0[1];
            d1[0] = pb1[0]; d1[1] = pb1[1];
        }
        __syncthreads();
        if (it + 1 < HID_ / 32) {
            if (abase) {
                const float* ap = abase + (it + 1) * 32;
                float4 f1 = *(const float4*)ap;
                float4 f2 = *(const float4*)(ap + 4);
                xv[0]=f1.x; xv[1]=f1.y; xv[2]=f1.z; xv[3]=f1.w;
                xv[4]=f2.x; xv[5]=f2.y; xv[6]=f2.z; xv[7]=f2.w;
            }
            const uint4* s0 = (const uint4*)(w0p + (it + 1) * 32);
            const uint4* s1 = (const uint4*)(w1p + (it + 1) * 32);
            pb0[0] = s0[0]; pb0[1] = s0[1];
            pb1[0] = s1[0]; pb1[1] = s1[1];
        }
        mma_iterT<2, 2>(A0, A1, B0, B1, wr, wc, lane, c);
        __syncthreads();
    }
#pragma unroll
    for (int mt = 0; mt < 2; mt++)
#pragma unroll
        for (int nt = 0; nt < 4; nt++) {
            int gr = m0 + wr * 32 + mt * 16 + g;
            int cc = col0 + wc * 32 + nt * 8 + 2 * tg;
            if (gr < ce) {
                g_H1[(size_t)(off + gr) * MHID_ + cc]     = fmaxf(c[mt][nt][0] + bias[cc], 0.f);
                g_H1[(size_t)(off + gr) * MHID_ + cc + 1] = fmaxf(c[mt][nt][1] + bias[cc + 1], 0.f);
            }
            if (gr + 8 < ce) {
                g_H1[(size_t)(off + gr + 8) * MHID_ + cc]     = fmaxf(c[mt][nt][2] + bias[cc], 0.f);
                g_H1[(size_t)(off + gr + 8) * MHID_ + cc + 1] = fmaxf(c[mt][nt][3] + bias[cc + 1], 0.f);
            }
        }
}

// ------------------------------------------------------------------
// Expert GEMM 2, N-tile 128: Y = H1 @ e2[e] + b   K=256
// grid (8, B/64, NE)
// ------------------------------------------------------------------
__global__ __launch_bounds__(256) void mma_eg2(const float* __restrict__ e2b)
{
    const int e = blockIdx.z;
    const int ce = g_ecount[e];
    const int m0 = blockIdx.y * 64;
    if (m0 >= ce) return;
    const int off = g_off[e];
    const int col0 = blockIdx.x * 128;
    const bh* W0 = g_e2t0 + (size_t)e * MHID_ * HID_;
    const bh* W1 = g_e2t1 + (size_t)e * MHID_ * HID_;
    const float* bias = e2b + (size_t)e * HID_;

    __shared__ __align__(16) bh A0[64][ROWW], A1[64][ROWW];
    __shared__ __align__(16) bh B0[128][ROWW], B1[128][ROWW];
    const int tid = threadIdx.x;
    const int wid = tid >> 5, lane = tid & 31;
    const int wr = wid >> 2, wc = wid & 3;
    const int g = lane >> 2, tg = lane & 3;
    const int ar = tid >> 2;
    const int ak = (tid & 3) * 8;
    const int brow = tid >> 1;
    const int bk = (tid & 1) * 16;
    const int gr0 = m0 + ar;
    const float* abase = (gr0 < ce) ? &g_H1[(size_t)(off + gr0) * MHID_ + ak] : nullptr;
    const bh* w0p = &W0[(size_t)(col0 + brow) * MHID_ + bk];
    const bh* w1p = &W1[(size_t)(col0 + brow) * MHID_ + bk];
    float c[2][4][4] = {};

    float xv[8] = {0.f,0.f,0.f,0.f,0.f,0.f,0.f,0.f};
    uint4 pb0[2], pb1[2];
    {
        if (abase) {
            float4 f1 = *(const float4*)abase;
            float4 f2 = *(const float4*)(abase + 4);
            xv[0]=f1.x; xv[1]=f1.y; xv[2]=f1.z; xv[3]=f1.w;
            xv[4]=f2.x; xv[5]=f2.y; xv[6]=f2.z; xv[7]=f2.w;
        }
        const uint4* s0 = (const uint4*)w0p;
        const uint4* s1 = (const uint4*)w1p;
        pb0[0] = s0[0]; pb0[1] = s0[1];
        pb1[0] = s1[0]; pb1[1] = s1[1];
    }

    for (int it = 0; it < MHID_ / 32; ++it) {
        split8_store(xv, &A0[ar][ak], &A1[ar][ak]);
        {
            uint4* d0 = (uint4*)&B0[brow][bk];
            uint4* d1 = (uint4*)&B1[brow][bk];
            d0[0] = pb0[0]; d0[1] = pb0[1];
            d1[0] = pb1[0]; d1[1] = pb1[1];
        }
        __syncthreads();
        if (it + 1 < MHID_ / 32) {
            if (abase) {
                const float* ap = abase + (it + 1) * 32;
                float4 f1 = *(const float4*)ap;
                float4 f2 = *(const float4*)(ap + 4);
                xv[0]=f1.x; xv[1]=f1.y; xv[2]=f1.z; xv[3]=f1.w;
                xv[4]=f2.x; xv[5]=f2.y; xv[6]=f2.z; xv[7]=f2.w;
            }
            const uint4* s0 = (const uint4*)(w0p + (it + 1) * 32);
            const uint4* s1 = (const uint4*)(w1p + (it + 1) * 32);
            pb0[0] = s0[0]; pb0[1] = s0[1];
            pb1[0] = s1[0]; pb1[1] = s1[1];
        }
        mma_iterT<2, 2>(A0, A1, B0, B1, wr, wc, lane, c);
        __syncthreads();
    }
#pragma unroll
    for (int mt = 0; mt < 2; mt++)
#pragma unroll
        for (int nt = 0; nt < 4; nt++) {
            int gr = m0 + wr * 32 + mt * 16 + g;
            int cc = col0 + wc * 32 + nt * 8 + 2 * tg;
            if (gr < ce) {
                g_Y[(size_t)(off + gr) * HID_ + cc]     = c[mt][nt][0] + bias[cc];
                g_Y[(size_t)(off + gr) * HID_ + cc + 1] = c[mt][nt][1] + bias[cc + 1];
            }
            if (gr + 8 < ce) {
                g_Y[(size_t)(off + gr + 8) * HID_ + cc]     = c[mt][nt][2] + bias[cc];
                g_Y[(size_t)(off + gr + 8) * HID_ + cc + 1] = c[mt][nt][3] + bias[cc + 1];
            }
        }
}

// ------------------------------------------------------------------
// Generic fp32 GEMM (se1 K=24, g2 N=32 only)
// ------------------------------------------------------------------
__global__ __launch_bounds__(256) void gemm64(
    const float* __restrict__ A, const float* __restrict__ W,
    const float* __restrict__ bias, float* __restrict__ C,
    int M, int N, int K, int relu_flag)
{
    __shared__ float As[16][68];
    __shared__ float Bs[16][68];
    const int tid = threadIdx.x;
    const int tx = tid & 15, ty = tid >> 4;
    const int row0 = blockIdx.y * 64, col0 = blockIdx.x * 64;
    float acc[4][4] = {};
    for (int k0 = 0; k0 < K; k0 += 16) {
#pragma unroll
        for (int i = 0; i < 4; i++) {
            int id = tid + 256 * i;
            int m = id >> 4, kk = id & 15;
            float v = 0.f;
            int gr = row0 + m, gk = k0 + kk;
            if (gr < M && gk < K) v = A[(size_t)gr * K + gk];
            As[kk][m] = v;
        }
#pragma unroll
        for (int i = 0; i < 4; i++) {
            int id = tid + 256 * i;
            int kk = id >> 6, n = id & 63;
            float v = 0.f;
            int gc = col0 + n, gk = k0 + kk;
            if (gk < K && gc < N) v = W[(size_t)gk * N + gc];
            Bs[kk][n] = v;
        }
        __syncthreads();
        float at[4][4] = {};
#pragma unroll
        for (int kk = 0; kk < 16; kk++) {
            float4 a4 = *(const float4*)&As[kk][ty * 4];
            float4 b4 = *(const float4*)&Bs[kk][tx * 4];
            float av[4] = {a4.x, a4.y, a4.z, a4.w};
            float bv[4] = {b4.x, b4.y, b4.z, b4.w};
#pragma unroll
            for (int i = 0; i < 4; i++)
#pragma unroll
                for (int j = 0; j < 4; j++) at[i][j] += av[i] * bv[j];
        }
#pragma unroll
        for (int i = 0; i < 4; i++)
#pragma unroll
            for (int j = 0; j < 4; j++) acc[i][j] += at[i][j];
        __syncthreads();
    }
#pragma unroll
    for (int i = 0; i < 4; i++) {
        int r = row0 + ty * 4 + i;
        if (r < M) {
#pragma unroll
            for (int j = 0; j < 4; j++) {
                int c = col0 + tx * 4 + j;
                if (c < N) {
                    float v = acc[i][j] + bias[c];
                    if (relu_flag) v = fmaxf(v, 0.f);
                    C[(size_t)r * N + c] = v;
                }
            }
        }
    }
}

// ------------------------------------------------------------------
// reduce partials (double) + bias + LayerNorm + tanh + add state enc
// ------------------------------------------------------------------
__global__ __launch_bounds__(256) void ln_fuse(
    const float* __restrict__ tb, const float* __restrict__ lng,
    const float* __restrict__ lnb)
{
    const int b = blockIdx.x, f = threadIdx.x;
    double vd = (double)tb[f];
#pragma unroll
    for (int s = 0; s < KSPL_; s++)
        vd += (double)g_part[((size_t)s * B_ + b) * FEAT_ + f];
    float v = (float)vd;

    __shared__ float sred[2][8];
    const int wid = f >> 5, lane = f & 31;
    float s1 = v, s2 = v * v;
#pragma unroll
    for (int o = 16; o; o >>= 1) {
        s1 += __shfl_xor_sync(0xffffffffu, s1, o);
        s2 += __shfl_xor_sync(0xffffffffu, s2, o);
    }
    if (lane == 0) { sred[0][wid] = s1; sred[1][wid] = s2; }
    __syncthreads();
    float t1 = 0.f, t2 = 0.f;
#pragma unroll
    for (int i = 0; i < 8; i++) { t1 += sred[0][i]; t2 += sred[1][i]; }
    float mu = t1 * (1.f / FEAT_);
    float var = t2 * (1.f / FEAT_) - mu * mu;
    float y = (v - mu) * rsqrtf(var + 1e-5f) * lng[f] + lnb[f];
    g_h[(size_t)b * FEAT_ + f] = tanhf(y) + g_s[(size_t)b * FEAT_ + f];
}

// ------------------------------------------------------------------
// top-k + softmax weights + importance
// ------------------------------------------------------------------
__global__ __launch_bounds__(256) void topk_kernel()
{
    const int wid = threadIdx.x >> 5, lane = threadIdx.x & 31;
    const int b = blockIdx.x * 8 + wid;
    __shared__ float simp[NE_];
    if (threadIdx.x < NE_) simp[threadIdx.x] = 0.f;
    __syncthreads();

    float v = g_logits[(size_t)b * NE_ + lane];

    float m = v;
#pragma unroll
    for (int o = 16; o; o >>= 1) m = fmaxf(m, __shfl_xor_sync(0xffffffffu, m, o));
    float p = expf(v - m);
    float ps = p;
#pragma unroll
    for (int o = 16; o; o >>= 1) ps += __shfl_xor_sync(0xffffffffu, ps, o);
    atomicAdd(&simp[lane], p / ps);

    const float NEG_INF = __int_as_float(0xff800000);
    float vv = v;
    float tv0 = 0.f, tv1 = 0.f, tv2 = 0.f, tv3 = 0.f;
    int ti0 = 0, ti1 = 0, ti2 = 0, ti3 = 0;
#pragma unroll
    for (int k = 0; k < 4; k++) {
        float mv = vv; int mi = lane;
#pragma unroll
        for (int o = 16; o; o >>= 1) {
            float ov = __shfl_xor_sync(0xffffffffu, mv, o);
            int   oi = __shfl_xor_sync(0xffffffffu, mi, o);
            if (ov > mv || (ov == mv && oi < mi)) { mv = ov; mi = oi; }
        }
        if (k == 0) { tv0 = mv; ti0 = mi; }
        else if (k == 1) { tv1 = mv; ti1 = mi; }
        else if (k == 2) { tv2 = mv; ti2 = mi; }
        else { tv3 = mv; ti3 = mi; }
        if (lane == mi) vv = NEG_INF;
    }
    float e0 = 1.f;
    float e1 = expf(tv1 - tv0);
    float e2 = expf(tv2 - tv0);
    float e3 = expf(tv3 - tv0);
    float sw = e0 + e1 + e2 + e3;

    if (lane < 4) {
        int   mye = (lane == 0) ? ti0 : (lane == 1) ? ti1 : (lane == 2) ? ti2 : ti3;
        float myw = ((lane == 0) ? e0 : (lane == 1) ? e1 : (lane == 2) ? e2 : e3) / sw;
        int pos = atomicAdd(&g_ecount[mye], 1);
        g_elist[mye * B_ + pos] = b;
        g_tok_e[b * TOPK_ + lane] = mye;
        g_tok_pos[b * TOPK_ + lane] = pos;
        g_tok_w[b * TOPK_ + lane] = myw;
    }
    __syncthreads();
    if (threadIdx.x < NE_) atomicAdd(&g_imp[threadIdx.x], simp[threadIdx.x]);
}

// ------------------------------------------------------------------
__global__ void scan_aux(float* aux_out)
{
    if (threadIdx.x == 0) {
        int off = 0;
        float aux = 0.f;
        for (int e = 0; e < NE_; e++) {
            g_off[e] = off;
            off += g_ecount[e];
            aux += (g_imp[e] / (float)B_) * ((float)g_ecount[e] / (float)B_);
        }
        if (aux_out) *aux_out = (float)NE_ * aux;
    }
}

// ------------------------------------------------------------------
__global__ __launch_bounds__(256) void combine_kernel()
{
    const int b = blockIdx.x;
    int   go[TOPK_];
    float w[TOPK_];
#pragma unroll
    for (int k = 0; k < TOPK_; k++) {
        int e = g_tok_e[b * TOPK_ + k];
        go[k] = g_off[e] + g_tok_pos[b * TOPK_ + k];
        w[k] = g_tok_w[b * TOPK_ + k];
    }
    for (int n = threadIdx.x; n < HID_; n += 256) {
        float acc = 0.f;
#pragma unroll
        for (int k = 0; k < TOPK_; k++)
            acc += w[k] * g_Y[(size_t)go[k] * HID_ + n];
        g_xmoe[(size_t)b * HID_ + n] = fmaxf(acc, 0.f);
    }
}

// ------------------------------------------------------------------
__global__ __launch_bounds__(256) void p2_kernel(
    const float* __restrict__ w, const float* __restrict__ bias,
    float* __restrict__ out)
{
    const int b = blockIdx.x;
    __shared__ float xs[HID_];
    for (int i = threadIdx.x; i < HID_; i += 256)
        xs[i] = g_xmoe[(size_t)b * HID_ + i];
    __syncthreads();
    const int wid = threadIdx.x >> 5, lane = threadIdx.x & 31;
    if (wid < ADIM_) {
        float acc = 0.f;
        for (int k = lane; k < HID_; k += 32)
            acc += xs[k] * w[(size_t)k * ADIM_ + wid];
#pragma unroll
        for (int o = 16; o; o >>= 1) acc += __shfl_xor_sync(0xffffffffu, acc, o);
        if (lane == 0) out[(size_t)b * ADIM_ + wid] = tanhf(acc + bias[wid]);
    }
}

// ------------------------------------------------------------------
// launcher
// ------------------------------------------------------------------
extern "C" void kernel_launch(void* const* d_in, const int* in_sizes, int n_in,
                              void* d_out, int out_size)
{
    const float* obs        = (const float*)d_in[0];
    const float* obs_sensor = (const float*)d_in[2];
    const float* trunk_w    = (const float*)d_in[3];
    const float* trunk_b    = (const float*)d_in[4];
    const float* ln_g       = (const float*)d_in[5];
    const float* ln_b       = (const float*)d_in[6];
    const float* se1_w      = (const float*)d_in[7];
    const float* se1_b      = (const float*)d_in[8];
    const float* se2_w      = (const float*)d_in[9];
    const float* se2_b      = (const float*)d_in[10];
    const float* fu1_w      = (const float*)d_in[11];
    const float* fu1_b      = (const float*)d_in[12];
    const float* fu2_w      = (const float*)d_in[13];
    const float* fu2_b      = (const float*)d_in[14];
    const float* p1_w       = (const float*)d_in[15];
    const float* p1_b       = (const float*)d_in[16];
    const float* g1_w       = (const float*)d_in[17];
    const float* g1_b       = (const float*)d_in[18];
    const float* g2_w       = (const float*)d_in[19];
    const float* g2_b       = (const float*)d_in[20];
    const float* e1_w       = (const float*)d_in[21];
    const float* e1_b       = (const float*)d_in[22];
    const float* e2_w       = (const float*)d_in[23];
    const float* e2_b       = (const float*)d_in[24];
    const float* p2_w       = (const float*)d_in[25];
    const float* p2_b       = (const float*)d_in[26];

    float* out = (float*)d_out;
    float* aux_out = (out_size > B_ * ADIM_) ? (out + (size_t)B_ * ADIM_) : nullptr;

    float* hid;    cudaGetSymbolAddress((void**)&hid,    g_hid);
    float* sbuf;   cudaGetSymbolAddress((void**)&sbuf,   g_s);
    float* part;   cudaGetSymbolAddress((void**)&part,   g_part);
    float* hbuf;   cudaGetSymbolAddress((void**)&hbuf,   g_h);
    float* h2buf;  cudaGetSymbolAddress((void**)&h2buf,  g_h2);
    float* xbuf;   cudaGetSymbolAddress((void**)&xbuf,   g_x);
    float* ghbuf;  cudaGetSymbolAddress((void**)&ghbuf,  g_gh);
    float* lgbuf;  cudaGetSymbolAddress((void**)&lgbuf,  g_logits);
    bh *wt0, *wt1, *wd0, *wd1, *e1t0, *e1t1, *e2t0, *e2t1;
    cudaGetSymbolAddress((void**)&wt0, g_wt0);
    cudaGetSymbolAddress((void**)&wt1, g_wt1);
    cudaGetSymbolAddress((void**)&wd0, g_wd0);
    cudaGetSymbolAddress((void**)&wd1, g_wd1);
    cudaGetSymbolAddress((void**)&e1t0, g_e1t0);
    cudaGetSymbolAddress((void**)&e1t1, g_e1t1);
    cudaGetSymbolAddress((void**)&e2t0, g_e2t0);
    cudaGetSymbolAddress((void**)&e2t1, g_e2t1);

    zero_kernel<<<1, 32>>>();
    tconv<<<dim3(REPR_/32, FEAT_/32, 1), dim3(32, 8)>>>(trunk_w, wt0, wt1, REPR_, FEAT_);
    tconv<<<dim3(1024/32, 256/32, 1), dim3(32, 8)>>>(se2_w, wd0 + 0*(size_t)WDSZ, wd1 + 0*(size_t)WDSZ, 1024, 256);
    trunk_mma<<<dim3(KSPL_, B_ / 128), 256>>>(obs, part);
    tconv<<<dim3(256/32, 1024/32, 1), dim3(32, 8)>>>(fu1_w, wd0 + 1*(size_t)WDSZ, wd1 + 1*(size_t)WDSZ, 256, 1024);
    tconv<<<dim3(1024/32, 256/32, 1), dim3(32, 8)>>>(fu2_w, wd0 + 2*(size_t)WDSZ, wd1 + 2*(size_t)WDSZ, 1024, 256);
    tconv<<<dim3(256/32, 1024/32, 1), dim3(32, 8)>>>(p1_w,  wd0 + 3*(size_t)WDSZ, wd1 + 3*(size_t)WDSZ, 256, 1024);
    tconv<<<dim3(1024/32, 256/32, 1), dim3(32, 8)>>>(g1_w,  wd0 + 4*(size_t)WDSZ, wd1 + 4*(size_t)WDSZ, 1024, 256);
    tconv<<<dim3(HID_/32, MHID_/32, NE_), dim3(32, 8)>>>(e1_w, e1t0, e1t1, HID_, MHID_);
    tconv<<<dim3(MHID_/32, HID_/32, NE_), dim3(32, 8)>>>(e2_w, e2t0, e2t1, MHID_, HID_);

    // state encoder: se1 (K=24, SIMT) -> se2 (MMA, N-tile 128)
    gemm64<<<dim3(HID_ / 64, B_ / 64), 256>>>(obs_sensor, se1_w, se1_b, hid,
                                              B_, HID_, SDIM_, 1);
    mma_dense128<<<dim3(2, B_ / 64), 256>>>(hid, wd0 + 0*(size_t)WDSZ, wd1 + 0*(size_t)WDSZ,
                                            se2_b, sbuf, FEAT_, HID_, 0);

    // reduce + LN + tanh + add s
    ln_fuse<<<B_, 256>>>(trunk_b, ln_g, ln_b);

    // fusion MLP + policy1 + gate hidden (MMA, N-tile 128)
    mma_dense128<<<dim3(8, B_ / 64), 256>>>(hbuf, wd0 + 1*(size_t)WDSZ, wd1 + 1*(size_t)WDSZ,
                                            fu1_b, hid, HID_, FEAT_, 1);
    mma_dense128<<<dim3(2, B_ / 64), 256>>>(hid, wd0 + 2*(size_t)WDSZ, wd1 + 2*(size_t)WDSZ,
                                            fu2_b, h2buf, FEAT_, HID_, 0);
    mma_dense128<<<dim3(8, B_ / 64), 256>>>(h2buf, wd0 + 3*(size_t)WDSZ, wd1 + 3*(size_t)WDSZ,
                                            p1_b, xbuf, HID_, FEAT_, 1);
    mma_dense128<<<dim3(2, B_ / 64), 256>>>(xbuf, wd0 + 4*(size_t)WDSZ, wd1 + 4*(size_t)WDSZ,
                                            g1_b, ghbuf, FEAT_, HID_, 1);
    // g2 (N=32, SIMT)
    gemm64<<<dim3(1, B_ / 64), 256>>>(ghbuf, g2_w, g2_b, lgbuf,
                                      B_, NE_, FEAT_, 0);

    // routing
    topk_kernel<<<B_ / 8, 256>>>();
    scan_aux<<<1, 32>>>(aux_out);

    // experts (3-pass MMA, pipelined, N-tile 128)
    mma_eg1<<<dim3(2, B_ / 64, NE_), 256>>>(e1_b);
    mma_eg2<<<dim3(8, B_ / 64, NE_), 256>>>(e2_b);

    // combine + policy2
    combine_kernel<<<B_, 256>>>();
    p2_kernel<<<B_, 256>>>(p2_w, p2_b, out);
}

// round 17
// speedup vs baseline: 1.1935x; 1.0002x over previous
#include <cuda_runtime.h>
#include <cuda_bf16.h>
#include <math.h>

#define B_    4096
#define REPR_ 39200
#define FEAT_ 256
#define HID_  1024
#define NE_   32
#define TOPK_ 4
#define SDIM_ 24
#define ADIM_ 7
#define MHID_ 256
#define KSPL_ 35
#define KCH_  1120          // REPR_/KSPL_
#define NROWS_ (B_*TOPK_)
#define ROWW  40            // smem row width (32 k + 8 pad), 80B stride
#define WDSZ  262144        // 1024*256 dense weight slice

typedef __nv_bfloat16 bh;

// ------------------------------------------------------------------
// Device scratch
// ------------------------------------------------------------------
__device__ float g_hid[(size_t)B_*HID_];
__device__ float g_s[(size_t)B_*FEAT_];
__device__ float g_part[(size_t)KSPL_*B_*FEAT_];
__device__ float g_h[(size_t)B_*FEAT_];
__device__ float g_h2[(size_t)B_*FEAT_];
__device__ float g_x[(size_t)B_*HID_];
__device__ float g_gh[(size_t)B_*FEAT_];
__device__ float g_logits[(size_t)B_*NE_];
__device__ float g_imp[NE_];
__device__ int   g_ecount[NE_];
__device__ int   g_off[NE_];
__device__ int   g_elist[NE_*B_];
__device__ int   g_tok_e[B_*TOPK_];
__device__ int   g_tok_pos[B_*TOPK_];
__device__ float g_tok_w[B_*TOPK_];
__device__ float g_H1[(size_t)NROWS_*MHID_];
__device__ float g_Y[(size_t)NROWS_*HID_];
__device__ float g_xmoe[(size_t)B_*HID_];
// 2-plane bf16 splits, TRANSPOSED to [n][k] layout
__device__ bh g_wt0[(size_t)REPR_*FEAT_];
__device__ bh g_wt1[(size_t)REPR_*FEAT_];
__device__ bh g_wd0[5*(size_t)WDSZ];   // se2|fu1|fu2|p1|g1, [n][k]
__device__ bh g_wd1[5*(size_t)WDSZ];
__device__ bh g_e1t0[(size_t)NE_*HID_*MHID_];   // [e][n=256][k=1024]
__device__ bh g_e1t1[(size_t)NE_*HID_*MHID_];
__device__ bh g_e2t0[(size_t)NE_*MHID_*HID_];   // [e][n=1024][k=256]
__device__ bh g_e2t1[(size_t)NE_*MHID_*HID_];

// ------------------------------------------------------------------
__global__ void zero_kernel() {
    int t = threadIdx.x;
    if (t < NE_) { g_ecount[t] = 0; g_imp[t] = 0.f; }
}

// ------------------------------------------------------------------
// transpose + 2-plane split: src [z][K][N] fp32 -> d0/d1 [z][N][K] bf16
// ------------------------------------------------------------------
__global__ __launch_bounds__(256) void tconv(
    const float* __restrict__ src, bh* __restrict__ d0, bh* __restrict__ d1,
    int K, int N)
{
    const int z = blockIdx.z;
    const float* s = src + (size_t)z * K * N;
    bh* p0 = d0 + (size_t)z * K * N;
    bh* p1 = d1 + (size_t)z * K * N;
    __shared__ float t[32][33];
    const int k0 = blockIdx.x * 32, n0 = blockIdx.y * 32;
#pragma unroll
    for (int i = 0; i < 4; i++) {
        int ky = threadIdx.y + 8 * i;
        t[ky][threadIdx.x] = s[(size_t)(k0 + ky) * N + n0 + threadIdx.x];
    }
    __syncthreads();
#pragma unroll
    for (int i = 0; i < 4; i++) {
        int ny = threadIdx.y + 8 * i;
        float x = t[threadIdx.x][ny];
        bh b0 = __float2bfloat16(x);
        size_t o = (size_t)(n0 + ny) * K + k0 + threadIdx.x;
        p0[o] = b0;
        p1[o] = __float2bfloat16(x - __bfloat162float(b0));
    }
}

// ------------------------------------------------------------------
// MMA + LDSM helpers
// ------------------------------------------------------------------
__device__ __forceinline__ void mma_bf16(float c[4], const unsigned a[4], const unsigned b[2]) {
    asm volatile(
        "mma.sync.aligned.m16n8k16.row.col.f32.bf16.bf16.f32 "
        "{%0,%1,%2,%3},{%4,%5,%6,%7},{%8,%9},{%0,%1,%2,%3};\n"
        : "+f"(c[0]), "+f"(c[1]), "+f"(c[2]), "+f"(c[3])
        : "r"(a[0]), "r"(a[1]), "r"(a[2]), "r"(a[3]), "r"(b[0]), "r"(b[1]));
}

__device__ __forceinline__ void ldsm4(unsigned r[4], const bh* p) {
    unsigned addr = (unsigned)__cvta_generic_to_shared(p);
    asm volatile("ldmatrix.sync.aligned.m8n8.x4.shared.b16 {%0,%1,%2,%3}, [%4];"
                 : "=r"(r[0]), "=r"(r[1]), "=r"(r[2]), "=r"(r[3]) : "r"(addr));
}

__device__ __forceinline__ unsigned pk(bh a, bh b) {
    __nv_bfloat162 t(a, b);
    return *(unsigned*)&t;
}

// convert 8 fp32 -> two 16B plane stores at A0/A1[row][kcol]
__device__ __forceinline__ void split8_store(
    const float x[8], bh* a0p, bh* a1p)
{
    unsigned u0[4], u1[4];
#pragma unroll
    for (int j = 0; j < 4; j++) {
        bh h0a = __float2bfloat16(x[2*j]);
        bh h0b = __float2bfloat16(x[2*j+1]);
        bh h1a = __float2bfloat16(x[2*j]   - __bfloat162float(h0a));
        bh h1b = __float2bfloat16(x[2*j+1] - __bfloat162float(h0b));
        u0[j] = pk(h0a, h0b);
        u1[j] = pk(h1a, h1b);
    }
    *(uint4*)a0p = make_uint4(u0[0], u0[1], u0[2], u0[3]);
    *(uint4*)a1p = make_uint4(u1[0], u1[1], u1[2], u1[3]);
}

// 32-k MMA block: MT m-tiles per warp-row, NP n-16-pairs per warp-col
// (per-element accumulation order identical across NP choices)
template<int MT, int NP>
__device__ __forceinline__ void mma_iterT(
    const bh (*A0)[ROWW], const bh (*A1)[ROWW],
    const bh (*B0)[ROWW], const bh (*B1)[ROWW],
    int wr, int wc, int lane, float c[MT][2*NP][4])
{
    const int frow = lane & 15;
    const int fcol = (lane >> 4) << 3;
#pragma unroll
    for (int kh = 0; kh < 2; kh++) {
        const int kc = kh * 16 + fcol;
        unsigned a0f[MT][4], a1f[MT][4];
#pragma unroll
        for (int mt = 0; mt < MT; mt++) {
            ldsm4(a0f[mt], &A0[wr * (MT * 16) + mt * 16 + frow][kc]);
            ldsm4(a1f[mt], &A1[wr * (MT * 16) + mt * 16 + frow][kc]);
        }
#pragma unroll
        for (int p = 0; p < NP; p++) {
            unsigned q0[4], q1[4];
            ldsm4(q0, &B0[wc * (NP * 16) + p * 16 + frow][kc]);
            ldsm4(q1, &B1[wc * (NP * 16) + p * 16 + frow][kc]);
            unsigned be0[2] = {q0[0], q0[2]}, bo0[2] = {q0[1], q0[3]};
            unsigned be1[2] = {q1[0], q1[2]}, bo1[2] = {q1[1], q1[3]};
#pragma unroll
            for (int mt = 0; mt < MT; mt++) {
                mma_bf16(c[mt][2*p],   a0f[mt], be0);
                mma_bf16(c[mt][2*p],   a0f[mt], be1);
                mma_bf16(c[mt][2*p],   a1f[mt], be0);
                mma_bf16(c[mt][2*p+1], a0f[mt], bo0);
                mma_bf16(c[mt][2*p+1], a0f[mt], bo1);
                mma_bf16(c[mt][2*p+1], a1f[mt], bo0);
            }
        }
    }
}

// ------------------------------------------------------------------
// Trunk GEMM: M-tile 128, N 256, split-K=35, pipelined, LDSM (R10 shape)
// ------------------------------------------------------------------
__global__ __launch_bounds__(256) void trunk_mma(
    const float* __restrict__ obs, float* __restrict__ part)
{
    const int s = blockIdx.x;
    const int m0 = blockIdx.y * 128;
    const int kbase = s * KCH_;
    __shared__ __align__(16) bh A0[128][ROWW], A1[128][ROWW];
    __shared__ __align__(16) bh B0[256][ROWW], B1[256][ROWW];
    const int tid = threadIdx.x;
    const int wid = tid >> 5, lane = tid & 31;
    const int wr = wid >> 2, wc = wid & 3;
    const int g = lane >> 2, tg = lane & 3;
    const int ar = tid >> 1;            // A row 0..127
    const int ak = (tid & 1) * 16;      // A k-offset 0/16
    float c[4][8][4] = {};

    const float* abase = &obs[(size_t)(m0 + ar) * REPR_ + kbase + ak];
    const uint4* wb0 = (const uint4*)&g_wt0[(size_t)tid * REPR_ + kbase];
    const uint4* wb1 = (const uint4*)&g_wt1[(size_t)tid * REPR_ + kbase];

    float xv[16];
    uint4 pb0[4], pb1[4];
    {
        float4 f1 = *(const float4*)abase;
        float4 f2 = *(const float4*)(abase + 4);
        float4 f3 = *(const float4*)(abase + 8);
        float4 f4 = *(const float4*)(abase + 12);
        xv[0]=f1.x; xv[1]=f1.y; xv[2]=f1.z; xv[3]=f1.w;
        xv[4]=f2.x; xv[5]=f2.y; xv[6]=f2.z; xv[7]=f2.w;
        xv[8]=f3.x; xv[9]=f3.y; xv[10]=f3.z; xv[11]=f3.w;
        xv[12]=f4.x; xv[13]=f4.y; xv[14]=f4.z; xv[15]=f4.w;
#pragma unroll
        for (int j = 0; j < 4; j++) { pb0[j] = wb0[j]; pb1[j] = wb1[j]; }
    }

    for (int it = 0; it < KCH_ / 32; ++it) {
        split8_store(xv,     &A0[ar][ak],     &A1[ar][ak]);
        split8_store(xv + 8, &A0[ar][ak + 8], &A1[ar][ak + 8]);
        {
            uint4* d0 = (uint4*)&B0[tid][0];
            uint4* d1 = (uint4*)&B1[tid][0];
#pragma unroll
            for (int j = 0; j < 4; j++) { d0[j] = pb0[j]; d1[j] = pb1[j]; }
        }
        __syncthreads();
        if (it + 1 < KCH_ / 32) {
            const float* ap = abase + (it + 1) * 32;
            float4 f1 = *(const float4*)ap;
            float4 f2 = *(const float4*)(ap + 4);
            float4 f3 = *(const float4*)(ap + 8);
            float4 f4 = *(const float4*)(ap + 12);
            xv[0]=f1.x; xv[1]=f1.y; xv[2]=f1.z; xv[3]=f1.w;
            xv[4]=f2.x; xv[5]=f2.y; xv[6]=f2.z; xv[7]=f2.w;
            xv[8]=f3.x; xv[9]=f3.y; xv[10]=f3.z; xv[11]=f3.w;
            xv[12]=f4.x; xv[13]=f4.y; xv[14]=f4.z; xv[15]=f4.w;
            const uint4* s0 = wb0 + (it + 1) * 4;
            const uint4* s1 = wb1 + (it + 1) * 4;
#pragma unroll
            for (int j = 0; j < 4; j++) { pb0[j] = s0[j]; pb1[j] = s1[j]; }
        }
        mma_iterT<4, 4>(A0, A1, B0, B1, wr, wc, lane, c);
        __syncthreads();
    }
#pragma unroll
    for (int mt = 0; mt < 4; mt++)
#pragma unroll
        for (int nt = 0; nt < 8; nt++) {
            int r = m0 + wr * 64 + mt * 16 + g;
            int cc = wc * 64 + nt * 8 + 2 * tg;
            float* p = &part[((size_t)s * B_ + r) * FEAT_ + cc];
            p[0] = c[mt][nt][0];
            p[1] = c[mt][nt][1];
            float* q = p + 8 * FEAT_;
            q[0] = c[mt][nt][2];
            q[1] = c[mt][nt][3];
        }
}

// ------------------------------------------------------------------
// Dense MMA GEMM, N-tile 128, 2 blocks/SM: grid (N/128, 64)
// ------------------------------------------------------------------
__global__ __launch_bounds__(256, 2) void mma_dense128(
    const float* __restrict__ A,
    const bh* __restrict__ W0, const bh* __restrict__ W1,
    const float* __restrict__ bias, float* __restrict__ C,
    int N, int K, int relu_flag)
{
    const int col0 = blockIdx.x * 128;
    const int m0 = blockIdx.y * 64;
    __shared__ __align__(16) bh A0[64][ROWW], A1[64][ROWW];
    __shared__ __align__(16) bh B0[128][ROWW], B1[128][ROWW];
    const int tid = threadIdx.x;
    const int wid = tid >> 5, lane = tid & 31;
    const int wr = wid >> 2, wc = wid & 3;
    const int g = lane >> 2, tg = lane & 3;
    const int ar = tid >> 2;
    const int ak = (tid & 3) * 8;
    const int brow = tid >> 1;          // B row 0..127
    const int bk = (tid & 1) * 16;      // B k-offset 0/16
    float c[2][4][4] = {};

    const float* abase = &A[(size_t)(m0 + ar) * K + ak];
    const bh* w0p = &W0[(size_t)(col0 + brow) * K + bk];
    const bh* w1p = &W1[(size_t)(col0 + brow) * K + bk];

    float xv[8];
    uint4 pb0[2], pb1[2];
    {
        float4 f1 = *(const float4*)abase;
        float4 f2 = *(const float4*)(abase + 4);
        xv[0]=f1.x; xv[1]=f1.y; xv[2]=f1.z; xv[3]=f1.w;
        xv[4]=f2.x; xv[5]=f2.y; xv[6]=f2.z; xv[7]=f2.w;
        const uint4* s0 = (const uint4*)w0p;
        const uint4* s1 = (const uint4*)w1p;
        pb0[0] = s0[0]; pb0[1] = s0[1];
        pb1[0] = s1[0]; pb1[1] = s1[1];
    }

    const int iters = K / 32;
    for (int it = 0; it < iters; ++it) {
        split8_store(xv, &A0[ar][ak], &A1[ar][ak]);
        {
            uint4* d0 = (uint4*)&B0[brow][bk];
            uint4* d1 = (uint4*)&B1[brow][bk];
            d0[0] = pb0[0]; d0[1] = pb0[1];
            d1[0] = pb1[0]; d1[1] = pb1[1];
        }
        __syncthreads();
        if (it + 1 < iters) {
            const float* ap = abase + (it + 1) * 32;
            float4 f1 = *(const float4*)ap;
            float4 f2 = *(const float4*)(ap + 4);
            xv[0]=f1.x; xv[1]=f1.y; xv[2]=f1.z; xv[3]=f1.w;
            xv[4]=f2.x; xv[5]=f2.y; xv[6]=f2.z; xv[7]=f2.w;
            const uint4* s0 = (const uint4*)(w0p + (it + 1) * 32);
            const uint4* s1 = (const uint4*)(w1p + (it + 1) * 32);
            pb0[0] = s0[0]; pb0[1] = s0[1];
            pb1[0] = s1[0]; pb1[1] = s1[1];
        }
        mma_iterT<2, 2>(A0, A1, B0, B1, wr, wc, lane, c);
        __syncthreads();
    }
#pragma unroll
    for (int mt = 0; mt < 2; mt++)
#pragma unroll
        for (int nt = 0; nt < 4; nt++) {
            int r = m0 + wr * 32 + mt * 16 + g;
            int cc = col0 + wc * 32 + nt * 8 + 2 * tg;
            float v0 = c[mt][nt][0] + bias[cc];
            float v1 = c[mt][nt][1] + bias[cc + 1];
            float v2 = c[mt][nt][2] + bias[cc];
            float v3 = c[mt][nt][3] + bias[cc + 1];
            if (relu_flag) {
                v0 = fmaxf(v0, 0.f); v1 = fmaxf(v1, 0.f);
                v2 = fmaxf(v2, 0.f); v3 = fmaxf(v3, 0.f);
            }
            C[(size_t)r * N + cc] = v0;
            C[(size_t)r * N + cc + 1] = v1;
            C[(size_t)(r + 8) * N + cc] = v2;
            C[(size_t)(r + 8) * N + cc + 1] = v3;
        }
}

// ------------------------------------------------------------------
// Expert GEMM 1, N-tile 128, 2 blocks/SM: K=1024; grid (2, B/64, NE)
// ------------------------------------------------------------------
__global__ __launch_bounds__(256, 2) void mma_eg1(const float* __restrict__ e1b)
{
    const int e = blockIdx.z;
    const int ce = g_ecount[e];
    const int m0 = blockIdx.y * 64;
    if (m0 >= ce) return;
    const int off = g_off[e];
    const int col0 = blockIdx.x * 128;
    const bh* W0 = g_e1t0 + (size_t)e * HID_ * MHID_;
    const bh* W1 = g_e1t1 + (size_t)e * HID_ * MHID_;
    const float* bias = e1b + (size_t)e * MHID_;

    __shared__ __align__(16) bh A0[64][ROWW], A1[64][ROWW];
    __shared__ __align__(16) bh B0[128][ROWW], B1[128][ROWW];
    const int tid = threadIdx.x;
    const int wid = tid >> 5, lane = tid & 31;
    const int wr = wid >> 2, wc = wid & 3;
    const int g = lane >> 2, tg = lane & 3;
    const int ar = tid >> 2;
    const int ak = (tid & 3) * 8;
    const int brow = tid >> 1;
    const int bk = (tid & 1) * 16;
    const int gr0 = m0 + ar;
    const int tok = (gr0 < ce) ? g_elist[e * B_ + gr0] : -1;
    const float* abase = (tok >= 0) ? &g_x[(size_t)tok * HID_ + ak] : nullptr;
    const bh* w0p = &W0[(size_t)(col0 + brow) * HID_ + bk];
    const bh* w1p = &W1[(size_t)(col0 + brow) * HID_ + bk];
    float c[2][4][4] = {};

    float xv[8] = {0.f,0.f,0.f,0.f,0.f,0.f,0.f,0.f};
    uint4 pb0[2], pb1[2];
    {
        if (abase) {
            float4 f1 = *(const float4*)abase;
            float4 f2 = *(const float4*)(abase + 4);
            xv[0]=f1.x; xv[1]=f1.y; xv[2]=f1.z; xv[3]=f1.w;
            xv[4]=f2.x; xv[5]=f2.y; xv[6]=f2.z; xv[7]=f2.w;
        }
        const uint4* s0 = (const uint4*)w0p;
        const uint4* s1 = (const uint4*)w1p;
        pb0[0] = s0[0]; pb0[1] = s0[1];
        pb1[0] = s1[0]; pb1[1] = s1[1];
    }

    for (int it = 0; it < HID_ / 32; ++it) {
        split8_store(xv, &A0[ar][ak], &A1[ar][ak]);
        {
            uint4* d0 = (uint4*)&B0[brow][bk];
            uint4* d1 = (uint4*)&B1[brow][bk];
            d0[0] = pb0[0]; d0[1] = pb0[1];
            d1[0] = pb1[0]; d1[1] = pb1[1];
        }
        __syncthreads();
        if (it + 1 < HID_ / 32) {
            if (abase) {
                const float* ap = abase + (it + 1) * 32;
                float4 f1 = *(const float4*)ap;
                float4 f2 = *(const float4*)(ap + 4);
                xv[0]=f1.x; xv[1]=f1.y; xv[2]=f1.z; xv[3]=f1.w;
                xv[4]=f2.x; xv[5]=f2.y; xv[6]=f2.z; xv[7]=f2.w;
            }
            const uint4* s0 = (const uint4*)(w0p + (it + 1) * 32);
            const uint4* s1 = (const uint4*)(w1p + (it + 1) * 32);
            pb0[0] = s0[0]; pb0[1] = s0[1];
            pb1[0] = s1[0]; pb1[1] = s1[1];
        }
        mma_iterT<2, 2>(A0, A1, B0, B1, wr, wc, lane, c);
        __syncthreads();
    }
#pragma unroll
    for (int mt = 0; mt < 2; mt++)
#pragma unroll
        for (int nt = 0; nt < 4; nt++) {
            int gr = m0 + wr * 32 + mt * 16 + g;
            int cc = col0 + wc * 32 + nt * 8 + 2 * tg;
            if (gr < ce) {
                g_H1[(size_t)(off + gr) * MHID_ + cc]     = fmaxf(c[mt][nt][0] + bias[cc], 0.f);
                g_H1[(size_t)(off + gr) * MHID_ + cc + 1] = fmaxf(c[mt][nt][1] + bias[cc + 1], 0.f);
            }
            if (gr + 8 < ce) {
                g_H1[(size_t)(off + gr + 8) * MHID_ + cc]     = fmaxf(c[mt][nt][2] + bias[cc], 0.f);
                g_H1[(size_t)(off + gr + 8) * MHID_ + cc + 1] = fmaxf(c[mt][nt][3] + bias[cc + 1], 0.f);
            }
        }
}

// ------------------------------------------------------------------
// Expert GEMM 2, N-tile 128, 2 blocks/SM: K=256; grid (8, B/64, NE)
// ------------------------------------------------------------------
__global__ __launch_bounds__(256, 2) void mma_eg2(const float* __restrict__ e2b)
{
    const int e = blockIdx.z;
    const int ce = g_ecount[e];
    const int m0 = blockIdx.y * 64;
    if (m0 >= ce) return;
    const int off = g_off[e];
    const int col0 = blockIdx.x * 128;
    const bh* W0 = g_e2t0 + (size_t)e * MHID_ * HID_;
    const bh* W1 = g_e2t1 + (size_t)e * MHID_ * HID_;
    const float* bias = e2b + (size_t)e * HID_;

    __shared__ __align__(16) bh A0[64][ROWW], A1[64][ROWW];
    __shared__ __align__(16) bh B0[128][ROWW], B1[128][ROWW];
    const int tid = threadIdx.x;
    const int wid = tid >> 5, lane = tid & 31;
    const int wr = wid >> 2, wc = wid & 3;
    const int g = lane >> 2, tg = lane & 3;
    const int ar = tid >> 2;
    const int ak = (tid & 3) * 8;
    const int brow = tid >> 1;
    const int bk = (tid & 1) * 16;
    const int gr0 = m0 + ar;
    const float* abase = (gr0 < ce) ? &g_H1[(size_t)(off + gr0) * MHID_ + ak] : nullptr;
    const bh* w0p = &W0[(size_t)(col0 + brow) * MHID_ + bk];
    const bh* w1p = &W1[(size_t)(col0 + brow) * MHID_ + bk];
    float c[2][4][4] = {};

    float xv[8] = {0.f,0.f,0.f,0.f,0.f,0.f,0.f,0.f};
    uint4 pb0[2], pb1[2];
    {
        if (abase) {
            float4 f1 = *(const float4*)abase;
            float4 f2 = *(const float4*)(abase + 4);
            xv[0]=f1.x; xv[1]=f1.y; xv[2]=f1.z; xv[3]=f1.w;
            xv[4]=f2.x; xv[5]=f2.y; xv[6]=f2.z; xv[7]=f2.w;
        }
        const uint4* s0 = (const uint4*)w0p;
        const uint4* s1 = (const uint4*)w1p;
        pb0[0] = s0[0]; pb0[1] = s0[1];
        pb1[0] = s1[0]; pb1[1] = s1[1];
    }

    for (int it = 0; it < MHID_ / 32; ++it) {
        split8_store(xv, &A0[ar][ak], &A1[ar][ak]);
        {
            uint4* d0 = (uint4*)&B0[brow][bk];
            uint4* d1 = (uint4*)&B1[brow][bk];
            d0[0] = pb0[0]; d0[1] = pb0[1];
            d1[0] = pb1[0]; d1[1] = pb1[1];
        }
        __syncthreads();
        if (it + 1 < MHID_ / 32) {
            if (abase) {
                const float* ap = abase + (it + 1) * 32;
                float4 f1 = *(const float4*)ap;
                float4 f2 = *(const float4*)(ap + 4);
                xv[0]=f1.x; xv[1]=f1.y; xv[2]=f1.z; xv[3]=f1.w;
                xv[4]=f2.x; xv[5]=f2.y; xv[6]=f2.z; xv[7]=f2.w;
            }
            const uint4* s0 = (const uint4*)(w0p + (it + 1) * 32);
            const uint4* s1 = (const uint4*)(w1p + (it + 1) * 32);
            pb0[0] = s0[0]; pb0[1] = s0[1];
            pb1[0] = s1[0]; pb1[1] = s1[1];
        }
        mma_iterT<2, 2>(A0, A1, B0, B1, wr, wc, lane, c);
        __syncthreads();
    }
#pragma unroll
    for (int mt = 0; mt < 2; mt++)
#pragma unroll
        for (int nt = 0; nt < 4; nt++) {
            int gr = m0 + wr * 32 + mt * 16 + g;
            int cc = col0 + wc * 32 + nt * 8 + 2 * tg;
            if (gr < ce) {
                g_Y[(size_t)(off + gr) * HID_ + cc]     = c[mt][nt][0] + bias[cc];
                g_Y[(size_t)(off + gr) * HID_ + cc + 1] = c[mt][nt][1] + bias[cc + 1];
            }
            if (gr + 8 < ce) {
                g_Y[(size_t)(off + gr + 8) * HID_ + cc]     = c[mt][nt][2] + bias[cc];
                g_Y[(size_t)(off + gr + 8) * HID_ + cc + 1] = c[mt][nt][3] + bias[cc + 1];
            }
        }
}

// ------------------------------------------------------------------
// Generic fp32 GEMM (se1 K=24, g2 N=32 only)
// ------------------------------------------------------------------
__global__ __launch_bounds__(256) void gemm64(
    const float* __restrict__ A, const float* __restrict__ W,
    const float* __restrict__ bias, float* __restrict__ C,
    int M, int N, int K, int relu_flag)
{
    __shared__ float As[16][68];
    __shared__ float Bs[16][68];
    const int tid = threadIdx.x;
    const int tx = tid & 15, ty = tid >> 4;
    const int row0 = blockIdx.y * 64, col0 = blockIdx.x * 64;
    float acc[4][4] = {};
    for (int k0 = 0; k0 < K; k0 += 16) {
#pragma unroll
        for (int i = 0; i < 4; i++) {
            int id = tid + 256 * i;
            int m = id >> 4, kk = id & 15;
            float v = 0.f;
            int gr = row0 + m, gk = k0 + kk;
            if (gr < M && gk < K) v = A[(size_t)gr * K + gk];
            As[kk][m] = v;
        }
#pragma unroll
        for (int i = 0; i < 4; i++) {
            int id = tid + 256 * i;
            int kk = id >> 6, n = id & 63;
            float v = 0.f;
            int gc = col0 + n, gk = k0 + kk;
            if (gk < K && gc < N) v = W[(size_t)gk * N + gc];
            Bs[kk][n] = v;
        }
        __syncthreads();
        float at[4][4] = {};
#pragma unroll
        for (int kk = 0; kk < 16; kk++) {
            float4 a4 = *(const float4*)&As[kk][ty * 4];
            float4 b4 = *(const float4*)&Bs[kk][tx * 4];
            float av[4] = {a4.x, a4.y, a4.z, a4.w};
            float bv[4] = {b4.x, b4.y, b4.z, b4.w};
#pragma unroll
            for (int i = 0; i < 4; i++)
#pragma unroll
                for (int j = 0; j < 4; j++) at[i][j] += av[i] * bv[j];
        }
#pragma unroll
        for (int i = 0; i < 4; i++)
#pragma unroll
            for (int j = 0; j < 4; j++) acc[i][j] += at[i][j];
        __syncthreads();
    }
#pragma unroll
    for (int i = 0; i < 4; i++) {
        int r = row0 + ty * 4 + i;
        if (r < M) {
#pragma unroll
            for (int j = 0; j < 4; j++) {
                int c = col0 + tx * 4 + j;
                if (c < N) {
                    float v = acc[i][j] + bias[c];
                    if (relu_flag) v = fmaxf(v, 0.f);
                    C[(size_t)r * N + c] = v;
                }
            }
        }
    }
}

// ------------------------------------------------------------------
// reduce partials (double) + bias + LayerNorm + tanh + add state enc
// ------------------------------------------------------------------
__global__ __launch_bounds__(256) void ln_fuse(
    const float* __restrict__ tb, const float* __restrict__ lng,
    const float* __restrict__ lnb)
{
    const int b = blockIdx.x, f = threadIdx.x;
    double vd = (double)tb[f];
#pragma unroll
    for (int s = 0; s < KSPL_; s++)
        vd += (double)g_part[((size_t)s * B_ + b) * FEAT_ + f];
    float v = (float)vd;

    __shared__ float sred[2][8];
    const int wid = f >> 5, lane = f & 31;
    float s1 = v, s2 = v * v;
#pragma unroll
    for (int o = 16; o; o >>= 1) {
        s1 += __shfl_xor_sync(0xffffffffu, s1, o);
        s2 += __shfl_xor_sync(0xffffffffu, s2, o);
    }
    if (lane == 0) { sred[0][wid] = s1; sred[1][wid] = s2; }
    __syncthreads();
    float t1 = 0.f, t2 = 0.f;
#pragma unroll
    for (int i = 0; i < 8; i++) { t1 += sred[0][i]; t2 += sred[1][i]; }
    float mu = t1 * (1.f / FEAT_);
    float var = t2 * (1.f / FEAT_) - mu * mu;
    float y = (v - mu) * rsqrtf(var + 1e-5f) * lng[f] + lnb[f];
    g_h[(size_t)b * FEAT_ + f] = tanhf(y) + g_s[(size_t)b * FEAT_ + f];
}

// ------------------------------------------------------------------
// top-k + softmax weights + importance
// ------------------------------------------------------------------
__global__ __launch_bounds__(256) void topk_kernel()
{
    const int wid = threadIdx.x >> 5, lane = threadIdx.x & 31;
    const int b = blockIdx.x * 8 + wid;
    __shared__ float simp[NE_];
    if (threadIdx.x < NE_) simp[threadIdx.x] = 0.f;
    __syncthreads();

    float v = g_logits[(size_t)b * NE_ + lane];

    float m = v;
#pragma unroll
    for (int o = 16; o; o >>= 1) m = fmaxf(m, __shfl_xor_sync(0xffffffffu, m, o));
    float p = expf(v - m);
    float ps = p;
#pragma unroll
    for (int o = 16; o; o >>= 1) ps += __shfl_xor_sync(0xffffffffu, ps, o);
    atomicAdd(&simp[lane], p / ps);

    const float NEG_INF = __int_as_float(0xff800000);
    float vv = v;
    float tv0 = 0.f, tv1 = 0.f, tv2 = 0.f, tv3 = 0.f;
    int ti0 = 0, ti1 = 0, ti2 = 0, ti3 = 0;
#pragma unroll
    for (int k = 0; k < 4; k++) {
        float mv = vv; int mi = lane;
#pragma unroll
        for (int o = 16; o; o >>= 1) {
            float ov = __shfl_xor_sync(0xffffffffu, mv, o);
            int   oi = __shfl_xor_sync(0xffffffffu, mi, o);
            if (ov > mv || (ov == mv && oi < mi)) { mv = ov; mi = oi; }
        }
        if (k == 0) { tv0 = mv; ti0 = mi; }
        else if (k == 1) { tv1 = mv; ti1 = mi; }
        else if (k == 2) { tv2 = mv; ti2 = mi; }
        else { tv3 = mv; ti3 = mi; }
        if (lane == mi) vv = NEG_INF;
    }
    float e0 = 1.f;
    float e1 = expf(tv1 - tv0);
    float e2 = expf(tv2 - tv0);
    float e3 = expf(tv3 - tv0);
    float sw = e0 + e1 + e2 + e3;

    if (lane < 4) {
        int   mye = (lane == 0) ? ti0 : (lane == 1) ? ti1 : (lane == 2) ? ti2 : ti3;
        float myw = ((lane == 0) ? e0 : (lane == 1) ? e1 : (lane == 2) ? e2 : e3) / sw;
        int pos = atomicAdd(&g_ecount[mye], 1);
        g_elist[mye * B_ + pos] = b;
        g_tok_e[b * TOPK_ + lane] = mye;
        g_tok_pos[b * TOPK_ + lane] = pos;
        g_tok_w[b * TOPK_ + lane] = myw;
    }
    __syncthreads();
    if (threadIdx.x < NE_) atomicAdd(&g_imp[threadIdx.x], simp[threadIdx.x]);
}

// ------------------------------------------------------------------
__global__ void scan_aux(float* aux_out)
{
    if (threadIdx.x == 0) {
        int off = 0;
        float aux = 0.f;
        for (int e = 0; e < NE_; e++) {
            g_off[e] = off;
            off += g_ecount[e];
            aux += (g_imp[e] / (float)B_) * ((float)g_ecount[e] / (float)B_);
        }
        if (aux_out) *aux_out = (float)NE_ * aux;
    }
}

// ------------------------------------------------------------------
__global__ __launch_bounds__(256) void combine_kernel()
{
    const int b = blockIdx.x;
    int   go[TOPK_];
    float w[TOPK_];
#pragma unroll
    for (int k = 0; k < TOPK_; k++) {
        int e = g_tok_e[b * TOPK_ + k];
        go[k] = g_off[e] + g_tok_pos[b * TOPK_ + k];
        w[k] = g_tok_w[b * TOPK_ + k];
    }
    for (int n = threadIdx.x; n < HID_; n += 256) {
        float acc = 0.f;
#pragma unroll
        for (int k = 0; k < TOPK_; k++)
            acc += w[k] * g_Y[(size_t)go[k] * HID_ + n];
        g_xmoe[(size_t)b * HID_ + n] = fmaxf(acc, 0.f);
    }
}

// ------------------------------------------------------------------
__global__ __launch_bounds__(256) void p2_kernel(
    const float* __restrict__ w, const float* __restrict__ bias,
    float* __restrict__ out)
{
    const int b = blockIdx.x;
    __shared__ float xs[HID_];
    for (int i = threadIdx.x; i < HID_; i += 256)
        xs[i] = g_xmoe[(size_t)b * HID_ + i];
    __syncthreads();
    const int wid = threadIdx.x >> 5, lane = threadIdx.x & 31;
    if (wid < ADIM_) {
        float acc = 0.f;
        for (int k = lane; k < HID_; k += 32)
            acc += xs[k] * w[(size_t)k * ADIM_ + wid];
#pragma unroll
        for (int o = 16; o; o >>= 1) acc += __shfl_xor_sync(0xffffffffu, acc, o);
        if (lane == 0) out[(size_t)b * ADIM_ + wid] = tanhf(acc + bias[wid]);
    }
}

// ------------------------------------------------------------------
// launcher
// ------------------------------------------------------------------
extern "C" void kernel_launch(void* const* d_in, const int* in_sizes, int n_in,
                              void* d_out, int out_size)
{
    const float* obs        = (const float*)d_in[0];
    const float* obs_sensor = (const float*)d_in[2];
    const float* trunk_w    = (const float*)d_in[3];
    const float* trunk_b    = (const float*)d_in[4];
    const float* ln_g       = (const float*)d_in[5];
    const float* ln_b       = (const float*)d_in[6];
    const float* se1_w      = (const float*)d_in[7];
    const float* se1_b      = (const float*)d_in[8];
    const float* se2_w      = (const float*)d_in[9];
    const float* se2_b      = (const float*)d_in[10];
    const float* fu1_w      = (const float*)d_in[11];
    const float* fu1_b      = (const float*)d_in[12];
    const float* fu2_w      = (const float*)d_in[13];
    const float* fu2_b      = (const float*)d_in[14];
    const float* p1_w       = (const float*)d_in[15];
    const float* p1_b       = (const float*)d_in[16];
    const float* g1_w       = (const float*)d_in[17];
    const float* g1_b       = (const float*)d_in[18];
    const float* g2_w       = (const float*)d_in[19];
    const float* g2_b       = (const float*)d_in[20];
    const float* e1_w       = (const float*)d_in[21];
    const float* e1_b       = (const float*)d_in[22];
    const float* e2_w       = (const float*)d_in[23];
    const float* e2_b       = (const float*)d_in[24];
    const float* p2_w       = (const float*)d_in[25];
    const float* p2_b       = (const float*)d_in[26];

    float* out = (float*)d_out;
    float* aux_out = (out_size > B_ * ADIM_) ? (out + (size_t)B_ * ADIM_) : nullptr;

    float* hid;    cudaGetSymbolAddress((void**)&hid,    g_hid);
    float* sbuf;   cudaGetSymbolAddress((void**)&sbuf,   g_s);
    float* part;   cudaGetSymbolAddress((void**)&part,   g_part);
    float* hbuf;   cudaGetSymbolAddress((void**)&hbuf,   g_h);
    float* h2buf;  cudaGetSymbolAddress((void**)&h2buf,  g_h2);
    float* xbuf;   cudaGetSymbolAddress((void**)&xbuf,   g_x);
    float* ghbuf;  cudaGetSymbolAddress((void**)&ghbuf,  g_gh);
    float* lgbuf;  cudaGetSymbolAddress((void**)&lgbuf,  g_logits);
    bh *wt0, *wt1, *wd0, *wd1, *e1t0, *e1t1, *e2t0, *e2t1;
    cudaGetSymbolAddress((void**)&wt0, g_wt0);
    cudaGetSymbolAddress((void**)&wt1, g_wt1);
    cudaGetSymbolAddress((void**)&wd0, g_wd0);
    cudaGetSymbolAddress((void**)&wd1, g_wd1);
    cudaGetSymbolAddress((void**)&e1t0, g_e1t0);
    cudaGetSymbolAddress((void**)&e1t1, g_e1t1);
    cudaGetSymbolAddress((void**)&e2t0, g_e2t0);
    cudaGetSymbolAddress((void**)&e2t1, g_e2t1);

    zero_kernel<<<1, 32>>>();
    tconv<<<dim3(REPR_/32, FEAT_/32, 1), dim3(32, 8)>>>(trunk_w, wt0, wt1, REPR_, FEAT_);
    tconv<<<dim3(1024/32, 256/32, 1), dim3(32, 8)>>>(se2_w, wd0 + 0*(size_t)WDSZ, wd1 + 0*(size_t)WDSZ, 1024, 256);
    trunk_mma<<<dim3(KSPL_, B_ / 128), 256>>>(obs, part);
    tconv<<<dim3(256/32, 1024/32, 1), dim3(32, 8)>>>(fu1_w, wd0 + 1*(size_t)WDSZ, wd1 + 1*(size_t)WDSZ, 256, 1024);
    tconv<<<dim3(1024/32, 256/32, 1), dim3(32, 8)>>>(fu2_w, wd0 + 2*(size_t)WDSZ, wd1 + 2*(size_t)WDSZ, 1024, 256);
    tconv<<<dim3(256/32, 1024/32, 1), dim3(32, 8)>>>(p1_w,  wd0 + 3*(size_t)WDSZ, wd1 + 3*(size_t)WDSZ, 256, 1024);
    tconv<<<dim3(1024/32, 256/32, 1), dim3(32, 8)>>>(g1_w,  wd0 + 4*(size_t)WDSZ, wd1 + 4*(size_t)WDSZ, 1024, 256);
    tconv<<<dim3(HID_/32, MHID_/32, NE_), dim3(32, 8)>>>(e1_w, e1t0, e1t1, HID_, MHID_);
    tconv<<<dim3(MHID_/32, HID_/32, NE_), dim3(32, 8)>>>(e2_w, e2t0, e2t1, MHID_, HID_);

    // state encoder: se1 (K=24, SIMT) -> se2 (MMA, N-tile 128)
    gemm64<<<dim3(HID_ / 64, B_ / 64), 256>>>(obs_sensor, se1_w, se1_b, hid,
                                              B_, HID_, SDIM_, 1);
    mma_dense128<<<dim3(2, B_ / 64), 256>>>(hid, wd0 + 0*(size_t)WDSZ, wd1 + 0*(size_t)WDSZ,
                                            se2_b, sbuf, FEAT_, HID_, 0);

    // reduce + LN + tanh + add s
    ln_fuse<<<B_, 256>>>(trunk_b, ln_g, ln_b);

    // fusion MLP + policy1 + gate hidden (MMA, N-tile 128)
    mma_dense128<<<dim3(8, B_ / 64), 256>>>(hbuf, wd0 + 1*(size_t)WDSZ, wd1 + 1*(size_t)WDSZ,
                                            fu1_b, hid, HID_, FEAT_, 1);
    mma_dense128<<<dim3(2, B_ / 64), 256>>>(hid, wd0 + 2*(size_t)WDSZ, wd1 + 2*(size_t)WDSZ,
                                            fu2_b, h2buf, FEAT_, HID_, 0);
    mma_dense128<<<dim3(8, B_ / 64), 256>>>(h2buf, wd0 + 3*(size_t)WDSZ, wd1 + 3*(size_t)WDSZ,
                                            p1_b, xbuf, HID_, FEAT_, 1);
    mma_dense128<<<dim3(2, B_ / 64), 256>>>(xbuf, wd0 + 4*(size_t)WDSZ, wd1 + 4*(size_t)WDSZ,
                                            g1_b, ghbuf, FEAT_, HID_, 1);
    // g2 (N=32, SIMT)
    gemm64<<<dim3(1, B_ / 64), 256>>>(ghbuf, g2_w, g2_b, lgbuf,
                                      B_, NE_, FEAT_, 0);

    // routing
    topk_kernel<<<B_ / 8, 256>>>();
    scan_aux<<<1, 32>>>(aux_out);

    // experts (3-pass MMA, pipelined, N-tile 128, 2 blocks/SM)
    mma_eg1<<<dim3(2, B_ / 64, NE_), 256>>>(e1_b);
    mma_eg2<<<dim3(8, B_ / 64, NE_), 256>>>(e2_b);

    // combine + policy2
    combine_kernel<<<B_, 256>>>();
    p2_kernel<<<B_, 256>>>(p2_w, p2_b, out);
}